// round 7
// baseline (speedup 1.0000x reference)
#include <cuda_runtime.h>
#include <math.h>

#define BB 4
#define SS 2048
#define FF 64
#define DD 256
#define NSC 15
#define NROW (BB*SS)   /* 8192 */
#define KSPLIT 8

// ---------------- device scratch ----------------
__device__ float g_G[(size_t)BB*SS*SS];
__device__ float g_E[(size_t)BB*SS*SS];
__device__ float g_q[NROW*FF];
__device__ float g_k[NROW*FF];
__device__ float g_sq[NROW];
__device__ float g_rn[NROW];
__device__ float g_pe[(size_t)KSPLIT*NROW*FF];

// ---------------- tf32 mma helpers ----------------
__device__ __forceinline__ void mma_tf32(float* c,
                                         unsigned a0, unsigned a1, unsigned a2, unsigned a3,
                                         unsigned b0, unsigned b1) {
    asm volatile(
        "mma.sync.aligned.m16n8k8.row.col.f32.tf32.tf32.f32 "
        "{%0,%1,%2,%3}, {%4,%5,%6,%7}, {%8,%9}, {%0,%1,%2,%3};\n"
        : "+f"(c[0]), "+f"(c[1]), "+f"(c[2]), "+f"(c[3])
        : "r"(a0), "r"(a1), "r"(a2), "r"(a3), "r"(b0), "r"(b1));
}

__device__ __forceinline__ unsigned cvt_tf32(float v) {
    unsigned r;
    asm("cvt.rna.tf32.f32 %0, %1;\n" : "=r"(r) : "f"(v));
    return r;
}

// ---------------- reductions ----------------
__device__ __forceinline__ float blk_sum256(float v, volatile float* red) {
    int tid = threadIdx.x;
    red[tid] = v; __syncthreads();
    for (int o = 128; o >= 1; o >>= 1) {
        if (tid < o) red[tid] = red[tid] + red[tid + o];
        __syncthreads();
    }
    float r = red[0]; __syncthreads();
    return r;
}

// ---------------- K1a: q/k projections + sq/rn ----------------
__global__ void qk_proj_kernel(const float* __restrict__ x,
                               const float* __restrict__ qW, const float* __restrict__ qb,
                               const float* __restrict__ kW, const float* __restrict__ kb) {
    int row = blockIdx.x * 4 + (threadIdx.x >> 6);
    int f   = threadIdx.x & 63;
    const float* xr = x + (size_t)row * FF;
    float aq = qb[f], ak = kb[f], ss = 0.f;
    #pragma unroll
    for (int k = 0; k < FF; k++) {
        float xv = xr[k];
        aq = fmaf(xv, qW[k*FF + f], aq);
        ak = fmaf(xv, kW[k*FF + f], ak);
        ss = fmaf(xv, xv, ss);
    }
    g_q[(size_t)row*FF + f] = aq;
    g_k[(size_t)row*FF + f] = ak;
    if (f == 0) g_sq[row] = ss;
    if (f == 1) g_rn[row] = 1.0f / fmaxf(sqrtf(ss), 1e-12f);
}

// ---------------- K1c: rpe branch ----------------
__global__ void rpe_kernel(const float* __restrict__ x,
                           const float* __restrict__ rW, const float* __restrict__ rb,
                           const float* __restrict__ l1w, const float* __restrict__ l1b,
                           const float* __restrict__ lns_p, const float* __restrict__ sw,
                           float* __restrict__ out) {
    __shared__ float red[256];
    __shared__ float sh3[3];
    int row = blockIdx.x;
    int b = row >> 11, s = row & (SS - 1);
    int d = threadIdx.x;
    float lns = fminf(fmaxf(lns_p[0], 1.0f), (float)NSC);
    int n = (int)rintf(lns);
    if (d < 32) {
        int sc = d + 1;
        float s0 = 0.f, s1 = 0.f, s2 = 0.f;
        if (sc <= n && s >= sc) {
            const float* xb = x + (size_t)b * SS * FF;
            float ds = xb[(size_t)s*FF + 0];
            float es = xb[(size_t)s*FF + FF - 1];
            float dd = xb[(size_t)(s - sc)*FF + 0] - ds;
            float de = xb[(size_t)(s - sc)*FF + FF - 1] - es;
            float wd = sw[sc - 1] * expf(-fabsf(dd) * exp2f(-(float)sc));
            s0 = dd; s1 = de; s2 = wd;
        }
        #pragma unroll
        for (int o = 16; o; o >>= 1) {
            s0 += __shfl_xor_sync(0xffffffffu, s0, o);
            s1 += __shfl_xor_sync(0xffffffffu, s1, o);
            s2 += __shfl_xor_sync(0xffffffffu, s2, o);
        }
        if (d == 0) { sh3[0] = s0; sh3[1] = s1; sh3[2] = s2; }
    }
    __syncthreads();
    float v = sh3[0]*rW[d] + sh3[1]*rW[DD + d] + sh3[2]*rW[2*DD + d] + (float)n * rb[d];
    float mean = blk_sum256(v, red) * (1.0f / DD);
    float dv = v - mean;
    float var = blk_sum256(dv*dv, red) * (1.0f / DD);
    out[(size_t)row*DD + d] = dv * rsqrtf(var + 1e-5f) * l1w[d] + l1b[d];
}

// ---------------- K2: 128x128 tile NT GEMM, pure 1x TF32 (K=64) ----------------
__global__ void __launch_bounds__(256, 2) gemm_nt_tf32(const float* __restrict__ x,
                                                       const float* __restrict__ q,
                                                       const float* __restrict__ k,
                                                       float* __restrict__ G,
                                                       float* __restrict__ E_) {
    __shared__ __align__(16) float As[128][36];
    __shared__ __align__(16) float Bs[128][36];
    int zz = blockIdx.z;
    int b  = zz & 3;
    bool isqk = zz >= 4;
    int s0 = blockIdx.y << 7;
    int t0 = blockIdx.x << 7;
    const float* Ab = (isqk ? q : x) + (size_t)b * SS * FF;
    const float* Bb = (isqk ? k : x) + (size_t)b * SS * FF;
    float*       Cb = (isqk ? E_ : G) + (size_t)b * SS * SS;
    int tid  = threadIdx.x;
    int lane = tid & 31;
    int wid  = tid >> 5;
    int rb   = (wid & 1) * 64;
    int cb   = (wid >> 1) * 32;
    int lr = lane >> 2, lc = lane & 3;

    float acc[4][4][4];
    #pragma unroll
    for (int i = 0; i < 4; i++)
        #pragma unroll
        for (int j = 0; j < 4; j++)
            #pragma unroll
            for (int r = 0; r < 4; r++) acc[i][j][r] = 0.f;

    #pragma unroll
    for (int st = 0; st < 2; st++) {
        int koff = st * 32;
        #pragma unroll
        for (int l = 0; l < 4; l++) {
            int f4 = tid + l*256;
            int r  = f4 >> 3;
            int kc = (f4 & 7) * 4;
            *(float4*)&As[r][kc] = *(const float4*)&Ab[(size_t)(s0 + r)*FF + koff + kc];
            *(float4*)&Bs[r][kc] = *(const float4*)&Bb[(size_t)(t0 + r)*FF + koff + kc];
        }
        __syncthreads();
        #pragma unroll
        for (int k0 = 0; k0 < 32; k0 += 8) {
            unsigned bh[4][2];
            #pragma unroll
            for (int nt = 0; nt < 4; nt++) {
                int n = cb + nt*8 + lr;
                bh[nt][0] = cvt_tf32(Bs[n][k0 + lc]);
                bh[nt][1] = cvt_tf32(Bs[n][k0 + 4 + lc]);
            }
            #pragma unroll
            for (int mt = 0; mt < 4; mt++) {
                int r = rb + mt*16 + lr;
                unsigned ah[4];
                ah[0] = cvt_tf32(As[r][k0 + lc]);
                ah[1] = cvt_tf32(As[r + 8][k0 + lc]);
                ah[2] = cvt_tf32(As[r][k0 + 4 + lc]);
                ah[3] = cvt_tf32(As[r + 8][k0 + 4 + lc]);
                #pragma unroll
                for (int nt = 0; nt < 4; nt++)
                    mma_tf32(acc[mt][nt], ah[0], ah[1], ah[2], ah[3], bh[nt][0], bh[nt][1]);
            }
        }
        __syncthreads();
    }
    #pragma unroll
    for (int mt = 0; mt < 4; mt++) {
        #pragma unroll
        for (int nt = 0; nt < 4; nt++) {
            int r    = s0 + rb + mt*16 + lr;
            int cidx = t0 + cb + nt*8 + (lc << 1);
            *(float2*)&Cb[(size_t)r*SS + cidx]       = make_float2(acc[mt][nt][0], acc[mt][nt][1]);
            *(float2*)&Cb[(size_t)(r + 8)*SS + cidx] = make_float2(acc[mt][nt][2], acc[mt][nt][3]);
        }
    }
}

// ---------------- K3: row kernel v4 ----------------
// Dual radix select; rank-(k+1) extracted from final level histogram
// (duplicate / next-nonzero-bin), global fallback only when the k+1
// rank leaves the 24-bit prefix window.
__global__ void __launch_bounds__(512) row_kernel(const float* __restrict__ alpha_p,
                                                  const float* __restrict__ sig_p) {
    __shared__ unsigned h[2][2][256];   // [parity][query][bin]
    __shared__ float redf[16];
    __shared__ unsigned redu[32];
    __shared__ unsigned bcA[4];         // {bin, excl, incl, nextbin}
    __shared__ unsigned bcB[4];
    int row = blockIdx.x;
    int b = row >> 11, s = row & (SS - 1);
    int tid = threadIdx.x;
    int lane = tid & 31, wid = tid >> 5;
    const float* Grow = g_G + (size_t)b*SS*SS + (size_t)s*SS;
    float*       Erow = g_E + (size_t)b*SS*SS + (size_t)s*SS;
    const float* sqb = g_sq + b*SS;
    const float* rnb = g_rn + b*SS;
    float sqs = sqb[s], rns = rnb[s];

    ((unsigned*)h)[tid]       = 0;
    ((unsigned*)h)[tid + 512] = 0;
    __syncthreads();

    float4 g4  = ((const float4*)Grow)[tid];
    float4 sc4 = ((const float4*)Erow)[tid];
    unsigned dv[4];
    {
        float4 sq4 = ((const float4*)sqb)[tid];
        float d2[4] = {fmaxf(sqs + sq4.x - 2.0f*g4.x, 0.0f),
                       fmaxf(sqs + sq4.y - 2.0f*g4.y, 0.0f),
                       fmaxf(sqs + sq4.z - 2.0f*g4.z, 0.0f),
                       fmaxf(sqs + sq4.w - 2.0f*g4.w, 0.0f)};
        #pragma unroll
        for (int j = 0; j < 4; j++) dv[j] = __float_as_uint(sqrtf(d2[j]));
    }
    // level-0 histogram, warp-aggregated (hot exponent bins)
    #pragma unroll
    for (int j = 0; j < 4; j++) {
        unsigned bin = dv[j] >> 24;
        unsigned mask = __match_any_sync(0xffffffffu, bin);
        if ((unsigned)(__ffs(mask) - 1) == (unsigned)lane)
            atomicAdd(&h[0][0][bin], (unsigned)__popc(mask));
    }
    // softmax Z without max shift (scores ~ N(0,1); exp safe in fp32)
    float z = __expf(sc4.x*0.125f) + __expf(sc4.y*0.125f)
            + __expf(sc4.z*0.125f) + __expf(sc4.w*0.125f);
    #pragma unroll
    for (int o = 16; o; o >>= 1) z += __shfl_xor_sync(0xffffffffu, z, o);
    if (lane == 0) redf[wid] = z;
    __syncthreads();

    const float fp05 = 0.05f * (float)(SS - 1);
    const int   l05 = (int)fp05; const float f05 = fp05 - (float)l05;
    const float fp95 = 0.95f * (float)(SS - 1);
    const int   l95 = (int)fp95; const float f95 = fp95 - (float)l95;
    int kA = l05, kB = l95;

    // level-0 find (warps 0/1); warp 2 reduces Z
    if (wid < 2) {
        int kq = wid ? kB : kA;
        volatile unsigned* bcq = wid ? bcB : bcA;
        unsigned vals[8]; unsigned sv = 0;
        #pragma unroll
        for (int j = 0; j < 8; j++) { vals[j] = h[0][0][lane*8 + j]; sv += vals[j]; }
        unsigned e = sv;
        #pragma unroll
        for (int o = 1; o < 32; o <<= 1) {
            unsigned t = __shfl_up_sync(0xffffffffu, e, o);
            if (lane >= o) e += t;
        }
        e -= sv;
        unsigned run = e;
        #pragma unroll
        for (int j = 0; j < 8; j++) {
            unsigned excl = run; run += vals[j];
            if (excl <= (unsigned)kq && (unsigned)kq < run) {
                bcq[0] = (unsigned)(lane*8 + j); bcq[1] = excl;
            }
        }
    } else if (wid == 2 && lane == 0) {
        float sz = 0.f;
        #pragma unroll
        for (int i = 0; i < 16; i++) sz += redf[i];
        redf[0] = sz;
    }
    __syncthreads();
    unsigned prefA = bcA[0] << 24;  kA -= (int)bcA[1];
    unsigned prefB = bcB[0] << 24;  kB -= (int)bcB[1];
    float Z = redf[0];

    // refine: shift = 16, 8, 0 with ping-pong buffers
    #pragma unroll
    for (int lev = 0; lev < 3; lev++) {
        int shift = 16 - 8*lev;
        int p = (lev & 1) ^ 1;
        unsigned himask = 0xFFFFFFFFu << (shift + 8);
        #pragma unroll
        for (int j = 0; j < 4; j++) {
            unsigned v = dv[j];
            unsigned bin = (v >> shift) & 255u;
            if ((v & himask) == prefA) atomicAdd(&h[p][0][bin], 1u);
            if ((v & himask) == prefB) atomicAdd(&h[p][1][bin], 1u);
        }
        __syncthreads();
        if (wid < 2) {
            int kq = wid ? kB : kA;
            volatile unsigned* bcq = wid ? bcB : bcA;
            unsigned vals[8]; unsigned sv = 0;
            #pragma unroll
            for (int j = 0; j < 8; j++) { vals[j] = h[p][wid][lane*8 + j]; sv += vals[j]; }
            unsigned e = sv;
            #pragma unroll
            for (int o = 1; o < 32; o <<= 1) {
                unsigned t = __shfl_up_sync(0xffffffffu, e, o);
                if (lane >= o) e += t;
            }
            e -= sv;
            unsigned run = e;
            #pragma unroll
            for (int j = 0; j < 8; j++) {
                unsigned excl = run; run += vals[j];
                if (excl <= (unsigned)kq && (unsigned)kq < run) {
                    bcq[0] = (unsigned)(lane*8 + j); bcq[1] = excl; bcq[2] = run;
                }
            }
            if (shift == 0) {
                __syncwarp();
                unsigned jsel = bcq[0];
                unsigned best = 0xFFFFFFFFu;
                #pragma unroll
                for (int j = 0; j < 8; j++) {
                    unsigned bin = (unsigned)(lane*8 + j);
                    if (bin > jsel && vals[j]) best = bin < best ? bin : best;
                }
                #pragma unroll
                for (int o = 16; o; o >>= 1) {
                    unsigned t = __shfl_xor_sync(0xffffffffu, best, o);
                    best = t < best ? t : best;
                }
                if (lane == 0) bcq[3] = best;
            }
        } else if (wid == 2 || wid == 3) {
            #pragma unroll
            for (int j = 0; j < 8; j++) h[p ^ 1][wid - 2][lane*8 + j] = 0;
        }
        __syncthreads();
        prefA |= bcA[0] << shift;  kA -= (int)bcA[1];
        prefB |= bcB[0] << shift;  kB -= (int)bcB[1];
    }
    unsigned vkA = prefA, vkB = prefB;

    // rank-(k+1) from final histogram
    unsigned cntA = bcA[2] - bcA[1];
    unsigned cntB = bcB[2] - bcB[1];
    bool dupA = ((unsigned)(kA + 1) < cntA);
    bool dupB = ((unsigned)(kB + 1) < cntB);
    bool needA = !dupA && (bcA[3] == 0xFFFFFFFFu);
    bool needB = !dupB && (bcB[3] == 0xFFFFFFFFu);
    unsigned vA1 = dupA ? vkA : ((vkA & 0xFFFFFF00u) | bcA[3]);
    unsigned vB1 = dupB ? vkB : ((vkB & 0xFFFFFF00u) | bcB[3]);
    if (needA || needB) {   // rare; uniform branch
        unsigned mA = 0xFFFFFFFFu, mB = 0xFFFFFFFFu;
        #pragma unroll
        for (int j = 0; j < 4; j++) {
            unsigned v = dv[j];
            if (v > vkA) mA = v < mA ? v : mA;
            if (v > vkB) mB = v < mB ? v : mB;
        }
        #pragma unroll
        for (int o = 16; o; o >>= 1) {
            unsigned t1 = __shfl_xor_sync(0xffffffffu, mA, o); mA = t1 < mA ? t1 : mA;
            unsigned t2 = __shfl_xor_sync(0xffffffffu, mB, o); mB = t2 < mB ? t2 : mB;
        }
        if (lane == 0) { redu[wid] = mA; redu[16 + wid] = mB; }
        __syncthreads();
        if (tid == 0) {
            unsigned smA = 0xFFFFFFFFu, smB = 0xFFFFFFFFu;
            #pragma unroll
            for (int i = 0; i < 16; i++) {
                unsigned t1 = redu[i];      smA = t1 < smA ? t1 : smA;
                unsigned t2 = redu[16 + i]; smB = t2 < smB ? t2 : smB;
            }
            redu[0] = smA; redu[16] = smB;
        }
        __syncthreads();
        if (needA) vA1 = redu[0];
        if (needB) vB1 = redu[16];
    }

    float qa0 = __uint_as_float(vkA), qa1 = __uint_as_float(vA1);
    float qb0 = __uint_as_float(vkB), qb1 = __uint_as_float(vB1);
    float vmin = qa0 + f05 * (qa1 - qa0);
    float vmax = qb0 + f95 * (qb1 - qb0);

    float a  = 1.0f / (1.0f + __expf(-alpha_p[0]));
    float sg = log1pf(__expf(sig_p[0])) + 0.001f;
    float inv2s2 = 1.0f / (2.0f * sg * sg);
    float invZ = 1.0f / Z;
    float iden = 1.0f / (vmax - vmin + 1e-6f);
    float4 rn4 = ((const float4*)rnb)[tid];
    float gg[4] = {g4.x, g4.y, g4.z, g4.w};
    float ssc[4] = {sc4.x, sc4.y, sc4.z, sc4.w};
    float rr[4] = {rn4.x, rn4.y, rn4.z, rn4.w};
    float oo[4];
    #pragma unroll
    for (int j = 0; j < 4; j++) {
        float dist = __uint_as_float(dv[j]);
        float eu = fminf(fmaxf((dist - vmin)*iden, 0.0f), 1.0f);
        float cs = (gg[j]*rns*rr[j] + 1.0f) * 0.5f;
        float hyb = a*cs + (1.0f - a)*(1.0f - eu);
        oo[j] = __expf(ssc[j]*0.125f - hyb*inv2s2) * invZ;
    }
    ((float4*)Erow)[tid] = make_float4(oo[0], oo[1], oo[2], oo[3]);
}

// ---------------- K4: pe64 = E @ x, pure 1x TF32, K-split ----------------
__global__ void __launch_bounds__(256, 2) gemm_Ex_tf32(const float* __restrict__ x) {
    __shared__ __align__(16) float Es[128][36];
    __shared__ __align__(16) float Xs[64][37];
    int part = blockIdx.x;
    int b  = blockIdx.z;
    int s0 = blockIdx.y << 7;
    const float* Eb = g_E + (size_t)b*SS*SS;
    const float* Xb = x   + (size_t)b*SS*FF;
    int tid  = threadIdx.x;
    int lane = tid & 31;
    int wid  = tid >> 5;
    int rb   = (wid & 1) * 64;
    int cb   = (wid >> 1) * 16;
    int lr = lane >> 2, lc = lane & 3;

    float acc[4][2][4];
    #pragma unroll
    for (int i = 0; i < 4; i++)
        #pragma unroll
        for (int j = 0; j < 2; j++)
            #pragma unroll
            for (int r = 0; r < 4; r++) acc[i][j][r] = 0.f;

    int kbeg = part * (SS/KSPLIT);
    for (int k0g = kbeg; k0g < kbeg + SS/KSPLIT; k0g += 32) {
        #pragma unroll
        for (int l = 0; l < 4; l++) {
            int f4 = tid + l*256;
            int r  = f4 >> 3;
            int kc = (f4 & 7) * 4;
            *(float4*)&Es[r][kc] = *(const float4*)&Eb[(size_t)(s0 + r)*SS + k0g + kc];
        }
        #pragma unroll
        for (int l = 0; l < 2; l++) {
            int f4 = tid + l*256;
            int r  = f4 >> 4;
            int cc = (f4 & 15) * 4;
            float4 xv = *(const float4*)&Xb[(size_t)(k0g + r)*FF + cc];
            Xs[cc+0][r] = xv.x; Xs[cc+1][r] = xv.y; Xs[cc+2][r] = xv.z; Xs[cc+3][r] = xv.w;
        }
        __syncthreads();
        #pragma unroll
        for (int k0 = 0; k0 < 32; k0 += 8) {
            unsigned bh[2][2];
            #pragma unroll
            for (int nt = 0; nt < 2; nt++) {
                int n = cb + nt*8 + lr;
                bh[nt][0] = cvt_tf32(Xs[n][k0 + lc]);
                bh[nt][1] = cvt_tf32(Xs[n][k0 + 4 + lc]);
            }
            #pragma unroll
            for (int mt = 0; mt < 4; mt++) {
                int r = rb + mt*16 + lr;
                unsigned ah[4];
                ah[0] = cvt_tf32(Es[r][k0 + lc]);
                ah[1] = cvt_tf32(Es[r + 8][k0 + lc]);
                ah[2] = cvt_tf32(Es[r][k0 + 4 + lc]);
                ah[3] = cvt_tf32(Es[r + 8][k0 + 4 + lc]);
                #pragma unroll
                for (int nt = 0; nt < 2; nt++)
                    mma_tf32(acc[mt][nt], ah[0], ah[1], ah[2], ah[3], bh[nt][0], bh[nt][1]);
            }
        }
        __syncthreads();
    }
    #pragma unroll
    for (int mt = 0; mt < 4; mt++) {
        #pragma unroll
        for (int nt = 0; nt < 2; nt++) {
            int r = s0 + rb + mt*16 + lr;
            int f = cb + nt*8 + (lc << 1);
            size_t base0 = ((size_t)part*NROW + (size_t)b*SS + r)*FF + f;
            size_t base1 = ((size_t)part*NROW + (size_t)b*SS + r + 8)*FF + f;
            *(float2*)&g_pe[base0] = make_float2(acc[mt][nt][0], acc[mt][nt][1]);
            *(float2*)&g_pe[base1] = make_float2(acc[mt][nt][2], acc[mt][nt][3]);
        }
    }
}

// ---------------- K5: pe256 = pe64 @ projW + b ; LN2 ; out += ----------------
__global__ void out_kernel(const float* __restrict__ pW, const float* __restrict__ pb,
                           const float* __restrict__ l2w, const float* __restrict__ l2b,
                           float* __restrict__ out) {
    __shared__ float pe[4][64];
    __shared__ float red[256];
    int r0 = blockIdx.x << 2;
    int tid = threadIdx.x;
    int rr = tid >> 6, f = tid & 63;
    float pv = 0.f;
    #pragma unroll
    for (int p = 0; p < KSPLIT; p++)
        pv += g_pe[((size_t)p*NROW + r0 + rr)*FF + f];
    pe[rr][f] = pv;
    __syncthreads();
    int d = tid;
    float a0 = pb[d], a1 = pb[d], a2 = pb[d], a3 = pb[d];
    #pragma unroll
    for (int ff = 0; ff < FF; ff++) {
        float w = pW[ff*DD + d];
        a0 = fmaf(pe[0][ff], w, a0);
        a1 = fmaf(pe[1][ff], w, a1);
        a2 = fmaf(pe[2][ff], w, a2);
        a3 = fmaf(pe[3][ff], w, a3);
    }
    float w2 = l2w[d], b2 = l2b[d];
    float accs[4] = {a0, a1, a2, a3};
    #pragma unroll
    for (int r = 0; r < 4; r++) {
        float mean = blk_sum256(accs[r], red) * (1.0f / DD);
        float dv = accs[r] - mean;
        float var = blk_sum256(dv*dv, red) * (1.0f / DD);
        size_t idx = (size_t)(r0 + r)*DD + d;
        out[idx] = out[idx] + dv * rsqrtf(var + 1e-5f) * w2 + b2;
    }
}

// ---------------- launch ----------------
extern "C" void kernel_launch(void* const* d_in, const int* in_sizes, int n_in,
                              void* d_out, int out_size) {
    const float* x   = (const float*)d_in[0];
    const float* rW  = (const float*)d_in[1];
    const float* rb  = (const float*)d_in[2];
    const float* pW  = (const float*)d_in[3];
    const float* pb  = (const float*)d_in[4];
    const float* l1w = (const float*)d_in[5];
    const float* l1b = (const float*)d_in[6];
    const float* l2w = (const float*)d_in[7];
    const float* l2b = (const float*)d_in[8];
    const float* al  = (const float*)d_in[9];
    const float* sg  = (const float*)d_in[10];
    const float* lns = (const float*)d_in[11];
    const float* sw  = (const float*)d_in[12];
    const float* qW  = (const float*)d_in[13];
    const float* qb  = (const float*)d_in[14];
    const float* kW  = (const float*)d_in[15];
    const float* kb  = (const float*)d_in[16];
    float* out = (float*)d_out;

    float* qg; float* kg; float* Gg; float* Eg;
    cudaGetSymbolAddress((void**)&Gg, g_G);
    cudaGetSymbolAddress((void**)&Eg, g_E);
    cudaGetSymbolAddress((void**)&qg, g_q);
    cudaGetSymbolAddress((void**)&kg, g_k);

    qk_proj_kernel<<<NROW/4, 256>>>(x, qW, qb, kW, kb);
    rpe_kernel<<<NROW, 256>>>(x, rW, rb, l1w, l1b, lns, sw, out);
    gemm_nt_tf32<<<dim3(SS/128, SS/128, 2*BB), 256>>>(x, qg, kg, Gg, Eg);
    row_kernel<<<NROW, 512>>>(al, sg);
    gemm_Ex_tf32<<<dim3(KSPLIT, SS/128, BB), 256>>>(x);
    out_kernel<<<NROW/4, 256>>>(pW, pb, l2w, l2b, out);
}

// round 8
// speedup vs baseline: 1.1638x; 1.1638x over previous
#include <cuda_runtime.h>
#include <math.h>

#define BB 4
#define SS 2048
#define FF 64
#define DD 256
#define NSC 15
#define NROW (BB*SS)   /* 8192 */
#define KSPLIT 8

// ---------------- device scratch ----------------
__device__ float g_G[(size_t)BB*SS*SS];
__device__ float g_E[(size_t)BB*SS*SS];
__device__ float g_q[NROW*FF];
__device__ float g_k[NROW*FF];
__device__ float g_sq[NROW];
__device__ float g_rn[NROW];
__device__ float g_pe[(size_t)KSPLIT*NROW*FF];

// ---------------- tf32 mma helpers ----------------
__device__ __forceinline__ void mma_tf32(float* c,
                                         unsigned a0, unsigned a1, unsigned a2, unsigned a3,
                                         unsigned b0, unsigned b1) {
    asm volatile(
        "mma.sync.aligned.m16n8k8.row.col.f32.tf32.tf32.f32 "
        "{%0,%1,%2,%3}, {%4,%5,%6,%7}, {%8,%9}, {%0,%1,%2,%3};\n"
        : "+f"(c[0]), "+f"(c[1]), "+f"(c[2]), "+f"(c[3])
        : "r"(a0), "r"(a1), "r"(a2), "r"(a3), "r"(b0), "r"(b1));
}

__device__ __forceinline__ unsigned cvt_tf32(float v) {
    unsigned r;
    asm("cvt.rna.tf32.f32 %0, %1;\n" : "=r"(r) : "f"(v));
    return r;
}

// ---------------- shuffle-based 256-thread sum ----------------
__device__ __forceinline__ float blk_sum256s(float v, volatile float* red) {
    int l = threadIdx.x & 31, w = threadIdx.x >> 5;
    #pragma unroll
    for (int o = 16; o; o >>= 1) v += __shfl_xor_sync(0xffffffffu, v, o);
    if (l == 0) red[w] = v;
    __syncthreads();
    if (threadIdx.x < 32) {
        float s = (l < 8) ? red[l] : 0.f;
        #pragma unroll
        for (int o = 4; o; o >>= 1) s += __shfl_xor_sync(0xffffffffu, s, o);
        if (l == 0) red[0] = s;
    }
    __syncthreads();
    float r = red[0];
    __syncthreads();
    return r;
}

// ---------------- K1a: q/k projections + sq/rn ----------------
__global__ void qk_proj_kernel(const float* __restrict__ x,
                               const float* __restrict__ qW, const float* __restrict__ qb,
                               const float* __restrict__ kW, const float* __restrict__ kb) {
    int row = blockIdx.x * 4 + (threadIdx.x >> 6);
    int f   = threadIdx.x & 63;
    const float* xr = x + (size_t)row * FF;
    float aq = qb[f], ak = kb[f], ss = 0.f;
    #pragma unroll
    for (int k = 0; k < FF; k++) {
        float xv = xr[k];
        aq = fmaf(xv, qW[k*FF + f], aq);
        ak = fmaf(xv, kW[k*FF + f], ak);
        ss = fmaf(xv, xv, ss);
    }
    g_q[(size_t)row*FF + f] = aq;
    g_k[(size_t)row*FF + f] = ak;
    if (f == 0) g_sq[row] = ss;
    if (f == 1) g_rn[row] = 1.0f / fmaxf(sqrtf(ss), 1e-12f);
}

// ---------------- K1c: rpe branch ----------------
__global__ void rpe_kernel(const float* __restrict__ x,
                           const float* __restrict__ rW, const float* __restrict__ rb,
                           const float* __restrict__ l1w, const float* __restrict__ l1b,
                           const float* __restrict__ lns_p, const float* __restrict__ sw,
                           float* __restrict__ out) {
    __shared__ float red[16];
    __shared__ float sh3[3];
    int row = blockIdx.x;
    int b = row >> 11, s = row & (SS - 1);
    int d = threadIdx.x;
    float lns = fminf(fmaxf(lns_p[0], 1.0f), (float)NSC);
    int n = (int)rintf(lns);
    if (d < 32) {
        int sc = d + 1;
        float s0 = 0.f, s1 = 0.f, s2 = 0.f;
        if (sc <= n && s >= sc) {
            const float* xb = x + (size_t)b * SS * FF;
            float ds = xb[(size_t)s*FF + 0];
            float es = xb[(size_t)s*FF + FF - 1];
            float dd = xb[(size_t)(s - sc)*FF + 0] - ds;
            float de = xb[(size_t)(s - sc)*FF + FF - 1] - es;
            float wd = sw[sc - 1] * expf(-fabsf(dd) * exp2f(-(float)sc));
            s0 = dd; s1 = de; s2 = wd;
        }
        #pragma unroll
        for (int o = 16; o; o >>= 1) {
            s0 += __shfl_xor_sync(0xffffffffu, s0, o);
            s1 += __shfl_xor_sync(0xffffffffu, s1, o);
            s2 += __shfl_xor_sync(0xffffffffu, s2, o);
        }
        if (d == 0) { sh3[0] = s0; sh3[1] = s1; sh3[2] = s2; }
    }
    __syncthreads();
    float v = sh3[0]*rW[d] + sh3[1]*rW[DD + d] + sh3[2]*rW[2*DD + d] + (float)n * rb[d];
    float mean = blk_sum256s(v, red) * (1.0f / DD);
    float dv = v - mean;
    float var = blk_sum256s(dv*dv, red) * (1.0f / DD);
    out[(size_t)row*DD + d] = dv * rsqrtf(var + 1e-5f) * l1w[d] + l1b[d];
}

// ---------------- K2: 128x128 tile NT GEMM, pure 1x TF32 (K=64) ----------------
__global__ void __launch_bounds__(256, 2) gemm_nt_tf32(const float* __restrict__ x,
                                                       const float* __restrict__ q,
                                                       const float* __restrict__ k,
                                                       float* __restrict__ G,
                                                       float* __restrict__ E_) {
    __shared__ __align__(16) float As[128][36];
    __shared__ __align__(16) float Bs[128][36];
    int zz = blockIdx.z;
    int b  = zz & 3;
    bool isqk = zz >= 4;
    int s0 = blockIdx.y << 7;
    int t0 = blockIdx.x << 7;
    const float* Ab = (isqk ? q : x) + (size_t)b * SS * FF;
    const float* Bb = (isqk ? k : x) + (size_t)b * SS * FF;
    float*       Cb = (isqk ? E_ : G) + (size_t)b * SS * SS;
    int tid  = threadIdx.x;
    int lane = tid & 31;
    int wid  = tid >> 5;
    int rb   = (wid & 1) * 64;
    int cb   = (wid >> 1) * 32;
    int lr = lane >> 2, lc = lane & 3;

    float acc[4][4][4];
    #pragma unroll
    for (int i = 0; i < 4; i++)
        #pragma unroll
        for (int j = 0; j < 4; j++)
            #pragma unroll
            for (int r = 0; r < 4; r++) acc[i][j][r] = 0.f;

    #pragma unroll
    for (int st = 0; st < 2; st++) {
        int koff = st * 32;
        #pragma unroll
        for (int l = 0; l < 4; l++) {
            int f4 = tid + l*256;
            int r  = f4 >> 3;
            int kc = (f4 & 7) * 4;
            *(float4*)&As[r][kc] = *(const float4*)&Ab[(size_t)(s0 + r)*FF + koff + kc];
            *(float4*)&Bs[r][kc] = *(const float4*)&Bb[(size_t)(t0 + r)*FF + koff + kc];
        }
        __syncthreads();
        #pragma unroll
        for (int k0 = 0; k0 < 32; k0 += 8) {
            unsigned bh[4][2];
            #pragma unroll
            for (int nt = 0; nt < 4; nt++) {
                int n = cb + nt*8 + lr;
                bh[nt][0] = cvt_tf32(Bs[n][k0 + lc]);
                bh[nt][1] = cvt_tf32(Bs[n][k0 + 4 + lc]);
            }
            #pragma unroll
            for (int mt = 0; mt < 4; mt++) {
                int r = rb + mt*16 + lr;
                unsigned ah[4];
                ah[0] = cvt_tf32(As[r][k0 + lc]);
                ah[1] = cvt_tf32(As[r + 8][k0 + lc]);
                ah[2] = cvt_tf32(As[r][k0 + 4 + lc]);
                ah[3] = cvt_tf32(As[r + 8][k0 + 4 + lc]);
                #pragma unroll
                for (int nt = 0; nt < 4; nt++)
                    mma_tf32(acc[mt][nt], ah[0], ah[1], ah[2], ah[3], bh[nt][0], bh[nt][1]);
            }
        }
        __syncthreads();
    }
    #pragma unroll
    for (int mt = 0; mt < 4; mt++) {
        #pragma unroll
        for (int nt = 0; nt < 4; nt++) {
            int r    = s0 + rb + mt*16 + lr;
            int cidx = t0 + cb + nt*8 + (lc << 1);
            *(float2*)&Cb[(size_t)r*SS + cidx]       = make_float2(acc[mt][nt][0], acc[mt][nt][1]);
            *(float2*)&Cb[(size_t)(r + 8)*SS + cidx] = make_float2(acc[mt][nt][2], acc[mt][nt][3]);
        }
    }
}

// ---------------- K3: row kernel v5 (R5 shape + reg cap) ----------------
__global__ void __launch_bounds__(512, 3) row_kernel(const float* __restrict__ alpha_p,
                                                     const float* __restrict__ sig_p) {
    __shared__ unsigned h[2][2][256];   // [parity][query][bin]
    __shared__ float redf[16];
    __shared__ unsigned redu[48];
    __shared__ unsigned bcA[2];
    __shared__ unsigned bcB[2];
    int row = blockIdx.x;
    int b = row >> 11, s = row & (SS - 1);
    int tid = threadIdx.x;
    int lane = tid & 31, wid = tid >> 5;
    const float* Grow = g_G + (size_t)b*SS*SS + (size_t)s*SS;
    float*       Erow = g_E + (size_t)b*SS*SS + (size_t)s*SS;
    const float* sqb = g_sq + b*SS;
    const float* rnb = g_rn + b*SS;
    float sqs = sqb[s], rns = rnb[s];

    ((unsigned*)h)[tid]       = 0;
    ((unsigned*)h)[tid + 512] = 0;
    __syncthreads();

    float4 g4  = ((const float4*)Grow)[tid];
    float4 sc4 = ((const float4*)Erow)[tid];
    unsigned dv[4];
    {
        float4 sq4 = ((const float4*)sqb)[tid];
        float d2[4] = {fmaxf(sqs + sq4.x - 2.0f*g4.x, 0.0f),
                       fmaxf(sqs + sq4.y - 2.0f*g4.y, 0.0f),
                       fmaxf(sqs + sq4.z - 2.0f*g4.z, 0.0f),
                       fmaxf(sqs + sq4.w - 2.0f*g4.w, 0.0f)};
        #pragma unroll
        for (int j = 0; j < 4; j++) dv[j] = __float_as_uint(sqrtf(d2[j]));
    }
    // level-0 histogram (exponent byte), warp-aggregated
    #pragma unroll
    for (int j = 0; j < 4; j++) {
        unsigned bin = dv[j] >> 24;
        unsigned mask = __match_any_sync(0xffffffffu, bin);
        if ((unsigned)(__ffs(mask) - 1) == (unsigned)lane)
            atomicAdd(&h[0][0][bin], (unsigned)__popc(mask));
    }
    // Z without max shift (scores ~ N(0,1); exp safe in fp32)
    float z = __expf(sc4.x*0.125f) + __expf(sc4.y*0.125f)
            + __expf(sc4.z*0.125f) + __expf(sc4.w*0.125f);
    #pragma unroll
    for (int o = 16; o; o >>= 1) z += __shfl_xor_sync(0xffffffffu, z, o);
    if (lane == 0) redf[wid] = z;
    __syncthreads();

    const float fp05 = 0.05f * (float)(SS - 1);
    const int   l05 = (int)fp05; const float f05 = fp05 - (float)l05;
    const float fp95 = 0.95f * (float)(SS - 1);
    const int   l95 = (int)fp95; const float f95 = fp95 - (float)l95;
    int kA = l05, kB = l95;

    // level-0 find (warp0->A, warp1->B); warp 2 reduces Z
    if (wid < 2) {
        int kq = wid ? kB : kA;
        volatile unsigned* bcq = wid ? bcB : bcA;
        unsigned vals[8]; unsigned sv = 0;
        #pragma unroll
        for (int j = 0; j < 8; j++) { vals[j] = h[0][0][lane*8 + j]; sv += vals[j]; }
        unsigned e = sv;
        #pragma unroll
        for (int o = 1; o < 32; o <<= 1) {
            unsigned t = __shfl_up_sync(0xffffffffu, e, o);
            if (lane >= o) e += t;
        }
        e -= sv;
        unsigned run = e;
        #pragma unroll
        for (int j = 0; j < 8; j++) {
            unsigned excl = run; run += vals[j];
            if (excl <= (unsigned)kq && (unsigned)kq < run) {
                bcq[0] = (unsigned)(lane*8 + j); bcq[1] = excl;
            }
        }
    } else if (wid == 2 && lane == 0) {
        float sz = 0.f;
        #pragma unroll
        for (int i = 0; i < 16; i++) sz += redf[i];
        redf[0] = sz;
    }
    __syncthreads();
    unsigned prefA = bcA[0] << 24;  kA -= (int)bcA[1];
    unsigned prefB = bcB[0] << 24;  kB -= (int)bcB[1];
    float Z = redf[0];

    // refine: shift = 16, 8, 0 with ping-pong buffers
    #pragma unroll
    for (int lev = 0; lev < 3; lev++) {
        int shift = 16 - 8*lev;
        int p = (lev & 1) ^ 1;
        unsigned himask = 0xFFFFFFFFu << (shift + 8);
        #pragma unroll
        for (int j = 0; j < 4; j++) {
            unsigned v = dv[j];
            unsigned bin = (v >> shift) & 255u;
            if ((v & himask) == prefA) atomicAdd(&h[p][0][bin], 1u);
            if ((v & himask) == prefB) atomicAdd(&h[p][1][bin], 1u);
        }
        __syncthreads();
        if (wid < 2) {
            int kq = wid ? kB : kA;
            volatile unsigned* bcq = wid ? bcB : bcA;
            unsigned vals[8]; unsigned sv = 0;
            #pragma unroll
            for (int j = 0; j < 8; j++) { vals[j] = h[p][wid][lane*8 + j]; sv += vals[j]; }
            unsigned e = sv;
            #pragma unroll
            for (int o = 1; o < 32; o <<= 1) {
                unsigned t = __shfl_up_sync(0xffffffffu, e, o);
                if (lane >= o) e += t;
            }
            e -= sv;
            unsigned run = e;
            #pragma unroll
            for (int j = 0; j < 8; j++) {
                unsigned excl = run; run += vals[j];
                if (excl <= (unsigned)kq && (unsigned)kq < run) {
                    bcq[0] = (unsigned)(lane*8 + j); bcq[1] = excl;
                }
            }
        } else if (wid == 2 || wid == 3) {
            #pragma unroll
            for (int j = 0; j < 8; j++) h[p ^ 1][wid - 2][lane*8 + j] = 0;
        }
        __syncthreads();
        prefA |= bcA[0] << shift;  kA -= (int)bcA[1];
        prefB |= bcB[0] << shift;  kB -= (int)bcB[1];
    }
    unsigned vkA = prefA, vkB = prefB;

    // fused neighbor/count pass (rank k+1 values)
    unsigned cA = 0, cB = 0, mA = 0xFFFFFFFFu, mB = 0xFFFFFFFFu;
    #pragma unroll
    for (int j = 0; j < 4; j++) {
        unsigned v = dv[j];
        if (v <= vkA) cA++; else mA = v < mA ? v : mA;
        if (v <= vkB) cB++; else mB = v < mB ? v : mB;
    }
    unsigned cp = cA | (cB << 16);
    #pragma unroll
    for (int o = 16; o; o >>= 1) {
        cp += __shfl_xor_sync(0xffffffffu, cp, o);
        unsigned t1 = __shfl_xor_sync(0xffffffffu, mA, o); mA = t1 < mA ? t1 : mA;
        unsigned t2 = __shfl_xor_sync(0xffffffffu, mB, o); mB = t2 < mB ? t2 : mB;
    }
    if (lane == 0) { redu[wid] = cp; redu[16 + wid] = mA; redu[32 + wid] = mB; }
    __syncthreads();
    if (tid == 0) {
        unsigned scp = 0, smA = 0xFFFFFFFFu, smB = 0xFFFFFFFFu;
        #pragma unroll
        for (int i = 0; i < 16; i++) {
            scp += redu[i];
            unsigned t1 = redu[16 + i]; smA = t1 < smA ? t1 : smA;
            unsigned t2 = redu[32 + i]; smB = t2 < smB ? t2 : smB;
        }
        redu[0] = scp; redu[16] = smA; redu[32] = smB;
    }
    __syncthreads();
    unsigned cleA = redu[0] & 0xFFFFu, cleB = redu[0] >> 16;
    unsigned vA1 = (cleA >= (unsigned)(l05 + 2)) ? vkA : redu[16];
    unsigned vB1 = (cleB >= (unsigned)(l95 + 2)) ? vkB : redu[32];

    float qa0 = __uint_as_float(vkA), qa1 = __uint_as_float(vA1);
    float qb0 = __uint_as_float(vkB), qb1 = __uint_as_float(vB1);
    float vmin = qa0 + f05 * (qa1 - qa0);
    float vmax = qb0 + f95 * (qb1 - qb0);

    float a  = 1.0f / (1.0f + __expf(-alpha_p[0]));
    float sg = log1pf(__expf(sig_p[0])) + 0.001f;
    float inv2s2 = 1.0f / (2.0f * sg * sg);
    float invZ = 1.0f / Z;
    float iden = 1.0f / (vmax - vmin + 1e-6f);
    float4 rn4 = ((const float4*)rnb)[tid];
    float gg[4] = {g4.x, g4.y, g4.z, g4.w};
    float ssc[4] = {sc4.x, sc4.y, sc4.z, sc4.w};
    float rr[4] = {rn4.x, rn4.y, rn4.z, rn4.w};
    float oo[4];
    #pragma unroll
    for (int j = 0; j < 4; j++) {
        float dist = __uint_as_float(dv[j]);
        float eu = fminf(fmaxf((dist - vmin)*iden, 0.0f), 1.0f);
        float cs = (gg[j]*rns*rr[j] + 1.0f) * 0.5f;
        float hyb = a*cs + (1.0f - a)*(1.0f - eu);
        oo[j] = __expf(ssc[j]*0.125f - hyb*inv2s2) * invZ;
    }
    ((float4*)Erow)[tid] = make_float4(oo[0], oo[1], oo[2], oo[3]);
}

// ---------------- K4: pe64 = E @ x, pure 1x TF32, K-split ----------------
__global__ void __launch_bounds__(256, 2) gemm_Ex_tf32(const float* __restrict__ x) {
    __shared__ __align__(16) float Es[128][36];
    __shared__ __align__(16) float Xs[64][37];
    int part = blockIdx.x;
    int b  = blockIdx.z;
    int s0 = blockIdx.y << 7;
    const float* Eb = g_E + (size_t)b*SS*SS;
    const float* Xb = x   + (size_t)b*SS*FF;
    int tid  = threadIdx.x;
    int lane = tid & 31;
    int wid  = tid >> 5;
    int rb   = (wid & 1) * 64;
    int cb   = (wid >> 1) * 16;
    int lr = lane >> 2, lc = lane & 3;

    float acc[4][2][4];
    #pragma unroll
    for (int i = 0; i < 4; i++)
        #pragma unroll
        for (int j = 0; j < 2; j++)
            #pragma unroll
            for (int r = 0; r < 4; r++) acc[i][j][r] = 0.f;

    int kbeg = part * (SS/KSPLIT);
    for (int k0g = kbeg; k0g < kbeg + SS/KSPLIT; k0g += 32) {
        #pragma unroll
        for (int l = 0; l < 4; l++) {
            int f4 = tid + l*256;
            int r  = f4 >> 3;
            int kc = (f4 & 7) * 4;
            *(float4*)&Es[r][kc] = *(const float4*)&Eb[(size_t)(s0 + r)*SS + k0g + kc];
        }
        #pragma unroll
        for (int l = 0; l < 2; l++) {
            int f4 = tid + l*256;
            int r  = f4 >> 4;
            int cc = (f4 & 15) * 4;
            float4 xv = *(const float4*)&Xb[(size_t)(k0g + r)*FF + cc];
            Xs[cc+0][r] = xv.x; Xs[cc+1][r] = xv.y; Xs[cc+2][r] = xv.z; Xs[cc+3][r] = xv.w;
        }
        __syncthreads();
        #pragma unroll
        for (int k0 = 0; k0 < 32; k0 += 8) {
            unsigned bh[2][2];
            #pragma unroll
            for (int nt = 0; nt < 2; nt++) {
                int n = cb + nt*8 + lr;
                bh[nt][0] = cvt_tf32(Xs[n][k0 + lc]);
                bh[nt][1] = cvt_tf32(Xs[n][k0 + 4 + lc]);
            }
            #pragma unroll
            for (int mt = 0; mt < 4; mt++) {
                int r = rb + mt*16 + lr;
                unsigned ah[4];
                ah[0] = cvt_tf32(Es[r][k0 + lc]);
                ah[1] = cvt_tf32(Es[r + 8][k0 + lc]);
                ah[2] = cvt_tf32(Es[r][k0 + 4 + lc]);
                ah[3] = cvt_tf32(Es[r + 8][k0 + 4 + lc]);
                #pragma unroll
                for (int nt = 0; nt < 2; nt++)
                    mma_tf32(acc[mt][nt], ah[0], ah[1], ah[2], ah[3], bh[nt][0], bh[nt][1]);
            }
        }
        __syncthreads();
    }
    #pragma unroll
    for (int mt = 0; mt < 4; mt++) {
        #pragma unroll
        for (int nt = 0; nt < 2; nt++) {
            int r = s0 + rb + mt*16 + lr;
            int f = cb + nt*8 + (lc << 1);
            size_t base0 = ((size_t)part*NROW + (size_t)b*SS + r)*FF + f;
            size_t base1 = ((size_t)part*NROW + (size_t)b*SS + r + 8)*FF + f;
            *(float2*)&g_pe[base0] = make_float2(acc[mt][nt][0], acc[mt][nt][1]);
            *(float2*)&g_pe[base1] = make_float2(acc[mt][nt][2], acc[mt][nt][3]);
        }
    }
}

// ---------------- K5: pe256 = pe64 @ projW + b ; LN2 ; out += ----------------
__global__ void out_kernel(const float* __restrict__ pW, const float* __restrict__ pb,
                           const float* __restrict__ l2w, const float* __restrict__ l2b,
                           float* __restrict__ out) {
    __shared__ float pe[4][64];
    __shared__ float red[16];
    int r0 = blockIdx.x << 2;
    int tid = threadIdx.x;
    int rr = tid >> 6, f = tid & 63;
    float pv = 0.f;
    #pragma unroll
    for (int p = 0; p < KSPLIT; p++)
        pv += g_pe[((size_t)p*NROW + r0 + rr)*FF + f];
    pe[rr][f] = pv;
    __syncthreads();
    int d = tid;
    float a0 = pb[d], a1 = pb[d], a2 = pb[d], a3 = pb[d];
    #pragma unroll
    for (int ff = 0; ff < FF; ff++) {
        float w = pW[ff*DD + d];
        a0 = fmaf(pe[0][ff], w, a0);
        a1 = fmaf(pe[1][ff], w, a1);
        a2 = fmaf(pe[2][ff], w, a2);
        a3 = fmaf(pe[3][ff], w, a3);
    }
    float w2 = l2w[d], b2 = l2b[d];
    float accs[4] = {a0, a1, a2, a3};
    #pragma unroll
    for (int r = 0; r < 4; r++) {
        float mean = blk_sum256s(accs[r], red) * (1.0f / DD);
        float dv = accs[r] - mean;
        float var = blk_sum256s(dv*dv, red) * (1.0f / DD);
        size_t idx = (size_t)(r0 + r)*DD + d;
        out[idx] = out[idx] + dv * rsqrtf(var + 1e-5f) * w2 + b2;
    }
}

// ---------------- launch ----------------
extern "C" void kernel_launch(void* const* d_in, const int* in_sizes, int n_in,
                              void* d_out, int out_size) {
    const float* x   = (const float*)d_in[0];
    const float* rW  = (const float*)d_in[1];
    const float* rb  = (const float*)d_in[2];
    const float* pW  = (const float*)d_in[3];
    const float* pb  = (const float*)d_in[4];
    const float* l1w = (const float*)d_in[5];
    const float* l1b = (const float*)d_in[6];
    const float* l2w = (const float*)d_in[7];
    const float* l2b = (const float*)d_in[8];
    const float* al  = (const float*)d_in[9];
    const float* sg  = (const float*)d_in[10];
    const float* lns = (const float*)d_in[11];
    const float* sw  = (const float*)d_in[12];
    const float* qW  = (const float*)d_in[13];
    const float* qb  = (const float*)d_in[14];
    const float* kW  = (const float*)d_in[15];
    const float* kb  = (const float*)d_in[16];
    float* out = (float*)d_out;

    float* qg; float* kg; float* Gg; float* Eg;
    cudaGetSymbolAddress((void**)&Gg, g_G);
    cudaGetSymbolAddress((void**)&Eg, g_E);
    cudaGetSymbolAddress((void**)&qg, g_q);
    cudaGetSymbolAddress((void**)&kg, g_k);

    qk_proj_kernel<<<NROW/4, 256>>>(x, qW, qb, kW, kb);
    rpe_kernel<<<NROW, 256>>>(x, rW, rb, l1w, l1b, lns, sw, out);
    gemm_nt_tf32<<<dim3(SS/128, SS/128, 2*BB), 256>>>(x, qg, kg, Gg, Eg);
    row_kernel<<<NROW, 512>>>(al, sg);
    gemm_Ex_tf32<<<dim3(KSPLIT, SS/128, BB), 256>>>(x);
    out_kernel<<<NROW/4, 256>>>(pW, pb, l2w, l2b, out);
}

// round 10
// speedup vs baseline: 1.2738x; 1.0946x over previous
#include <cuda_runtime.h>
#include <math.h>

#define BB 4
#define SS 2048
#define FF 64
#define DD 256
#define NSC 15
#define NROW (BB*SS)   /* 8192 */
#define KSPLIT 8
#define NB 4096        /* histogram bins for quantile */

// ---------------- device scratch ----------------
__device__ float g_G[(size_t)BB*SS*SS];
__device__ float g_E[(size_t)BB*SS*SS];
__device__ float g_q[NROW*FF];
__device__ float g_k[NROW*FF];
__device__ float g_sq[NROW];
__device__ float g_rn[NROW];
__device__ float g_pe[(size_t)KSPLIT*NROW*FF];

// ---------------- tf32 mma helpers ----------------
__device__ __forceinline__ void mma_tf32(float* c,
                                         unsigned a0, unsigned a1, unsigned a2, unsigned a3,
                                         unsigned b0, unsigned b1) {
    asm volatile(
        "mma.sync.aligned.m16n8k8.row.col.f32.tf32.tf32.f32 "
        "{%0,%1,%2,%3}, {%4,%5,%6,%7}, {%8,%9}, {%0,%1,%2,%3};\n"
        : "+f"(c[0]), "+f"(c[1]), "+f"(c[2]), "+f"(c[3])
        : "r"(a0), "r"(a1), "r"(a2), "r"(a3), "r"(b0), "r"(b1));
}

__device__ __forceinline__ unsigned cvt_tf32(float v) {
    unsigned r;
    asm("cvt.rna.tf32.f32 %0, %1;\n" : "=r"(r) : "f"(v));
    return r;
}

__device__ __forceinline__ float sqrt_approx(float x) {
    float r;
    asm("sqrt.approx.f32 %0, %1;\n" : "=f"(r) : "f"(x));
    return r;
}

// ---------------- shuffle-based 256-thread sum ----------------
__device__ __forceinline__ float blk_sum256s(float v, volatile float* red) {
    int l = threadIdx.x & 31, w = threadIdx.x >> 5;
    #pragma unroll
    for (int o = 16; o; o >>= 1) v += __shfl_xor_sync(0xffffffffu, v, o);
    if (l == 0) red[w] = v;
    __syncthreads();
    if (threadIdx.x < 32) {
        float s = (l < 8) ? red[l] : 0.f;
        #pragma unroll
        for (int o = 4; o; o >>= 1) s += __shfl_xor_sync(0xffffffffu, s, o);
        if (l == 0) red[0] = s;
    }
    __syncthreads();
    float r = red[0];
    __syncthreads();
    return r;
}

// ---------------- K1a: q/k projections + sq/rn ----------------
__global__ void qk_proj_kernel(const float* __restrict__ x,
                               const float* __restrict__ qW, const float* __restrict__ qb,
                               const float* __restrict__ kW, const float* __restrict__ kb) {
    int row = blockIdx.x * 4 + (threadIdx.x >> 6);
    int f   = threadIdx.x & 63;
    const float* xr = x + (size_t)row * FF;
    float aq = qb[f], ak = kb[f], ss = 0.f;
    #pragma unroll
    for (int k = 0; k < FF; k++) {
        float xv = xr[k];
        aq = fmaf(xv, qW[k*FF + f], aq);
        ak = fmaf(xv, kW[k*FF + f], ak);
        ss = fmaf(xv, xv, ss);
    }
    g_q[(size_t)row*FF + f] = aq;
    g_k[(size_t)row*FF + f] = ak;
    if (f == 0) g_sq[row] = ss;
    if (f == 1) g_rn[row] = 1.0f / fmaxf(sqrtf(ss), 1e-12f);
}

// ---------------- K1c: rpe branch ----------------
__global__ void rpe_kernel(const float* __restrict__ x,
                           const float* __restrict__ rW, const float* __restrict__ rb,
                           const float* __restrict__ l1w, const float* __restrict__ l1b,
                           const float* __restrict__ lns_p, const float* __restrict__ sw,
                           float* __restrict__ out) {
    __shared__ float red[16];
    __shared__ float sh3[3];
    int row = blockIdx.x;
    int b = row >> 11, s = row & (SS - 1);
    int d = threadIdx.x;
    float lns = fminf(fmaxf(lns_p[0], 1.0f), (float)NSC);
    int n = (int)rintf(lns);
    if (d < 32) {
        int sc = d + 1;
        float s0 = 0.f, s1 = 0.f, s2 = 0.f;
        if (sc <= n && s >= sc) {
            const float* xb = x + (size_t)b * SS * FF;
            float ds = xb[(size_t)s*FF + 0];
            float es = xb[(size_t)s*FF + FF - 1];
            float dd = xb[(size_t)(s - sc)*FF + 0] - ds;
            float de = xb[(size_t)(s - sc)*FF + FF - 1] - es;
            float wd = sw[sc - 1] * expf(-fabsf(dd) * exp2f(-(float)sc));
            s0 = dd; s1 = de; s2 = wd;
        }
        #pragma unroll
        for (int o = 16; o; o >>= 1) {
            s0 += __shfl_xor_sync(0xffffffffu, s0, o);
            s1 += __shfl_xor_sync(0xffffffffu, s1, o);
            s2 += __shfl_xor_sync(0xffffffffu, s2, o);
        }
        if (d == 0) { sh3[0] = s0; sh3[1] = s1; sh3[2] = s2; }
    }
    __syncthreads();
    float v = sh3[0]*rW[d] + sh3[1]*rW[DD + d] + sh3[2]*rW[2*DD + d] + (float)n * rb[d];
    float mean = blk_sum256s(v, red) * (1.0f / DD);
    float dv = v - mean;
    float var = blk_sum256s(dv*dv, red) * (1.0f / DD);
    out[(size_t)row*DD + d] = dv * rsqrtf(var + 1e-5f) * l1w[d] + l1b[d];
}

// ---------------- K2: 128x128 tile NT GEMM, pure 1x TF32 (K=64) ----------------
__global__ void __launch_bounds__(256, 2) gemm_nt_tf32(const float* __restrict__ x,
                                                       const float* __restrict__ q,
                                                       const float* __restrict__ k,
                                                       float* __restrict__ G,
                                                       float* __restrict__ E_) {
    __shared__ __align__(16) float As[128][36];
    __shared__ __align__(16) float Bs[128][36];
    int zz = blockIdx.z;
    int b  = zz & 3;
    bool isqk = zz >= 4;
    int s0 = blockIdx.y << 7;
    int t0 = blockIdx.x << 7;
    const float* Ab = (isqk ? q : x) + (size_t)b * SS * FF;
    const float* Bb = (isqk ? k : x) + (size_t)b * SS * FF;
    float*       Cb = (isqk ? E_ : G) + (size_t)b * SS * SS;
    int tid  = threadIdx.x;
    int lane = tid & 31;
    int wid  = tid >> 5;
    int rb   = (wid & 1) * 64;
    int cb   = (wid >> 1) * 32;
    int lr = lane >> 2, lc = lane & 3;

    float acc[4][4][4];
    #pragma unroll
    for (int i = 0; i < 4; i++)
        #pragma unroll
        for (int j = 0; j < 4; j++)
            #pragma unroll
            for (int r = 0; r < 4; r++) acc[i][j][r] = 0.f;

    #pragma unroll
    for (int st = 0; st < 2; st++) {
        int koff = st * 32;
        #pragma unroll
        for (int l = 0; l < 4; l++) {
            int f4 = tid + l*256;
            int r  = f4 >> 3;
            int kc = (f4 & 7) * 4;
            *(float4*)&As[r][kc] = *(const float4*)&Ab[(size_t)(s0 + r)*FF + koff + kc];
            *(float4*)&Bs[r][kc] = *(const float4*)&Bb[(size_t)(t0 + r)*FF + koff + kc];
        }
        __syncthreads();
        #pragma unroll
        for (int k0 = 0; k0 < 32; k0 += 8) {
            unsigned bh[4][2];
            #pragma unroll
            for (int nt = 0; nt < 4; nt++) {
                int n = cb + nt*8 + lr;
                bh[nt][0] = cvt_tf32(Bs[n][k0 + lc]);
                bh[nt][1] = cvt_tf32(Bs[n][k0 + 4 + lc]);
            }
            #pragma unroll
            for (int mt = 0; mt < 4; mt++) {
                int r = rb + mt*16 + lr;
                unsigned ah[4];
                ah[0] = cvt_tf32(As[r][k0 + lc]);
                ah[1] = cvt_tf32(As[r + 8][k0 + lc]);
                ah[2] = cvt_tf32(As[r][k0 + 4 + lc]);
                ah[3] = cvt_tf32(As[r + 8][k0 + 4 + lc]);
                #pragma unroll
                for (int nt = 0; nt < 4; nt++)
                    mma_tf32(acc[mt][nt], ah[0], ah[1], ah[2], ah[3], bh[nt][0], bh[nt][1]);
            }
        }
        __syncthreads();
    }
    #pragma unroll
    for (int mt = 0; mt < 4; mt++) {
        #pragma unroll
        for (int nt = 0; nt < 4; nt++) {
            int r    = s0 + rb + mt*16 + lr;
            int cidx = t0 + cb + nt*8 + (lc << 1);
            *(float2*)&Cb[(size_t)r*SS + cidx]       = make_float2(acc[mt][nt][0], acc[mt][nt][1]);
            *(float2*)&Cb[(size_t)(r + 8)*SS + cidx] = make_float2(acc[mt][nt][2], acc[mt][nt][3]);
        }
    }
}

// ---------------- K3: row kernel v6 — histogram quantile ----------------
__global__ void __launch_bounds__(512, 3) row_kernel(const float* __restrict__ alpha_p,
                                                     const float* __restrict__ sig_p) {
    __shared__ unsigned hist[NB];       // 16 KB
    __shared__ float redf[3][16];       // min/max/z warp partials
    __shared__ float stat[3];           // d2min, d2max, Z
    __shared__ unsigned woff[16];
    __shared__ unsigned bq[6];          // {exclA,cntA,binA, exclB,cntB,binB}
    int row = blockIdx.x;
    int b = row >> 11, s = row & (SS - 1);
    int tid = threadIdx.x;
    int lane = tid & 31, wid = tid >> 5;
    const float* Grow = g_G + (size_t)b*SS*SS + (size_t)s*SS;
    float*       Erow = g_E + (size_t)b*SS*SS + (size_t)s*SS;
    const float* sqb = g_sq + b*SS;
    const float* rnb = g_rn + b*SS;
    float sqs = sqb[s], rns = rnb[s];

    // zero histogram (covered by the reduction barrier below)
    #pragma unroll
    for (int j = 0; j < 8; j++) hist[tid + j*512] = 0;

    // pass 1: load, d2, min/max/Z partials
    float4 g4  = ((const float4*)Grow)[tid];
    float4 sc4 = ((const float4*)Erow)[tid];
    float d2[4];
    {
        float4 sq4 = ((const float4*)sqb)[tid];
        d2[0] = fmaxf(sqs + sq4.x - 2.0f*g4.x, 0.0f);
        d2[1] = fmaxf(sqs + sq4.y - 2.0f*g4.y, 0.0f);
        d2[2] = fmaxf(sqs + sq4.z - 2.0f*g4.z, 0.0f);
        d2[3] = fmaxf(sqs + sq4.w - 2.0f*g4.w, 0.0f);
    }
    float mn = fminf(fminf(d2[0], d2[1]), fminf(d2[2], d2[3]));
    float mx = fmaxf(fmaxf(d2[0], d2[1]), fmaxf(d2[2], d2[3]));
    float z = __expf(sc4.x*0.125f) + __expf(sc4.y*0.125f)
            + __expf(sc4.z*0.125f) + __expf(sc4.w*0.125f);
    #pragma unroll
    for (int o = 16; o; o >>= 1) {
        mn = fminf(mn, __shfl_xor_sync(0xffffffffu, mn, o));
        mx = fmaxf(mx, __shfl_xor_sync(0xffffffffu, mx, o));
        z += __shfl_xor_sync(0xffffffffu, z, o);
    }
    if (lane == 0) { redf[0][wid] = mn; redf[1][wid] = mx; redf[2][wid] = z; }
    __syncthreads();
    if (tid == 0) {
        float m0 = redf[0][0], m1 = redf[1][0], zz = redf[2][0];
        #pragma unroll
        for (int i = 1; i < 16; i++) {
            m0 = fminf(m0, redf[0][i]);
            m1 = fmaxf(m1, redf[1][i]);
            zz += redf[2][i];
        }
        stat[0] = m0; stat[1] = m1; stat[2] = zz;
    }
    __syncthreads();
    float d2min = stat[0], d2max = stat[1], Z = stat[2];
    float w   = (d2max - d2min) * (1.0f / NB);
    float iw  = (float)NB / fmaxf(d2max - d2min, 1e-30f);

    // histogram
    #pragma unroll
    for (int j = 0; j < 4; j++) {
        int bin = (int)((d2[j] - d2min) * iw);
        bin = bin < NB-1 ? bin : NB-1;
        bin = bin > 0 ? bin : 0;
        atomicAdd(&hist[bin], 1u);
    }
    __syncthreads();

    // prefix scan over NB bins (8 per thread, contiguous)
    uint4 v0 = ((const uint4*)hist)[tid*2];
    uint4 v1 = ((const uint4*)hist)[tid*2 + 1];
    unsigned vals[8] = {v0.x, v0.y, v0.z, v0.w, v1.x, v1.y, v1.z, v1.w};
    unsigned st = 0;
    #pragma unroll
    for (int j = 0; j < 8; j++) st += vals[j];
    unsigned e = st;
    #pragma unroll
    for (int o = 1; o < 32; o <<= 1) {
        unsigned t = __shfl_up_sync(0xffffffffu, e, o);
        if (lane >= o) e += t;
    }
    if (lane == 31) woff[wid] = e;     // warp total
    unsigned lexcl = e - st;           // lane-exclusive within warp
    __syncthreads();
    if (tid < 32) {
        unsigned t = (lane < 16) ? woff[lane] : 0u;
        unsigned ei = t;
        #pragma unroll
        for (int o = 1; o < 16; o <<= 1) {
            unsigned u = __shfl_up_sync(0xffffffffu, ei, o);
            if (lane >= o) ei += u;
        }
        if (lane < 16) woff[lane] = ei - t;   // warp-exclusive
    }
    __syncthreads();
    {
        unsigned run = woff[wid] + lexcl;
        #pragma unroll
        for (int j = 0; j < 8; j++) {
            unsigned excl = run; run += vals[j];
            if (excl <= 102u && 102u < run)  { bq[0] = excl; bq[1] = vals[j]; bq[2] = (unsigned)(tid*8 + j); }
            if (excl <= 1944u && 1944u < run){ bq[3] = excl; bq[4] = vals[j]; bq[5] = (unsigned)(tid*8 + j); }
        }
    }
    __syncthreads();

    // quantiles with sub-bin interpolation (continuous ranks 102.35 / 1944.65)
    float frA = (102.35f  - (float)bq[0] + 0.5f) / (float)bq[1];
    float frB = (1944.65f - (float)bq[3] + 0.5f) / (float)bq[4];
    frA = fminf(fmaxf(frA, 0.0f), 1.0f);
    frB = fminf(fmaxf(frB, 0.0f), 1.0f);
    float vmin = sqrt_approx(fmaxf(d2min + ((float)bq[2] + frA) * w, 0.0f));
    float vmax = sqrt_approx(fmaxf(d2min + ((float)bq[5] + frB) * w, 0.0f));

    float a  = 1.0f / (1.0f + __expf(-alpha_p[0]));
    float sg = log1pf(__expf(sig_p[0])) + 0.001f;
    float inv2s2 = 1.0f / (2.0f * sg * sg);
    float invZ = 1.0f / Z;
    float iden = 1.0f / (vmax - vmin + 1e-6f);
    float4 rn4 = ((const float4*)rnb)[tid];
    float gg[4] = {g4.x, g4.y, g4.z, g4.w};
    float ssc[4] = {sc4.x, sc4.y, sc4.z, sc4.w};
    float rr[4] = {rn4.x, rn4.y, rn4.z, rn4.w};
    float oo[4];
    #pragma unroll
    for (int j = 0; j < 4; j++) {
        float dist = sqrt_approx(d2[j]);
        float eu = fminf(fmaxf((dist - vmin)*iden, 0.0f), 1.0f);
        float cs = (gg[j]*rns*rr[j] + 1.0f) * 0.5f;
        float hyb = a*cs + (1.0f - a)*(1.0f - eu);
        oo[j] = __expf(ssc[j]*0.125f - hyb*inv2s2) * invZ;
    }
    ((float4*)Erow)[tid] = make_float4(oo[0], oo[1], oo[2], oo[3]);
}

// ---------------- K4: pe64 = E @ x, pure 1x TF32, K-split ----------------
__global__ void __launch_bounds__(256, 2) gemm_Ex_tf32(const float* __restrict__ x) {
    __shared__ __align__(16) float Es[128][36];
    __shared__ __align__(16) float Xs[64][37];
    int part = blockIdx.x;
    int b  = blockIdx.z;
    int s0 = blockIdx.y << 7;
    const float* Eb = g_E + (size_t)b*SS*SS;
    const float* Xb = x   + (size_t)b*SS*FF;
    int tid  = threadIdx.x;
    int lane = tid & 31;
    int wid  = tid >> 5;
    int rb   = (wid & 1) * 64;
    int cb   = (wid >> 1) * 16;
    int lr = lane >> 2, lc = lane & 3;

    float acc[4][2][4];
    #pragma unroll
    for (int i = 0; i < 4; i++)
        #pragma unroll
        for (int j = 0; j < 2; j++)
            #pragma unroll
            for (int r = 0; r < 4; r++) acc[i][j][r] = 0.f;

    int kbeg = part * (SS/KSPLIT);
    for (int k0g = kbeg; k0g < kbeg + SS/KSPLIT; k0g += 32) {
        #pragma unroll
        for (int l = 0; l < 4; l++) {
            int f4 = tid + l*256;
            int r  = f4 >> 3;
            int kc = (f4 & 7) * 4;
            *(float4*)&Es[r][kc] = *(const float4*)&Eb[(size_t)(s0 + r)*SS + k0g + kc];
        }
        #pragma unroll
        for (int l = 0; l < 2; l++) {
            int f4 = tid + l*256;
            int r  = f4 >> 4;
            int cc = (f4 & 15) * 4;
            float4 xv = *(const float4*)&Xb[(size_t)(k0g + r)*FF + cc];
            Xs[cc+0][r] = xv.x; Xs[cc+1][r] = xv.y; Xs[cc+2][r] = xv.z; Xs[cc+3][r] = xv.w;
        }
        __syncthreads();
        #pragma unroll
        for (int k0 = 0; k0 < 32; k0 += 8) {
            unsigned bh[2][2];
            #pragma unroll
            for (int nt = 0; nt < 2; nt++) {
                int n = cb + nt*8 + lr;
                bh[nt][0] = cvt_tf32(Xs[n][k0 + lc]);
                bh[nt][1] = cvt_tf32(Xs[n][k0 + 4 + lc]);
            }
            #pragma unroll
            for (int mt = 0; mt < 4; mt++) {
                int r = rb + mt*16 + lr;
                unsigned ah[4];
                ah[0] = cvt_tf32(Es[r][k0 + lc]);
                ah[1] = cvt_tf32(Es[r + 8][k0 + lc]);
                ah[2] = cvt_tf32(Es[r][k0 + 4 + lc]);
                ah[3] = cvt_tf32(Es[r + 8][k0 + 4 + lc]);
                #pragma unroll
                for (int nt = 0; nt < 2; nt++)
                    mma_tf32(acc[mt][nt], ah[0], ah[1], ah[2], ah[3], bh[nt][0], bh[nt][1]);
            }
        }
        __syncthreads();
    }
    #pragma unroll
    for (int mt = 0; mt < 4; mt++) {
        #pragma unroll
        for (int nt = 0; nt < 2; nt++) {
            int r = s0 + rb + mt*16 + lr;
            int f = cb + nt*8 + (lc << 1);
            size_t base0 = ((size_t)part*NROW + (size_t)b*SS + r)*FF + f;
            size_t base1 = ((size_t)part*NROW + (size_t)b*SS + r + 8)*FF + f;
            *(float2*)&g_pe[base0] = make_float2(acc[mt][nt][0], acc[mt][nt][1]);
            *(float2*)&g_pe[base1] = make_float2(acc[mt][nt][2], acc[mt][nt][3]);
        }
    }
}

// ---------------- K5: pe256 = pe64 @ projW + b ; LN2 ; out += ----------------
__global__ void out_kernel(const float* __restrict__ pW, const float* __restrict__ pb,
                           const float* __restrict__ l2w, const float* __restrict__ l2b,
                           float* __restrict__ out) {
    __shared__ float pe[4][64];
    __shared__ float red[16];
    int r0 = blockIdx.x << 2;
    int tid = threadIdx.x;
    int rr = tid >> 6, f = tid & 63;
    float pv = 0.f;
    #pragma unroll
    for (int p = 0; p < KSPLIT; p++)
        pv += g_pe[((size_t)p*NROW + r0 + rr)*FF + f];
    pe[rr][f] = pv;
    __syncthreads();
    int d = tid;
    float a0 = pb[d], a1 = pb[d], a2 = pb[d], a3 = pb[d];
    #pragma unroll
    for (int ff = 0; ff < FF; ff++) {
        float w = pW[ff*DD + d];
        a0 = fmaf(pe[0][ff], w, a0);
        a1 = fmaf(pe[1][ff], w, a1);
        a2 = fmaf(pe[2][ff], w, a2);
        a3 = fmaf(pe[3][ff], w, a3);
    }
    float w2 = l2w[d], b2 = l2b[d];
    float accs[4] = {a0, a1, a2, a3};
    #pragma unroll
    for (int r = 0; r < 4; r++) {
        float mean = blk_sum256s(accs[r], red) * (1.0f / DD);
        float dv = accs[r] - mean;
        float var = blk_sum256s(dv*dv, red) * (1.0f / DD);
        size_t idx = (size_t)(r0 + r)*DD + d;
        out[idx] = out[idx] + dv * rsqrtf(var + 1e-5f) * w2 + b2;
    }
}

// ---------------- launch ----------------
extern "C" void kernel_launch(void* const* d_in, const int* in_sizes, int n_in,
                              void* d_out, int out_size) {
    const float* x   = (const float*)d_in[0];
    const float* rW  = (const float*)d_in[1];
    const float* rb  = (const float*)d_in[2];
    const float* pW  = (const float*)d_in[3];
    const float* pb  = (const float*)d_in[4];
    const float* l1w = (const float*)d_in[5];
    const float* l1b = (const float*)d_in[6];
    const float* l2w = (const float*)d_in[7];
    const float* l2b = (const float*)d_in[8];
    const float* al  = (const float*)d_in[9];
    const float* sg  = (const float*)d_in[10];
    const float* lns = (const float*)d_in[11];
    const float* sw  = (const float*)d_in[12];
    const float* qW  = (const float*)d_in[13];
    const float* qb  = (const float*)d_in[14];
    const float* kW  = (const float*)d_in[15];
    const float* kb  = (const float*)d_in[16];
    float* out = (float*)d_out;

    float* qg; float* kg; float* Gg; float* Eg;
    cudaGetSymbolAddress((void**)&Gg, g_G);
    cudaGetSymbolAddress((void**)&Eg, g_E);
    cudaGetSymbolAddress((void**)&qg, g_q);
    cudaGetSymbolAddress((void**)&kg, g_k);

    qk_proj_kernel<<<NROW/4, 256>>>(x, qW, qb, kW, kb);
    rpe_kernel<<<NROW, 256>>>(x, rW, rb, l1w, l1b, lns, sw, out);
    gemm_nt_tf32<<<dim3(SS/128, SS/128, 2*BB), 256>>>(x, qg, kg, Gg, Eg);
    row_kernel<<<NROW, 512>>>(al, sg);
    gemm_Ex_tf32<<<dim3(KSPLIT, SS/128, BB), 256>>>(x);
    out_kernel<<<NROW/4, 256>>>(pW, pb, l2w, l2b, out);
}

// round 11
// speedup vs baseline: 1.4188x; 1.1138x over previous
#include <cuda_runtime.h>
#include <math.h>

#define BB 4
#define SS 2048
#define FF 64
#define DD 256
#define NSC 15
#define NROW (BB*SS)   /* 8192 */
#define KSPLIT 8
#define NB 2048        /* histogram bins for quantile */

// ---------------- device scratch ----------------
__device__ float g_G[(size_t)BB*SS*SS];
__device__ float g_E[(size_t)BB*SS*SS];
__device__ float g_q[NROW*FF];
__device__ float g_k[NROW*FF];
__device__ float g_sq[NROW];
__device__ float g_pe[(size_t)KSPLIT*NROW*FF];

// ---------------- tf32 mma helpers ----------------
__device__ __forceinline__ void mma_tf32(float* c,
                                         unsigned a0, unsigned a1, unsigned a2, unsigned a3,
                                         unsigned b0, unsigned b1) {
    asm volatile(
        "mma.sync.aligned.m16n8k8.row.col.f32.tf32.tf32.f32 "
        "{%0,%1,%2,%3}, {%4,%5,%6,%7}, {%8,%9}, {%0,%1,%2,%3};\n"
        : "+f"(c[0]), "+f"(c[1]), "+f"(c[2]), "+f"(c[3])
        : "r"(a0), "r"(a1), "r"(a2), "r"(a3), "r"(b0), "r"(b1));
}

__device__ __forceinline__ unsigned cvt_tf32(float v) {
    unsigned r;
    asm("cvt.rna.tf32.f32 %0, %1;\n" : "=r"(r) : "f"(v));
    return r;
}

__device__ __forceinline__ float sqrt_approx(float x) {
    float r;
    asm("sqrt.approx.f32 %0, %1;\n" : "=f"(r) : "f"(x));
    return r;
}

__device__ __forceinline__ float rsqrt_approx(float x) {
    float r;
    asm("rsqrt.approx.f32 %0, %1;\n" : "=f"(r) : "f"(x));
    return r;
}

// ---------------- batched 8-value 256-thread sum (3 barriers total) ----------------
__device__ __forceinline__ void blk_sum8(const float* v, float* res, volatile float (*red)[8]) {
    int l = threadIdx.x & 31, w = threadIdx.x >> 5;
    #pragma unroll
    for (int r = 0; r < 8; r++) {
        float t = v[r];
        #pragma unroll
        for (int o = 16; o; o >>= 1) t += __shfl_xor_sync(0xffffffffu, t, o);
        if (l == 0) red[r][w] = t;
    }
    __syncthreads();
    if (threadIdx.x < 32) {
        int r = l >> 2, i = l & 3;
        float t = red[r][i] + red[r][i + 4];
        t += __shfl_xor_sync(0xffffffffu, t, 2);
        t += __shfl_xor_sync(0xffffffffu, t, 1);
        if (i == 0) red[r][0] = t;
    }
    __syncthreads();
    #pragma unroll
    for (int r = 0; r < 8; r++) res[r] = red[r][0];
    __syncthreads();
}

// ---------------- K1a: q/k projections + sq ----------------
__global__ void qk_proj_kernel(const float* __restrict__ x,
                               const float* __restrict__ qW, const float* __restrict__ qb,
                               const float* __restrict__ kW, const float* __restrict__ kb) {
    int row = blockIdx.x * 4 + (threadIdx.x >> 6);
    int f   = threadIdx.x & 63;
    const float* xr = x + (size_t)row * FF;
    float aq = qb[f], ak = kb[f], ss = 0.f;
    #pragma unroll
    for (int k = 0; k < FF; k++) {
        float xv = xr[k];
        aq = fmaf(xv, qW[k*FF + f], aq);
        ak = fmaf(xv, kW[k*FF + f], ak);
        ss = fmaf(xv, xv, ss);
    }
    g_q[(size_t)row*FF + f] = aq;
    g_k[(size_t)row*FF + f] = ak;
    if (f == 0) g_sq[row] = ss;
}

// ---------------- K2: 128x128 tile NT GEMM, pure 1x TF32 (K=64) ----------------
__global__ void __launch_bounds__(256, 2) gemm_nt_tf32(const float* __restrict__ x,
                                                       const float* __restrict__ q,
                                                       const float* __restrict__ k,
                                                       float* __restrict__ G,
                                                       float* __restrict__ E_) {
    __shared__ __align__(16) float As[128][36];
    __shared__ __align__(16) float Bs[128][36];
    int zz = blockIdx.z;
    int b  = zz & 3;
    bool isqk = zz >= 4;
    int s0 = blockIdx.y << 7;
    int t0 = blockIdx.x << 7;
    const float* Ab = (isqk ? q : x) + (size_t)b * SS * FF;
    const float* Bb = (isqk ? k : x) + (size_t)b * SS * FF;
    float*       Cb = (isqk ? E_ : G) + (size_t)b * SS * SS;
    int tid  = threadIdx.x;
    int lane = tid & 31;
    int wid  = tid >> 5;
    int rb   = (wid & 1) * 64;
    int cb   = (wid >> 1) * 32;
    int lr = lane >> 2, lc = lane & 3;

    float acc[4][4][4];
    #pragma unroll
    for (int i = 0; i < 4; i++)
        #pragma unroll
        for (int j = 0; j < 4; j++)
            #pragma unroll
            for (int r = 0; r < 4; r++) acc[i][j][r] = 0.f;

    #pragma unroll
    for (int st = 0; st < 2; st++) {
        int koff = st * 32;
        #pragma unroll
        for (int l = 0; l < 4; l++) {
            int f4 = tid + l*256;
            int r  = f4 >> 3;
            int kc = (f4 & 7) * 4;
            *(float4*)&As[r][kc] = *(const float4*)&Ab[(size_t)(s0 + r)*FF + koff + kc];
            *(float4*)&Bs[r][kc] = *(const float4*)&Bb[(size_t)(t0 + r)*FF + koff + kc];
        }
        __syncthreads();
        #pragma unroll
        for (int k0 = 0; k0 < 32; k0 += 8) {
            unsigned bh[4][2];
            #pragma unroll
            for (int nt = 0; nt < 4; nt++) {
                int n = cb + nt*8 + lr;
                bh[nt][0] = cvt_tf32(Bs[n][k0 + lc]);
                bh[nt][1] = cvt_tf32(Bs[n][k0 + 4 + lc]);
            }
            #pragma unroll
            for (int mt = 0; mt < 4; mt++) {
                int r = rb + mt*16 + lr;
                unsigned ah[4];
                ah[0] = cvt_tf32(As[r][k0 + lc]);
                ah[1] = cvt_tf32(As[r + 8][k0 + lc]);
                ah[2] = cvt_tf32(As[r][k0 + 4 + lc]);
                ah[3] = cvt_tf32(As[r + 8][k0 + 4 + lc]);
                #pragma unroll
                for (int nt = 0; nt < 4; nt++)
                    mma_tf32(acc[mt][nt], ah[0], ah[1], ah[2], ah[3], bh[nt][0], bh[nt][1]);
            }
        }
        __syncthreads();
    }
    #pragma unroll
    for (int mt = 0; mt < 4; mt++) {
        #pragma unroll
        for (int nt = 0; nt < 4; nt++) {
            int r    = s0 + rb + mt*16 + lr;
            int cidx = t0 + cb + nt*8 + (lc << 1);
            *(float2*)&Cb[(size_t)r*SS + cidx]       = make_float2(acc[mt][nt][0], acc[mt][nt][1]);
            *(float2*)&Cb[(size_t)(r + 8)*SS + cidx] = make_float2(acc[mt][nt][2], acc[mt][nt][3]);
        }
    }
}

// ---------------- K3: row kernel v7 — 2048-bin histogram quantile ----------------
__global__ void __launch_bounds__(512, 3) row_kernel(const float* __restrict__ alpha_p,
                                                     const float* __restrict__ sig_p) {
    __shared__ unsigned hist[NB];       // 8 KB
    __shared__ float redf[3][16];
    __shared__ float stat[3];           // d2min, d2max, Z
    __shared__ unsigned woff[16];
    __shared__ unsigned bq[6];          // {exclA,cntA,binA, exclB,cntB,binB}
    int row = blockIdx.x;
    int b = row >> 11, s = row & (SS - 1);
    int tid = threadIdx.x;
    int lane = tid & 31, wid = tid >> 5;
    const float* Grow = g_G + (size_t)b*SS*SS + (size_t)s*SS;
    float*       Erow = g_E + (size_t)b*SS*SS + (size_t)s*SS;
    const float* sqb = g_sq + b*SS;
    float sqs = sqb[s];
    float rns = rsqrt_approx(fmaxf(sqs, 1e-24f));

    // zero histogram (4 words/thread; covered by the reduction barrier below)
    #pragma unroll
    for (int j = 0; j < 4; j++) hist[tid + j*512] = 0;

    // pass 1: load, d2, min/max/Z partials
    float4 g4  = ((const float4*)Grow)[tid];
    float4 sc4 = ((const float4*)Erow)[tid];
    float4 sq4 = ((const float4*)sqb)[tid];
    float d2[4];
    d2[0] = fmaxf(sqs + sq4.x - 2.0f*g4.x, 0.0f);
    d2[1] = fmaxf(sqs + sq4.y - 2.0f*g4.y, 0.0f);
    d2[2] = fmaxf(sqs + sq4.z - 2.0f*g4.z, 0.0f);
    d2[3] = fmaxf(sqs + sq4.w - 2.0f*g4.w, 0.0f);
    float mn = fminf(fminf(d2[0], d2[1]), fminf(d2[2], d2[3]));
    float mx = fmaxf(fmaxf(d2[0], d2[1]), fmaxf(d2[2], d2[3]));
    float z = __expf(sc4.x*0.125f) + __expf(sc4.y*0.125f)
            + __expf(sc4.z*0.125f) + __expf(sc4.w*0.125f);
    #pragma unroll
    for (int o = 16; o; o >>= 1) {
        mn = fminf(mn, __shfl_xor_sync(0xffffffffu, mn, o));
        mx = fmaxf(mx, __shfl_xor_sync(0xffffffffu, mx, o));
        z += __shfl_xor_sync(0xffffffffu, z, o);
    }
    if (lane == 0) { redf[0][wid] = mn; redf[1][wid] = mx; redf[2][wid] = z; }
    __syncthreads();
    if (tid == 0) {
        float m0 = redf[0][0], m1 = redf[1][0], zz = redf[2][0];
        #pragma unroll
        for (int i = 1; i < 16; i++) {
            m0 = fminf(m0, redf[0][i]);
            m1 = fmaxf(m1, redf[1][i]);
            zz += redf[2][i];
        }
        stat[0] = m0; stat[1] = m1; stat[2] = zz;
    }
    __syncthreads();
    float d2min = stat[0], d2max = stat[1], Z = stat[2];
    float w   = (d2max - d2min) * (1.0f / NB);
    float iw  = (float)NB / fmaxf(d2max - d2min, 1e-30f);

    // histogram
    #pragma unroll
    for (int j = 0; j < 4; j++) {
        int bin = (int)((d2[j] - d2min) * iw);
        bin = bin < NB-1 ? bin : NB-1;
        bin = bin > 0 ? bin : 0;
        atomicAdd(&hist[bin], 1u);
    }
    __syncthreads();

    // prefix scan over NB bins (4 per thread, contiguous)
    uint4 v0 = ((const uint4*)hist)[tid];
    unsigned vals[4] = {v0.x, v0.y, v0.z, v0.w};
    unsigned st = vals[0] + vals[1] + vals[2] + vals[3];
    unsigned e = st;
    #pragma unroll
    for (int o = 1; o < 32; o <<= 1) {
        unsigned t = __shfl_up_sync(0xffffffffu, e, o);
        if (lane >= o) e += t;
    }
    if (lane == 31) woff[wid] = e;     // warp total
    unsigned lexcl = e - st;
    __syncthreads();
    if (tid < 32) {
        unsigned t = (lane < 16) ? woff[lane] : 0u;
        unsigned ei = t;
        #pragma unroll
        for (int o = 1; o < 16; o <<= 1) {
            unsigned u = __shfl_up_sync(0xffffffffu, ei, o);
            if (lane >= o) ei += u;
        }
        if (lane < 16) woff[lane] = ei - t;
    }
    __syncthreads();
    {
        unsigned run = woff[wid] + lexcl;
        #pragma unroll
        for (int j = 0; j < 4; j++) {
            unsigned excl = run; run += vals[j];
            if (excl <= 102u && 102u < run)  { bq[0] = excl; bq[1] = vals[j]; bq[2] = (unsigned)(tid*4 + j); }
            if (excl <= 1944u && 1944u < run){ bq[3] = excl; bq[4] = vals[j]; bq[5] = (unsigned)(tid*4 + j); }
        }
    }
    __syncthreads();

    // quantiles with sub-bin interpolation (continuous ranks 102.35 / 1944.65)
    float frA = (102.35f  - (float)bq[0] + 0.5f) / (float)bq[1];
    float frB = (1944.65f - (float)bq[3] + 0.5f) / (float)bq[4];
    frA = fminf(fmaxf(frA, 0.0f), 1.0f);
    frB = fminf(fmaxf(frB, 0.0f), 1.0f);
    float vmin = sqrt_approx(fmaxf(d2min + ((float)bq[2] + frA) * w, 0.0f));
    float vmax = sqrt_approx(fmaxf(d2min + ((float)bq[5] + frB) * w, 0.0f));

    float a  = 1.0f / (1.0f + __expf(-alpha_p[0]));
    float sg = log1pf(__expf(sig_p[0])) + 0.001f;
    float inv2s2 = 1.0f / (2.0f * sg * sg);
    float invZ = 1.0f / Z;
    float iden = 1.0f / (vmax - vmin + 1e-6f);
    float gg[4] = {g4.x, g4.y, g4.z, g4.w};
    float ssc[4] = {sc4.x, sc4.y, sc4.z, sc4.w};
    float sq_[4] = {sq4.x, sq4.y, sq4.z, sq4.w};
    float oo[4];
    #pragma unroll
    for (int j = 0; j < 4; j++) {
        float dist = sqrt_approx(d2[j]);
        float eu = fminf(fmaxf((dist - vmin)*iden, 0.0f), 1.0f);
        float rr = rsqrt_approx(fmaxf(sq_[j], 1e-24f));
        float cs = (gg[j]*rns*rr + 1.0f) * 0.5f;
        float hyb = a*cs + (1.0f - a)*(1.0f - eu);
        oo[j] = __expf(ssc[j]*0.125f - hyb*inv2s2) * invZ;
    }
    ((float4*)Erow)[tid] = make_float4(oo[0], oo[1], oo[2], oo[3]);
}

// ---------------- K4: pe64 = E @ x, pure 1x TF32, K-split ----------------
__global__ void __launch_bounds__(256, 2) gemm_Ex_tf32(const float* __restrict__ x) {
    __shared__ __align__(16) float Es[128][36];
    __shared__ __align__(16) float Xs[64][37];
    int part = blockIdx.x;
    int b  = blockIdx.z;
    int s0 = blockIdx.y << 7;
    const float* Eb = g_E + (size_t)b*SS*SS;
    const float* Xb = x   + (size_t)b*SS*FF;
    int tid  = threadIdx.x;
    int lane = tid & 31;
    int wid  = tid >> 5;
    int rb   = (wid & 1) * 64;
    int cb   = (wid >> 1) * 16;
    int lr = lane >> 2, lc = lane & 3;

    float acc[4][2][4];
    #pragma unroll
    for (int i = 0; i < 4; i++)
        #pragma unroll
        for (int j = 0; j < 2; j++)
            #pragma unroll
            for (int r = 0; r < 4; r++) acc[i][j][r] = 0.f;

    int kbeg = part * (SS/KSPLIT);
    for (int k0g = kbeg; k0g < kbeg + SS/KSPLIT; k0g += 32) {
        #pragma unroll
        for (int l = 0; l < 4; l++) {
            int f4 = tid + l*256;
            int r  = f4 >> 3;
            int kc = (f4 & 7) * 4;
            *(float4*)&Es[r][kc] = *(const float4*)&Eb[(size_t)(s0 + r)*SS + k0g + kc];
        }
        #pragma unroll
        for (int l = 0; l < 2; l++) {
            int f4 = tid + l*256;
            int r  = f4 >> 4;
            int cc = (f4 & 15) * 4;
            float4 xv = *(const float4*)&Xb[(size_t)(k0g + r)*FF + cc];
            Xs[cc+0][r] = xv.x; Xs[cc+1][r] = xv.y; Xs[cc+2][r] = xv.z; Xs[cc+3][r] = xv.w;
        }
        __syncthreads();
        #pragma unroll
        for (int k0 = 0; k0 < 32; k0 += 8) {
            unsigned bh[2][2];
            #pragma unroll
            for (int nt = 0; nt < 2; nt++) {
                int n = cb + nt*8 + lr;
                bh[nt][0] = cvt_tf32(Xs[n][k0 + lc]);
                bh[nt][1] = cvt_tf32(Xs[n][k0 + 4 + lc]);
            }
            #pragma unroll
            for (int mt = 0; mt < 4; mt++) {
                int r = rb + mt*16 + lr;
                unsigned ah[4];
                ah[0] = cvt_tf32(Es[r][k0 + lc]);
                ah[1] = cvt_tf32(Es[r + 8][k0 + lc]);
                ah[2] = cvt_tf32(Es[r][k0 + 4 + lc]);
                ah[3] = cvt_tf32(Es[r + 8][k0 + 4 + lc]);
                #pragma unroll
                for (int nt = 0; nt < 2; nt++)
                    mma_tf32(acc[mt][nt], ah[0], ah[1], ah[2], ah[3], bh[nt][0], bh[nt][1]);
            }
        }
        __syncthreads();
    }
    #pragma unroll
    for (int mt = 0; mt < 4; mt++) {
        #pragma unroll
        for (int nt = 0; nt < 2; nt++) {
            int r = s0 + rb + mt*16 + lr;
            int f = cb + nt*8 + (lc << 1);
            size_t base0 = ((size_t)part*NROW + (size_t)b*SS + r)*FF + f;
            size_t base1 = ((size_t)part*NROW + (size_t)b*SS + r + 8)*FF + f;
            *(float2*)&g_pe[base0] = make_float2(acc[mt][nt][0], acc[mt][nt][1]);
            *(float2*)&g_pe[base1] = make_float2(acc[mt][nt][2], acc[mt][nt][3]);
        }
    }
}

// ---------------- K5: merged rpe + projection + dual LN -> out ----------------
__global__ void out_kernel(const float* __restrict__ x,
                           const float* __restrict__ rW, const float* __restrict__ rb,
                           const float* __restrict__ l1w, const float* __restrict__ l1b,
                           const float* __restrict__ lns_p, const float* __restrict__ sw,
                           const float* __restrict__ pW, const float* __restrict__ pb,
                           const float* __restrict__ l2w, const float* __restrict__ l2b,
                           float* __restrict__ out) {
    __shared__ float pe[4][64];
    __shared__ float red[8][8];
    __shared__ float sh3[4][3];
    int r0 = blockIdx.x << 2;
    int tid = threadIdx.x;
    int lane = tid & 31, wid = tid >> 5;
    int rr = tid >> 6, f = tid & 63;

    float lns = fminf(fmaxf(lns_p[0], 1.0f), (float)NSC);
    int n = (int)rintf(lns);

    // pe partial sums for the 4 rows
    float pv = 0.f;
    #pragma unroll
    for (int p = 0; p < KSPLIT; p++)
        pv += g_pe[((size_t)p*NROW + r0 + rr)*FF + f];
    pe[rr][f] = pv;

    // rpe scale sums: warps 0..3 handle rows r0..r0+3
    if (wid < 4) {
        int row = r0 + wid;
        int b = row >> 11, s = row & (SS - 1);
        int sc = lane + 1;
        float s0 = 0.f, s1 = 0.f, s2 = 0.f;
        if (sc <= n && s >= sc) {
            const float* xb = x + (size_t)b * SS * FF;
            float ds = xb[(size_t)s*FF + 0];
            float es = xb[(size_t)s*FF + FF - 1];
            float dd = xb[(size_t)(s - sc)*FF + 0] - ds;
            float de = xb[(size_t)(s - sc)*FF + FF - 1] - es;
            float wd = sw[sc - 1] * expf(-fabsf(dd) * exp2f(-(float)sc));
            s0 = dd; s1 = de; s2 = wd;
        }
        #pragma unroll
        for (int o = 16; o; o >>= 1) {
            s0 += __shfl_xor_sync(0xffffffffu, s0, o);
            s1 += __shfl_xor_sync(0xffffffffu, s1, o);
            s2 += __shfl_xor_sync(0xffffffffu, s2, o);
        }
        if (lane == 0) { sh3[wid][0] = s0; sh3[wid][1] = s1; sh3[wid][2] = s2; }
    }
    __syncthreads();

    // 8 values per thread: rows 0..3 rpe, rows 0..3 pe
    int d = tid;
    float w1 = rW[d], w2r = rW[DD + d], w3 = rW[2*DD + d];
    float rbv = (float)n * rb[d];
    float vals[8];
    #pragma unroll
    for (int r = 0; r < 4; r++)
        vals[r] = sh3[r][0]*w1 + sh3[r][1]*w2r + sh3[r][2]*w3 + rbv;
    {
        float pbv = pb[d];
        float a0 = pbv, a1 = pbv, a2 = pbv, a3 = pbv;
        #pragma unroll
        for (int ff = 0; ff < FF; ff++) {
            float wv = pW[ff*DD + d];
            a0 = fmaf(pe[0][ff], wv, a0);
            a1 = fmaf(pe[1][ff], wv, a1);
            a2 = fmaf(pe[2][ff], wv, a2);
            a3 = fmaf(pe[3][ff], wv, a3);
        }
        vals[4] = a0; vals[5] = a1; vals[6] = a2; vals[7] = a3;
    }

    float mean[8];
    blk_sum8(vals, mean, red);
    float dv[8], v2[8];
    #pragma unroll
    for (int r = 0; r < 8; r++) { dv[r] = vals[r] - mean[r]*(1.0f/DD); v2[r] = dv[r]*dv[r]; }
    float var[8];
    blk_sum8(v2, var, red);

    float lw1 = l1w[d], lb1 = l1b[d], lw2 = l2w[d], lb2 = l2b[d];
    #pragma unroll
    for (int r = 0; r < 4; r++) {
        float o1 = dv[r]   * rsqrtf(var[r]  *(1.0f/DD) + 1e-5f) * lw1 + lb1;
        float o2 = dv[r+4] * rsqrtf(var[r+4]*(1.0f/DD) + 1e-5f) * lw2 + lb2;
        out[(size_t)(r0 + r)*DD + d] = o1 + o2;
    }
}

// ---------------- launch ----------------
extern "C" void kernel_launch(void* const* d_in, const int* in_sizes, int n_in,
                              void* d_out, int out_size) {
    const float* x   = (const float*)d_in[0];
    const float* rW  = (const float*)d_in[1];
    const float* rb  = (const float*)d_in[2];
    const float* pW  = (const float*)d_in[3];
    const float* pb  = (const float*)d_in[4];
    const float* l1w = (const float*)d_in[5];
    const float* l1b = (const float*)d_in[6];
    const float* l2w = (const float*)d_in[7];
    const float* l2b = (const float*)d_in[8];
    const float* al  = (const float*)d_in[9];
    const float* sg  = (const float*)d_in[10];
    const float* lns = (const float*)d_in[11];
    const float* sw  = (const float*)d_in[12];
    const float* qW  = (const float*)d_in[13];
    const float* qb  = (const float*)d_in[14];
    const float* kW  = (const float*)d_in[15];
    const float* kb  = (const float*)d_in[16];
    float* out = (float*)d_out;

    float* qg; float* kg; float* Gg; float* Eg;
    cudaGetSymbolAddress((void**)&Gg, g_G);
    cudaGetSymbolAddress((void**)&Eg, g_E);
    cudaGetSymbolAddress((void**)&qg, g_q);
    cudaGetSymbolAddress((void**)&kg, g_k);

    qk_proj_kernel<<<NROW/4, 256>>>(x, qW, qb, kW, kb);
    gemm_nt_tf32<<<dim3(SS/128, SS/128, 2*BB), 256>>>(x, qg, kg, Gg, Eg);
    row_kernel<<<NROW, 512>>>(al, sg);
    gemm_Ex_tf32<<<dim3(KSPLIT, SS/128, BB), 256>>>(x);
    out_kernel<<<NROW/4, 256>>>(x, rW, rb, l1w, l1b, lns, sw, pW, pb, l2w, l2b, out);
}

// round 12
// speedup vs baseline: 1.4192x; 1.0003x over previous
#include <cuda_runtime.h>
#include <cuda_fp16.h>
#include <math.h>

#define BB 4
#define SS 2048
#define FF 64
#define DD 256
#define NSC 15
#define NROW (BB*SS)   /* 8192 */
#define KSPLIT 16
#define NB 2048        /* histogram bins for quantile */

// ---------------- device scratch ----------------
__device__ float  g_G[(size_t)BB*SS*SS];     // gram (fp32)
__device__ float  g_E[(size_t)BB*SS*SS];     // qk scores (fp32)
__device__ __half g_Eh[(size_t)BB*SS*SS];    // E weights (fp16)
__device__ float  g_q[NROW*FF];
__device__ float  g_k[NROW*FF];
__device__ float  g_sq[NROW];
__device__ float  g_pe[(size_t)KSPLIT*NROW*FF];

// ---------------- tf32 mma helpers ----------------
__device__ __forceinline__ void mma_tf32(float* c,
                                         unsigned a0, unsigned a1, unsigned a2, unsigned a3,
                                         unsigned b0, unsigned b1) {
    asm volatile(
        "mma.sync.aligned.m16n8k8.row.col.f32.tf32.tf32.f32 "
        "{%0,%1,%2,%3}, {%4,%5,%6,%7}, {%8,%9}, {%0,%1,%2,%3};\n"
        : "+f"(c[0]), "+f"(c[1]), "+f"(c[2]), "+f"(c[3])
        : "r"(a0), "r"(a1), "r"(a2), "r"(a3), "r"(b0), "r"(b1));
}

__device__ __forceinline__ unsigned cvt_tf32(float v) {
    unsigned r;
    asm("cvt.rna.tf32.f32 %0, %1;\n" : "=r"(r) : "f"(v));
    return r;
}

__device__ __forceinline__ float sqrt_approx(float x) {
    float r;
    asm("sqrt.approx.f32 %0, %1;\n" : "=f"(r) : "f"(x));
    return r;
}

__device__ __forceinline__ float rsqrt_approx(float x) {
    float r;
    asm("rsqrt.approx.f32 %0, %1;\n" : "=f"(r) : "f"(x));
    return r;
}

// ---------------- batched 8-value 256-thread sum ----------------
__device__ __forceinline__ void blk_sum8(const float* v, float* res, volatile float (*red)[8]) {
    int l = threadIdx.x & 31, w = threadIdx.x >> 5;
    #pragma unroll
    for (int r = 0; r < 8; r++) {
        float t = v[r];
        #pragma unroll
        for (int o = 16; o; o >>= 1) t += __shfl_xor_sync(0xffffffffu, t, o);
        if (l == 0) red[r][w] = t;
    }
    __syncthreads();
    if (threadIdx.x < 32) {
        int r = l >> 2, i = l & 3;
        float t = red[r][i] + red[r][i + 4];
        t += __shfl_xor_sync(0xffffffffu, t, 2);
        t += __shfl_xor_sync(0xffffffffu, t, 1);
        if (i == 0) red[r][0] = t;
    }
    __syncthreads();
    #pragma unroll
    for (int r = 0; r < 8; r++) res[r] = red[r][0];
    __syncthreads();
}

// ---------------- K1a: q/k projections + sq ----------------
__global__ void qk_proj_kernel(const float* __restrict__ x,
                               const float* __restrict__ qW, const float* __restrict__ qb,
                               const float* __restrict__ kW, const float* __restrict__ kb) {
    int row = blockIdx.x * 4 + (threadIdx.x >> 6);
    int f   = threadIdx.x & 63;
    const float* xr = x + (size_t)row * FF;
    float aq = qb[f], ak = kb[f], ss = 0.f;
    #pragma unroll
    for (int k = 0; k < FF; k++) {
        float xv = xr[k];
        aq = fmaf(xv, qW[k*FF + f], aq);
        ak = fmaf(xv, kW[k*FF + f], ak);
        ss = fmaf(xv, xv, ss);
    }
    g_q[(size_t)row*FF + f] = aq;
    g_k[(size_t)row*FF + f] = ak;
    if (f == 0) g_sq[row] = ss;
}

// ---------------- K2: 128x128 tile NT GEMM, pure 1x TF32 (K=64) ----------------
__global__ void __launch_bounds__(256, 2) gemm_nt_tf32(const float* __restrict__ x,
                                                       const float* __restrict__ q,
                                                       const float* __restrict__ k,
                                                       float* __restrict__ G,
                                                       float* __restrict__ E_) {
    __shared__ __align__(16) float As[128][36];
    __shared__ __align__(16) float Bs[128][36];
    int zz = blockIdx.z;
    int b  = zz & 3;
    bool isqk = zz >= 4;
    int s0 = blockIdx.y << 7;
    int t0 = blockIdx.x << 7;
    const float* Ab = (isqk ? q : x) + (size_t)b * SS * FF;
    const float* Bb = (isqk ? k : x) + (size_t)b * SS * FF;
    float*       Cb = (isqk ? E_ : G) + (size_t)b * SS * SS;
    int tid  = threadIdx.x;
    int lane = tid & 31;
    int wid  = tid >> 5;
    int rb   = (wid & 1) * 64;
    int cb   = (wid >> 1) * 32;
    int lr = lane >> 2, lc = lane & 3;

    float acc[4][4][4];
    #pragma unroll
    for (int i = 0; i < 4; i++)
        #pragma unroll
        for (int j = 0; j < 4; j++)
            #pragma unroll
            for (int r = 0; r < 4; r++) acc[i][j][r] = 0.f;

    #pragma unroll
    for (int st = 0; st < 2; st++) {
        int koff = st * 32;
        #pragma unroll
        for (int l = 0; l < 4; l++) {
            int f4 = tid + l*256;
            int r  = f4 >> 3;
            int kc = (f4 & 7) * 4;
            *(float4*)&As[r][kc] = *(const float4*)&Ab[(size_t)(s0 + r)*FF + koff + kc];
            *(float4*)&Bs[r][kc] = *(const float4*)&Bb[(size_t)(t0 + r)*FF + koff + kc];
        }
        __syncthreads();
        #pragma unroll
        for (int k0 = 0; k0 < 32; k0 += 8) {
            unsigned bh[4][2];
            #pragma unroll
            for (int nt = 0; nt < 4; nt++) {
                int n = cb + nt*8 + lr;
                bh[nt][0] = cvt_tf32(Bs[n][k0 + lc]);
                bh[nt][1] = cvt_tf32(Bs[n][k0 + 4 + lc]);
            }
            #pragma unroll
            for (int mt = 0; mt < 4; mt++) {
                int r = rb + mt*16 + lr;
                unsigned ah[4];
                ah[0] = cvt_tf32(As[r][k0 + lc]);
                ah[1] = cvt_tf32(As[r + 8][k0 + lc]);
                ah[2] = cvt_tf32(As[r][k0 + 4 + lc]);
                ah[3] = cvt_tf32(As[r + 8][k0 + 4 + lc]);
                #pragma unroll
                for (int nt = 0; nt < 4; nt++)
                    mma_tf32(acc[mt][nt], ah[0], ah[1], ah[2], ah[3], bh[nt][0], bh[nt][1]);
            }
        }
        __syncthreads();
    }
    #pragma unroll
    for (int mt = 0; mt < 4; mt++) {
        #pragma unroll
        for (int nt = 0; nt < 4; nt++) {
            int r    = s0 + rb + mt*16 + lr;
            int cidx = t0 + cb + nt*8 + (lc << 1);
            *(float2*)&Cb[(size_t)r*SS + cidx]       = make_float2(acc[mt][nt][0], acc[mt][nt][1]);
            *(float2*)&Cb[(size_t)(r + 8)*SS + cidx] = make_float2(acc[mt][nt][2], acc[mt][nt][3]);
        }
    }
}

// ---------------- K3: row kernel v8 — histogram quantile, fp16 E output ----------------
__global__ void __launch_bounds__(512, 3) row_kernel(const float* __restrict__ alpha_p,
                                                     const float* __restrict__ sig_p) {
    __shared__ unsigned hist[NB];       // 8 KB
    __shared__ float redf[3][16];
    __shared__ float stat[3];           // d2min, d2max, Z
    __shared__ unsigned woff[16];
    __shared__ unsigned bq[6];
    int row = blockIdx.x;
    int b = row >> 11, s = row & (SS - 1);
    int tid = threadIdx.x;
    int lane = tid & 31, wid = tid >> 5;
    const float* Grow = g_G + (size_t)b*SS*SS + (size_t)s*SS;
    const float* Srow = g_E + (size_t)b*SS*SS + (size_t)s*SS;
    __half*      Ehrow = g_Eh + (size_t)b*SS*SS + (size_t)s*SS;
    const float* sqb = g_sq + b*SS;
    float sqs = sqb[s];
    float rns = rsqrt_approx(fmaxf(sqs, 1e-24f));

    #pragma unroll
    for (int j = 0; j < 4; j++) hist[tid + j*512] = 0;

    float4 g4  = ((const float4*)Grow)[tid];
    float4 sc4 = ((const float4*)Srow)[tid];
    float4 sq4 = ((const float4*)sqb)[tid];
    float d2[4];
    d2[0] = fmaxf(sqs + sq4.x - 2.0f*g4.x, 0.0f);
    d2[1] = fmaxf(sqs + sq4.y - 2.0f*g4.y, 0.0f);
    d2[2] = fmaxf(sqs + sq4.z - 2.0f*g4.z, 0.0f);
    d2[3] = fmaxf(sqs + sq4.w - 2.0f*g4.w, 0.0f);
    float mn = fminf(fminf(d2[0], d2[1]), fminf(d2[2], d2[3]));
    float mx = fmaxf(fmaxf(d2[0], d2[1]), fmaxf(d2[2], d2[3]));
    float z = __expf(sc4.x*0.125f) + __expf(sc4.y*0.125f)
            + __expf(sc4.z*0.125f) + __expf(sc4.w*0.125f);
    #pragma unroll
    for (int o = 16; o; o >>= 1) {
        mn = fminf(mn, __shfl_xor_sync(0xffffffffu, mn, o));
        mx = fmaxf(mx, __shfl_xor_sync(0xffffffffu, mx, o));
        z += __shfl_xor_sync(0xffffffffu, z, o);
    }
    if (lane == 0) { redf[0][wid] = mn; redf[1][wid] = mx; redf[2][wid] = z; }
    __syncthreads();
    if (tid == 0) {
        float m0 = redf[0][0], m1 = redf[1][0], zz = redf[2][0];
        #pragma unroll
        for (int i = 1; i < 16; i++) {
            m0 = fminf(m0, redf[0][i]);
            m1 = fmaxf(m1, redf[1][i]);
            zz += redf[2][i];
        }
        stat[0] = m0; stat[1] = m1; stat[2] = zz;
    }
    __syncthreads();
    float d2min = stat[0], d2max = stat[1], Z = stat[2];
    float w   = (d2max - d2min) * (1.0f / NB);
    float iw  = (float)NB / fmaxf(d2max - d2min, 1e-30f);

    #pragma unroll
    for (int j = 0; j < 4; j++) {
        int bin = (int)((d2[j] - d2min) * iw);
        bin = bin < NB-1 ? bin : NB-1;
        bin = bin > 0 ? bin : 0;
        atomicAdd(&hist[bin], 1u);
    }
    __syncthreads();

    uint4 v0 = ((const uint4*)hist)[tid];
    unsigned vals[4] = {v0.x, v0.y, v0.z, v0.w};
    unsigned st = vals[0] + vals[1] + vals[2] + vals[3];
    unsigned e = st;
    #pragma unroll
    for (int o = 1; o < 32; o <<= 1) {
        unsigned t = __shfl_up_sync(0xffffffffu, e, o);
        if (lane >= o) e += t;
    }
    if (lane == 31) woff[wid] = e;
    unsigned lexcl = e - st;
    __syncthreads();
    if (tid < 32) {
        unsigned t = (lane < 16) ? woff[lane] : 0u;
        unsigned ei = t;
        #pragma unroll
        for (int o = 1; o < 16; o <<= 1) {
            unsigned u = __shfl_up_sync(0xffffffffu, ei, o);
            if (lane >= o) ei += u;
        }
        if (lane < 16) woff[lane] = ei - t;
    }
    __syncthreads();
    {
        unsigned run = woff[wid] + lexcl;
        #pragma unroll
        for (int j = 0; j < 4; j++) {
            unsigned excl = run; run += vals[j];
            if (excl <= 102u && 102u < run)  { bq[0] = excl; bq[1] = vals[j]; bq[2] = (unsigned)(tid*4 + j); }
            if (excl <= 1944u && 1944u < run){ bq[3] = excl; bq[4] = vals[j]; bq[5] = (unsigned)(tid*4 + j); }
        }
    }
    __syncthreads();

    float frA = (102.35f  - (float)bq[0] + 0.5f) / (float)bq[1];
    float frB = (1944.65f - (float)bq[3] + 0.5f) / (float)bq[4];
    frA = fminf(fmaxf(frA, 0.0f), 1.0f);
    frB = fminf(fmaxf(frB, 0.0f), 1.0f);
    float vmin = sqrt_approx(fmaxf(d2min + ((float)bq[2] + frA) * w, 0.0f));
    float vmax = sqrt_approx(fmaxf(d2min + ((float)bq[5] + frB) * w, 0.0f));

    float a  = 1.0f / (1.0f + __expf(-alpha_p[0]));
    float sg = log1pf(__expf(sig_p[0])) + 0.001f;
    float inv2s2 = 1.0f / (2.0f * sg * sg);
    float invZ = 1.0f / Z;
    float iden = 1.0f / (vmax - vmin + 1e-6f);
    float gg[4] = {g4.x, g4.y, g4.z, g4.w};
    float ssc[4] = {sc4.x, sc4.y, sc4.z, sc4.w};
    float sq_[4] = {sq4.x, sq4.y, sq4.z, sq4.w};
    float oo[4];
    #pragma unroll
    for (int j = 0; j < 4; j++) {
        float dist = sqrt_approx(d2[j]);
        float eu = fminf(fmaxf((dist - vmin)*iden, 0.0f), 1.0f);
        float rr = rsqrt_approx(fmaxf(sq_[j], 1e-24f));
        float cs = (gg[j]*rns*rr + 1.0f) * 0.5f;
        float hyb = a*cs + (1.0f - a)*(1.0f - eu);
        oo[j] = __expf(ssc[j]*0.125f - hyb*inv2s2) * invZ;
    }
    __half2 h0 = __floats2half2_rn(oo[0], oo[1]);
    __half2 h1 = __floats2half2_rn(oo[2], oo[3]);
    uint2 pk;
    pk.x = *(unsigned*)&h0;
    pk.y = *(unsigned*)&h1;
    ((uint2*)Ehrow)[tid] = pk;
}

// ---------------- K4: pe64 = E(fp16) @ x, tf32 mma, K-split ----------------
__global__ void __launch_bounds__(256, 2) gemm_Ex_tf32(const float* __restrict__ x) {
    __shared__ __align__(16) float Es[128][36];
    __shared__ __align__(16) float Xs[64][37];
    int part = blockIdx.x;
    int b  = blockIdx.z;
    int s0 = blockIdx.y << 7;
    const __half* Eb = g_Eh + (size_t)b*SS*SS;
    const float*  Xb = x    + (size_t)b*SS*FF;
    int tid  = threadIdx.x;
    int lane = tid & 31;
    int wid  = tid >> 5;
    int rb   = (wid & 1) * 64;
    int cb   = (wid >> 1) * 16;
    int lr = lane >> 2, lc = lane & 3;

    float acc[4][2][4];
    #pragma unroll
    for (int i = 0; i < 4; i++)
        #pragma unroll
        for (int j = 0; j < 2; j++)
            #pragma unroll
            for (int r = 0; r < 4; r++) acc[i][j][r] = 0.f;

    int kbeg = part * (SS/KSPLIT);
    for (int k0g = kbeg; k0g < kbeg + SS/KSPLIT; k0g += 32) {
        // stage E tile: 128 rows x 32 halfs; 8 halfs per (thread,l)
        #pragma unroll
        for (int l = 0; l < 2; l++) {
            int f4 = tid + l*256;
            int r  = f4 >> 2;
            int kc = (f4 & 3) * 8;
            uint4 hv = *(const uint4*)&Eb[(size_t)(s0 + r)*SS + k0g + kc];
            __half2* hp = (__half2*)&hv;
            float2 f0 = __half22float2(hp[0]);
            float2 f1 = __half22float2(hp[1]);
            float2 f2 = __half22float2(hp[2]);
            float2 f3 = __half22float2(hp[3]);
            *(float4*)&Es[r][kc]     = make_float4(f0.x, f0.y, f1.x, f1.y);
            *(float4*)&Es[r][kc + 4] = make_float4(f2.x, f2.y, f3.x, f3.y);
        }
        #pragma unroll
        for (int l = 0; l < 2; l++) {
            int f4 = tid + l*256;
            int r  = f4 >> 4;
            int cc = (f4 & 15) * 4;
            float4 xv = *(const float4*)&Xb[(size_t)(k0g + r)*FF + cc];
            Xs[cc+0][r] = xv.x; Xs[cc+1][r] = xv.y; Xs[cc+2][r] = xv.z; Xs[cc+3][r] = xv.w;
        }
        __syncthreads();
        #pragma unroll
        for (int k0 = 0; k0 < 32; k0 += 8) {
            unsigned bh[2][2];
            #pragma unroll
            for (int nt = 0; nt < 2; nt++) {
                int n = cb + nt*8 + lr;
                bh[nt][0] = cvt_tf32(Xs[n][k0 + lc]);
                bh[nt][1] = cvt_tf32(Xs[n][k0 + 4 + lc]);
            }
            #pragma unroll
            for (int mt = 0; mt < 4; mt++) {
                int r = rb + mt*16 + lr;
                unsigned ah[4];
                ah[0] = cvt_tf32(Es[r][k0 + lc]);
                ah[1] = cvt_tf32(Es[r + 8][k0 + lc]);
                ah[2] = cvt_tf32(Es[r][k0 + 4 + lc]);
                ah[3] = cvt_tf32(Es[r + 8][k0 + 4 + lc]);
                #pragma unroll
                for (int nt = 0; nt < 2; nt++)
                    mma_tf32(acc[mt][nt], ah[0], ah[1], ah[2], ah[3], bh[nt][0], bh[nt][1]);
            }
        }
        __syncthreads();
    }
    #pragma unroll
    for (int mt = 0; mt < 4; mt++) {
        #pragma unroll
        for (int nt = 0; nt < 2; nt++) {
            int r = s0 + rb + mt*16 + lr;
            int f = cb + nt*8 + (lc << 1);
            size_t base0 = ((size_t)part*NROW + (size_t)b*SS + r)*FF + f;
            size_t base1 = ((size_t)part*NROW + (size_t)b*SS + r + 8)*FF + f;
            *(float2*)&g_pe[base0] = make_float2(acc[mt][nt][0], acc[mt][nt][1]);
            *(float2*)&g_pe[base1] = make_float2(acc[mt][nt][2], acc[mt][nt][3]);
        }
    }
}

// ---------------- K5: merged rpe + projection + dual LN -> out ----------------
__global__ void out_kernel(const float* __restrict__ x,
                           const float* __restrict__ rW, const float* __restrict__ rb,
                           const float* __restrict__ l1w, const float* __restrict__ l1b,
                           const float* __restrict__ lns_p, const float* __restrict__ sw,
                           const float* __restrict__ pW, const float* __restrict__ pb,
                           const float* __restrict__ l2w, const float* __restrict__ l2b,
                           float* __restrict__ out) {
    __shared__ float pe[4][64];
    __shared__ float red[8][8];
    __shared__ float sh3[4][3];
    int r0 = blockIdx.x << 2;
    int tid = threadIdx.x;
    int lane = tid & 31, wid = tid >> 5;
    int rr = tid >> 6, f = tid & 63;

    float lns = fminf(fmaxf(lns_p[0], 1.0f), (float)NSC);
    int n = (int)rintf(lns);

    float pv = 0.f;
    #pragma unroll
    for (int p = 0; p < KSPLIT; p++)
        pv += g_pe[((size_t)p*NROW + r0 + rr)*FF + f];
    pe[rr][f] = pv;

    if (wid < 4) {
        int row = r0 + wid;
        int b = row >> 11, s = row & (SS - 1);
        int sc = lane + 1;
        float s0 = 0.f, s1 = 0.f, s2 = 0.f;
        if (sc <= n && s >= sc) {
            const float* xb = x + (size_t)b * SS * FF;
            float ds = xb[(size_t)s*FF + 0];
            float es = xb[(size_t)s*FF + FF - 1];
            float dd = xb[(size_t)(s - sc)*FF + 0] - ds;
            float de = xb[(size_t)(s - sc)*FF + FF - 1] - es;
            float wd = sw[sc - 1] * expf(-fabsf(dd) * exp2f(-(float)sc));
            s0 = dd; s1 = de; s2 = wd;
        }
        #pragma unroll
        for (int o = 16; o; o >>= 1) {
            s0 += __shfl_xor_sync(0xffffffffu, s0, o);
            s1 += __shfl_xor_sync(0xffffffffu, s1, o);
            s2 += __shfl_xor_sync(0xffffffffu, s2, o);
        }
        if (lane == 0) { sh3[wid][0] = s0; sh3[wid][1] = s1; sh3[wid][2] = s2; }
    }
    __syncthreads();

    int d = tid;
    float w1 = rW[d], w2r = rW[DD + d], w3 = rW[2*DD + d];
    float rbv = (float)n * rb[d];
    float vals[8];
    #pragma unroll
    for (int r = 0; r < 4; r++)
        vals[r] = sh3[r][0]*w1 + sh3[r][1]*w2r + sh3[r][2]*w3 + rbv;
    {
        float pbv = pb[d];
        float a0 = pbv, a1 = pbv, a2 = pbv, a3 = pbv;
        #pragma unroll
        for (int ff = 0; ff < FF; ff++) {
            float wv = pW[ff*DD + d];
            a0 = fmaf(pe[0][ff], wv, a0);
            a1 = fmaf(pe[1][ff], wv, a1);
            a2 = fmaf(pe[2][ff], wv, a2);
            a3 = fmaf(pe[3][ff], wv, a3);
        }
        vals[4] = a0; vals[5] = a1; vals[6] = a2; vals[7] = a3;
    }

    float mean[8];
    blk_sum8(vals, mean, red);
    float dv[8], v2[8];
    #pragma unroll
    for (int r = 0; r < 8; r++) { dv[r] = vals[r] - mean[r]*(1.0f/DD); v2[r] = dv[r]*dv[r]; }
    float var[8];
    blk_sum8(v2, var, red);

    float lw1 = l1w[d], lb1 = l1b[d], lw2 = l2w[d], lb2 = l2b[d];
    #pragma unroll
    for (int r = 0; r < 4; r++) {
        float o1 = dv[r]   * rsqrtf(var[r]  *(1.0f/DD) + 1e-5f) * lw1 + lb1;
        float o2 = dv[r+4] * rsqrtf(var[r+4]*(1.0f/DD) + 1e-5f) * lw2 + lb2;
        out[(size_t)(r0 + r)*DD + d] = o1 + o2;
    }
}

// ---------------- launch ----------------
extern "C" void kernel_launch(void* const* d_in, const int* in_sizes, int n_in,
                              void* d_out, int out_size) {
    const float* x   = (const float*)d_in[0];
    const float* rW  = (const float*)d_in[1];
    const float* rb  = (const float*)d_in[2];
    const float* pW  = (const float*)d_in[3];
    const float* pb  = (const float*)d_in[4];
    const float* l1w = (const float*)d_in[5];
    const float* l1b = (const float*)d_in[6];
    const float* l2w = (const float*)d_in[7];
    const float* l2b = (const float*)d_in[8];
    const float* al  = (const float*)d_in[9];
    const float* sg  = (const float*)d_in[10];
    const float* lns = (const float*)d_in[11];
    const float* sw  = (const float*)d_in[12];
    const float* qW  = (const float*)d_in[13];
    const float* qb  = (const float*)d_in[14];
    const float* kW  = (const float*)d_in[15];
    const float* kb  = (const float*)d_in[16];
    float* out = (float*)d_out;

    float* qg; float* kg; float* Gg; float* Eg;
    cudaGetSymbolAddress((void**)&Gg, g_G);
    cudaGetSymbolAddress((void**)&Eg, g_E);
    cudaGetSymbolAddress((void**)&qg, g_q);
    cudaGetSymbolAddress((void**)&kg, g_k);

    qk_proj_kernel<<<NROW/4, 256>>>(x, qW, qb, kW, kb);
    gemm_nt_tf32<<<dim3(SS/128, SS/128, 2*BB), 256>>>(x, qg, kg, Gg, Eg);
    row_kernel<<<NROW, 512>>>(al, sg);
    gemm_Ex_tf32<<<dim3(KSPLIT, SS/128, BB), 256>>>(x);
    out_kernel<<<NROW/4, 256>>>(x, rW, rb, l1w, l1b, lns, sw, pW, pb, l2w, l2b, out);
}

// round 13
// speedup vs baseline: 1.4275x; 1.0058x over previous
#include <cuda_runtime.h>
#include <cuda_fp16.h>
#include <math.h>

#define BB 4
#define SS 2048
#define FF 64
#define DD 256
#define NSC 15
#define NROW (BB*SS)   /* 8192 */
#define KSPLIT 16
#define NB 2048        /* histogram bins for quantile */

// ---------------- device scratch ----------------
__device__ float  g_G[(size_t)BB*SS*SS];     // gram (fp32)
__device__ float  g_E[(size_t)BB*SS*SS];     // qk scores (fp32)
__device__ __half g_Eh[(size_t)BB*SS*SS];    // E weights (fp16)
__device__ float  g_q[NROW*FF];
__device__ float  g_k[NROW*FF];
__device__ float  g_sq[NROW];
__device__ float  g_pe[(size_t)KSPLIT*NROW*FF];

// ---------------- tf32 mma helpers ----------------
__device__ __forceinline__ void mma_tf32(float* c,
                                         unsigned a0, unsigned a1, unsigned a2, unsigned a3,
                                         unsigned b0, unsigned b1) {
    asm volatile(
        "mma.sync.aligned.m16n8k8.row.col.f32.tf32.tf32.f32 "
        "{%0,%1,%2,%3}, {%4,%5,%6,%7}, {%8,%9}, {%0,%1,%2,%3};\n"
        : "+f"(c[0]), "+f"(c[1]), "+f"(c[2]), "+f"(c[3])
        : "r"(a0), "r"(a1), "r"(a2), "r"(a3), "r"(b0), "r"(b1));
}

__device__ __forceinline__ unsigned cvt_tf32(float v) {
    unsigned r;
    asm("cvt.rna.tf32.f32 %0, %1;\n" : "=r"(r) : "f"(v));
    return r;
}

__device__ __forceinline__ float sqrt_approx(float x) {
    float r;
    asm("sqrt.approx.f32 %0, %1;\n" : "=f"(r) : "f"(x));
    return r;
}

__device__ __forceinline__ float rsqrt_approx(float x) {
    float r;
    asm("rsqrt.approx.f32 %0, %1;\n" : "=f"(r) : "f"(x));
    return r;
}

// ---------------- batched 8-value 256-thread sum ----------------
__device__ __forceinline__ void blk_sum8(const float* v, float* res, volatile float (*red)[8]) {
    int l = threadIdx.x & 31, w = threadIdx.x >> 5;
    #pragma unroll
    for (int r = 0; r < 8; r++) {
        float t = v[r];
        #pragma unroll
        for (int o = 16; o; o >>= 1) t += __shfl_xor_sync(0xffffffffu, t, o);
        if (l == 0) red[r][w] = t;
    }
    __syncthreads();
    if (threadIdx.x < 32) {
        int r = l >> 2, i = l & 3;
        float t = red[r][i] + red[r][i + 4];
        t += __shfl_xor_sync(0xffffffffu, t, 2);
        t += __shfl_xor_sync(0xffffffffu, t, 1);
        if (i == 0) red[r][0] = t;
    }
    __syncthreads();
    #pragma unroll
    for (int r = 0; r < 8; r++) res[r] = red[r][0];
    __syncthreads();
}

// ---------------- K1a: q/k projections + sq ----------------
__global__ void qk_proj_kernel(const float* __restrict__ x,
                               const float* __restrict__ qW, const float* __restrict__ qb,
                               const float* __restrict__ kW, const float* __restrict__ kb) {
    int row = blockIdx.x * 4 + (threadIdx.x >> 6);
    int f   = threadIdx.x & 63;
    const float* xr = x + (size_t)row * FF;
    float aq = qb[f], ak = kb[f], ss = 0.f;
    #pragma unroll
    for (int k = 0; k < FF; k++) {
        float xv = xr[k];
        aq = fmaf(xv, qW[k*FF + f], aq);
        ak = fmaf(xv, kW[k*FF + f], ak);
        ss = fmaf(xv, xv, ss);
    }
    g_q[(size_t)row*FF + f] = aq;
    g_k[(size_t)row*FF + f] = ak;
    if (f == 0) g_sq[row] = ss;
}

// ---------------- K2: 128x128 tile NT GEMM, pure 1x TF32 (K=64) ----------------
__global__ void __launch_bounds__(256, 2) gemm_nt_tf32(const float* __restrict__ x,
                                                       const float* __restrict__ q,
                                                       const float* __restrict__ k,
                                                       float* __restrict__ G,
                                                       float* __restrict__ E_) {
    __shared__ __align__(16) float As[128][36];
    __shared__ __align__(16) float Bs[128][36];
    int zz = blockIdx.z;
    int b  = zz & 3;
    bool isqk = zz >= 4;
    int s0 = blockIdx.y << 7;
    int t0 = blockIdx.x << 7;
    const float* Ab = (isqk ? q : x) + (size_t)b * SS * FF;
    const float* Bb = (isqk ? k : x) + (size_t)b * SS * FF;
    float*       Cb = (isqk ? E_ : G) + (size_t)b * SS * SS;
    int tid  = threadIdx.x;
    int lane = tid & 31;
    int wid  = tid >> 5;
    int rb   = (wid & 1) * 64;
    int cb   = (wid >> 1) * 32;
    int lr = lane >> 2, lc = lane & 3;

    float acc[4][4][4];
    #pragma unroll
    for (int i = 0; i < 4; i++)
        #pragma unroll
        for (int j = 0; j < 4; j++)
            #pragma unroll
            for (int r = 0; r < 4; r++) acc[i][j][r] = 0.f;

    #pragma unroll
    for (int st = 0; st < 2; st++) {
        int koff = st * 32;
        #pragma unroll
        for (int l = 0; l < 4; l++) {
            int f4 = tid + l*256;
            int r  = f4 >> 3;
            int kc = (f4 & 7) * 4;
            *(float4*)&As[r][kc] = *(const float4*)&Ab[(size_t)(s0 + r)*FF + koff + kc];
            *(float4*)&Bs[r][kc] = *(const float4*)&Bb[(size_t)(t0 + r)*FF + koff + kc];
        }
        __syncthreads();
        #pragma unroll
        for (int k0 = 0; k0 < 32; k0 += 8) {
            unsigned bh[4][2];
            #pragma unroll
            for (int nt = 0; nt < 4; nt++) {
                int n = cb + nt*8 + lr;
                bh[nt][0] = cvt_tf32(Bs[n][k0 + lc]);
                bh[nt][1] = cvt_tf32(Bs[n][k0 + 4 + lc]);
            }
            #pragma unroll
            for (int mt = 0; mt < 4; mt++) {
                int r = rb + mt*16 + lr;
                unsigned ah[4];
                ah[0] = cvt_tf32(As[r][k0 + lc]);
                ah[1] = cvt_tf32(As[r + 8][k0 + lc]);
                ah[2] = cvt_tf32(As[r][k0 + 4 + lc]);
                ah[3] = cvt_tf32(As[r + 8][k0 + 4 + lc]);
                #pragma unroll
                for (int nt = 0; nt < 4; nt++)
                    mma_tf32(acc[mt][nt], ah[0], ah[1], ah[2], ah[3], bh[nt][0], bh[nt][1]);
            }
        }
        __syncthreads();
    }
    #pragma unroll
    for (int mt = 0; mt < 4; mt++) {
        #pragma unroll
        for (int nt = 0; nt < 4; nt++) {
            int r    = s0 + rb + mt*16 + lr;
            int cidx = t0 + cb + nt*8 + (lc << 1);
            *(float2*)&Cb[(size_t)r*SS + cidx]       = make_float2(acc[mt][nt][0], acc[mt][nt][1]);
            *(float2*)&Cb[(size_t)(r + 8)*SS + cidx] = make_float2(acc[mt][nt][2], acc[mt][nt][3]);
        }
    }
}

// ---------------- K3: row kernel v8 — histogram quantile, fp16 E output ----------------
__global__ void __launch_bounds__(512, 3) row_kernel(const float* __restrict__ alpha_p,
                                                     const float* __restrict__ sig_p) {
    __shared__ unsigned hist[NB];       // 8 KB
    __shared__ float redf[3][16];
    __shared__ float stat[3];           // d2min, d2max, Z
    __shared__ unsigned woff[16];
    __shared__ unsigned bq[6];
    int row = blockIdx.x;
    int b = row >> 11, s = row & (SS - 1);
    int tid = threadIdx.x;
    int lane = tid & 31, wid = tid >> 5;
    const float* Grow = g_G + (size_t)b*SS*SS + (size_t)s*SS;
    const float* Srow = g_E + (size_t)b*SS*SS + (size_t)s*SS;
    __half*      Ehrow = g_Eh + (size_t)b*SS*SS + (size_t)s*SS;
    const float* sqb = g_sq + b*SS;
    float sqs = sqb[s];
    float rns = rsqrt_approx(fmaxf(sqs, 1e-24f));

    #pragma unroll
    for (int j = 0; j < 4; j++) hist[tid + j*512] = 0;

    float4 g4  = ((const float4*)Grow)[tid];
    float4 sc4 = ((const float4*)Srow)[tid];
    float4 sq4 = ((const float4*)sqb)[tid];
    float d2[4];
    d2[0] = fmaxf(sqs + sq4.x - 2.0f*g4.x, 0.0f);
    d2[1] = fmaxf(sqs + sq4.y - 2.0f*g4.y, 0.0f);
    d2[2] = fmaxf(sqs + sq4.z - 2.0f*g4.z, 0.0f);
    d2[3] = fmaxf(sqs + sq4.w - 2.0f*g4.w, 0.0f);
    float mn = fminf(fminf(d2[0], d2[1]), fminf(d2[2], d2[3]));
    float mx = fmaxf(fmaxf(d2[0], d2[1]), fmaxf(d2[2], d2[3]));
    float z = __expf(sc4.x*0.125f) + __expf(sc4.y*0.125f)
            + __expf(sc4.z*0.125f) + __expf(sc4.w*0.125f);
    #pragma unroll
    for (int o = 16; o; o >>= 1) {
        mn = fminf(mn, __shfl_xor_sync(0xffffffffu, mn, o));
        mx = fmaxf(mx, __shfl_xor_sync(0xffffffffu, mx, o));
        z += __shfl_xor_sync(0xffffffffu, z, o);
    }
    if (lane == 0) { redf[0][wid] = mn; redf[1][wid] = mx; redf[2][wid] = z; }
    __syncthreads();
    if (tid == 0) {
        float m0 = redf[0][0], m1 = redf[1][0], zz = redf[2][0];
        #pragma unroll
        for (int i = 1; i < 16; i++) {
            m0 = fminf(m0, redf[0][i]);
            m1 = fmaxf(m1, redf[1][i]);
            zz += redf[2][i];
        }
        stat[0] = m0; stat[1] = m1; stat[2] = zz;
    }
    __syncthreads();
    float d2min = stat[0], d2max = stat[1], Z = stat[2];
    float w   = (d2max - d2min) * (1.0f / NB);
    float iw  = (float)NB / fmaxf(d2max - d2min, 1e-30f);

    #pragma unroll
    for (int j = 0; j < 4; j++) {
        int bin = (int)((d2[j] - d2min) * iw);
        bin = bin < NB-1 ? bin : NB-1;
        bin = bin > 0 ? bin : 0;
        atomicAdd(&hist[bin], 1u);
    }
    __syncthreads();

    uint4 v0 = ((const uint4*)hist)[tid];
    unsigned vals[4] = {v0.x, v0.y, v0.z, v0.w};
    unsigned st = vals[0] + vals[1] + vals[2] + vals[3];
    unsigned e = st;
    #pragma unroll
    for (int o = 1; o < 32; o <<= 1) {
        unsigned t = __shfl_up_sync(0xffffffffu, e, o);
        if (lane >= o) e += t;
    }
    if (lane == 31) woff[wid] = e;
    unsigned lexcl = e - st;
    __syncthreads();
    if (tid < 32) {
        unsigned t = (lane < 16) ? woff[lane] : 0u;
        unsigned ei = t;
        #pragma unroll
        for (int o = 1; o < 16; o <<= 1) {
            unsigned u = __shfl_up_sync(0xffffffffu, ei, o);
            if (lane >= o) ei += u;
        }
        if (lane < 16) woff[lane] = ei - t;
    }
    __syncthreads();
    {
        unsigned run = woff[wid] + lexcl;
        #pragma unroll
        for (int j = 0; j < 4; j++) {
            unsigned excl = run; run += vals[j];
            if (excl <= 102u && 102u < run)  { bq[0] = excl; bq[1] = vals[j]; bq[2] = (unsigned)(tid*4 + j); }
            if (excl <= 1944u && 1944u < run){ bq[3] = excl; bq[4] = vals[j]; bq[5] = (unsigned)(tid*4 + j); }
        }
    }
    __syncthreads();

    float frA = (102.35f  - (float)bq[0] + 0.5f) / (float)bq[1];
    float frB = (1944.65f - (float)bq[3] + 0.5f) / (float)bq[4];
    frA = fminf(fmaxf(frA, 0.0f), 1.0f);
    frB = fminf(fmaxf(frB, 0.0f), 1.0f);
    float vmin = sqrt_approx(fmaxf(d2min + ((float)bq[2] + frA) * w, 0.0f));
    float vmax = sqrt_approx(fmaxf(d2min + ((float)bq[5] + frB) * w, 0.0f));

    float a  = 1.0f / (1.0f + __expf(-alpha_p[0]));
    float sg = log1pf(__expf(sig_p[0])) + 0.001f;
    float inv2s2 = 1.0f / (2.0f * sg * sg);
    float invZ = 1.0f / Z;
    float iden = 1.0f / (vmax - vmin + 1e-6f);
    float gg[4] = {g4.x, g4.y, g4.z, g4.w};
    float ssc[4] = {sc4.x, sc4.y, sc4.z, sc4.w};
    float sq_[4] = {sq4.x, sq4.y, sq4.z, sq4.w};
    float oo[4];
    #pragma unroll
    for (int j = 0; j < 4; j++) {
        float dist = sqrt_approx(d2[j]);
        float eu = fminf(fmaxf((dist - vmin)*iden, 0.0f), 1.0f);
        float rr = rsqrt_approx(fmaxf(sq_[j], 1e-24f));
        float cs = (gg[j]*rns*rr + 1.0f) * 0.5f;
        float hyb = a*cs + (1.0f - a)*(1.0f - eu);
        oo[j] = __expf(ssc[j]*0.125f - hyb*inv2s2) * invZ;
    }
    __half2 h0 = __floats2half2_rn(oo[0], oo[1]);
    __half2 h1 = __floats2half2_rn(oo[2], oo[3]);
    uint2 pk;
    pk.x = *(unsigned*)&h0;
    pk.y = *(unsigned*)&h1;
    ((uint2*)Ehrow)[tid] = pk;
}

// ---------------- K4: pe64 = E(fp16) @ x, tf32 mma, K-split ----------------
__global__ void __launch_bounds__(256, 2) gemm_Ex_tf32(const float* __restrict__ x) {
    __shared__ __align__(16) float Es[128][36];
    __shared__ __align__(16) float Xs[64][37];
    int part = blockIdx.x;
    int b  = blockIdx.z;
    int s0 = blockIdx.y << 7;
    const __half* Eb = g_Eh + (size_t)b*SS*SS;
    const float*  Xb = x    + (size_t)b*SS*FF;
    int tid  = threadIdx.x;
    int lane = tid & 31;
    int wid  = tid >> 5;
    int rb   = (wid & 1) * 64;
    int cb   = (wid >> 1) * 16;
    int lr = lane >> 2, lc = lane & 3;

    float acc[4][2][4];
    #pragma unroll
    for (int i = 0; i < 4; i++)
        #pragma unroll
        for (int j = 0; j < 2; j++)
            #pragma unroll
            for (int r = 0; r < 4; r++) acc[i][j][r] = 0.f;

    int kbeg = part * (SS/KSPLIT);
    for (int k0g = kbeg; k0g < kbeg + SS/KSPLIT; k0g += 32) {
        // stage E tile: 128 rows x 32 halfs; 8 halfs per (thread,l)
        #pragma unroll
        for (int l = 0; l < 2; l++) {
            int f4 = tid + l*256;
            int r  = f4 >> 2;
            int kc = (f4 & 3) * 8;
            uint4 hv = *(const uint4*)&Eb[(size_t)(s0 + r)*SS + k0g + kc];
            __half2* hp = (__half2*)&hv;
            float2 f0 = __half22float2(hp[0]);
            float2 f1 = __half22float2(hp[1]);
            float2 f2 = __half22float2(hp[2]);
            float2 f3 = __half22float2(hp[3]);
            *(float4*)&Es[r][kc]     = make_float4(f0.x, f0.y, f1.x, f1.y);
            *(float4*)&Es[r][kc + 4] = make_float4(f2.x, f2.y, f3.x, f3.y);
        }
        #pragma unroll
        for (int l = 0; l < 2; l++) {
            int f4 = tid + l*256;
            int r  = f4 >> 4;
            int cc = (f4 & 15) * 4;
            float4 xv = *(const float4*)&Xb[(size_t)(k0g + r)*FF + cc];
            Xs[cc+0][r] = xv.x; Xs[cc+1][r] = xv.y; Xs[cc+2][r] = xv.z; Xs[cc+3][r] = xv.w;
        }
        __syncthreads();
        #pragma unroll
        for (int k0 = 0; k0 < 32; k0 += 8) {
            unsigned bh[2][2];
            #pragma unroll
            for (int nt = 0; nt < 2; nt++) {
                int n = cb + nt*8 + lr;
                bh[nt][0] = cvt_tf32(Xs[n][k0 + lc]);
                bh[nt][1] = cvt_tf32(Xs[n][k0 + 4 + lc]);
            }
            #pragma unroll
            for (int mt = 0; mt < 4; mt++) {
                int r = rb + mt*16 + lr;
                unsigned ah[4];
                ah[0] = cvt_tf32(Es[r][k0 + lc]);
                ah[1] = cvt_tf32(Es[r + 8][k0 + lc]);
                ah[2] = cvt_tf32(Es[r][k0 + 4 + lc]);
                ah[3] = cvt_tf32(Es[r + 8][k0 + 4 + lc]);
                #pragma unroll
                for (int nt = 0; nt < 2; nt++)
                    mma_tf32(acc[mt][nt], ah[0], ah[1], ah[2], ah[3], bh[nt][0], bh[nt][1]);
            }
        }
        __syncthreads();
    }
    #pragma unroll
    for (int mt = 0; mt < 4; mt++) {
        #pragma unroll
        for (int nt = 0; nt < 2; nt++) {
            int r = s0 + rb + mt*16 + lr;
            int f = cb + nt*8 + (lc << 1);
            size_t base0 = ((size_t)part*NROW + (size_t)b*SS + r)*FF + f;
            size_t base1 = ((size_t)part*NROW + (size_t)b*SS + r + 8)*FF + f;
            *(float2*)&g_pe[base0] = make_float2(acc[mt][nt][0], acc[mt][nt][1]);
            *(float2*)&g_pe[base1] = make_float2(acc[mt][nt][2], acc[mt][nt][3]);
        }
    }
}

// ---------------- K5: merged rpe + projection + dual LN -> out ----------------
__global__ void out_kernel(const float* __restrict__ x,
                           const float* __restrict__ rW, const float* __restrict__ rb,
                           const float* __restrict__ l1w, const float* __restrict__ l1b,
                           const float* __restrict__ lns_p, const float* __restrict__ sw,
                           const float* __restrict__ pW, const float* __restrict__ pb,
                           const float* __restrict__ l2w, const float* __restrict__ l2b,
                           float* __restrict__ out) {
    __shared__ float pe[4][64];
    __shared__ float red[8][8];
    __shared__ float sh3[4][3];
    int r0 = blockIdx.x << 2;
    int tid = threadIdx.x;
    int lane = tid & 31, wid = tid >> 5;
    int rr = tid >> 6, f = tid & 63;

    float lns = fminf(fmaxf(lns_p[0], 1.0f), (float)NSC);
    int n = (int)rintf(lns);

    float pv = 0.f;
    #pragma unroll
    for (int p = 0; p < KSPLIT; p++)
        pv += g_pe[((size_t)p*NROW + r0 + rr)*FF + f];
    pe[rr][f] = pv;

    if (wid < 4) {
        int row = r0 + wid;
        int b = row >> 11, s = row & (SS - 1);
        int sc = lane + 1;
        float s0 = 0.f, s1 = 0.f, s2 = 0.f;
        if (sc <= n && s >= sc) {
            const float* xb = x + (size_t)b * SS * FF;
            float ds = xb[(size_t)s*FF + 0];
            float es = xb[(size_t)s*FF + FF - 1];
            float dd = xb[(size_t)(s - sc)*FF + 0] - ds;
            float de = xb[(size_t)(s - sc)*FF + FF - 1] - es;
            float wd = sw[sc - 1] * expf(-fabsf(dd) * exp2f(-(float)sc));
            s0 = dd; s1 = de; s2 = wd;
        }
        #pragma unroll
        for (int o = 16; o; o >>= 1) {
            s0 += __shfl_xor_sync(0xffffffffu, s0, o);
            s1 += __shfl_xor_sync(0xffffffffu, s1, o);
            s2 += __shfl_xor_sync(0xffffffffu, s2, o);
        }
        if (lane == 0) { sh3[wid][0] = s0; sh3[wid][1] = s1; sh3[wid][2] = s2; }
    }
    __syncthreads();

    int d = tid;
    float w1 = rW[d], w2r = rW[DD + d], w3 = rW[2*DD + d];
    float rbv = (float)n * rb[d];
    float vals[8];
    #pragma unroll
    for (int r = 0; r < 4; r++)
        vals[r] = sh3[r][0]*w1 + sh3[r][1]*w2r + sh3[r][2]*w3 + rbv;
    {
        float pbv = pb[d];
        float a0 = pbv, a1 = pbv, a2 = pbv, a3 = pbv;
        #pragma unroll
        for (int ff = 0; ff < FF; ff++) {
            float wv = pW[ff*DD + d];
            a0 = fmaf(pe[0][ff], wv, a0);
            a1 = fmaf(pe[1][ff], wv, a1);
            a2 = fmaf(pe[2][ff], wv, a2);
            a3 = fmaf(pe[3][ff], wv, a3);
        }
        vals[4] = a0; vals[5] = a1; vals[6] = a2; vals[7] = a3;
    }

    float mean[8];
    blk_sum8(vals, mean, red);
    float dv[8], v2[8];
    #pragma unroll
    for (int r = 0; r < 8; r++) { dv[r] = vals[r] - mean[r]*(1.0f/DD); v2[r] = dv[r]*dv[r]; }
    float var[8];
    blk_sum8(v2, var, red);

    float lw1 = l1w[d], lb1 = l1b[d], lw2 = l2w[d], lb2 = l2b[d];
    #pragma unroll
    for (int r = 0; r < 4; r++) {
        float o1 = dv[r]   * rsqrtf(var[r]  *(1.0f/DD) + 1e-5f) * lw1 + lb1;
        float o2 = dv[r+4] * rsqrtf(var[r+4]*(1.0f/DD) + 1e-5f) * lw2 + lb2;
        out[(size_t)(r0 + r)*DD + d] = o1 + o2;
    }
}

// ---------------- launch ----------------
extern "C" void kernel_launch(void* const* d_in, const int* in_sizes, int n_in,
                              void* d_out, int out_size) {
    const float* x   = (const float*)d_in[0];
    const float* rW  = (const float*)d_in[1];
    const float* rb  = (const float*)d_in[2];
    const float* pW  = (const float*)d_in[3];
    const float* pb  = (const float*)d_in[4];
    const float* l1w = (const float*)d_in[5];
    const float* l1b = (const float*)d_in[6];
    const float* l2w = (const float*)d_in[7];
    const float* l2b = (const float*)d_in[8];
    const float* al  = (const float*)d_in[9];
    const float* sg  = (const float*)d_in[10];
    const float* lns = (const float*)d_in[11];
    const float* sw  = (const float*)d_in[12];
    const float* qW  = (const float*)d_in[13];
    const float* qb  = (const float*)d_in[14];
    const float* kW  = (const float*)d_in[15];
    const float* kb  = (const float*)d_in[16];
    float* out = (float*)d_out;

    float* qg; float* kg; float* Gg; float* Eg;
    cudaGetSymbolAddress((void**)&Gg, g_G);
    cudaGetSymbolAddress((void**)&Eg, g_E);
    cudaGetSymbolAddress((void**)&qg, g_q);
    cudaGetSymbolAddress((void**)&kg, g_k);

    qk_proj_kernel<<<NROW/4, 256>>>(x, qW, qb, kW, kb);
    gemm_nt_tf32<<<dim3(SS/128, SS/128, 2*BB), 256>>>(x, qg, kg, Gg, Eg);
    row_kernel<<<NROW, 512>>>(al, sg);
    gemm_Ex_tf32<<<dim3(KSPLIT, SS/128, BB), 256>>>(x);
    out_kernel<<<NROW/4, 256>>>(x, rW, rb, l1w, l1b, lns, sw, pW, pb, l2w, l2b, out);
}

// round 15
// speedup vs baseline: 1.4465x; 1.0133x over previous
#include <cuda_runtime.h>
#include <cuda_fp16.h>
#include <math.h>

#define BB 4
#define SS 2048
#define FF 64
#define DD 256
#define NSC 15
#define NROW (BB*SS)   /* 8192 */
#define KSPLIT 16
#define NB 2048        /* histogram bins for quantile */

// ---------------- device scratch ----------------
__device__ __half g_Gh[(size_t)BB*SS*SS];    // gram (fp16)
__device__ __half g_Sh[(size_t)BB*SS*SS];    // qk scores (fp16)
__device__ __half g_Eh[(size_t)BB*SS*SS];    // E weights (fp16)
__device__ float  g_q[NROW*FF];
__device__ float  g_k[NROW*FF];
__device__ float  g_sq[NROW];
__device__ float  g_pe[(size_t)KSPLIT*NROW*FF];

// ---------------- tf32 mma helpers ----------------
__device__ __forceinline__ void mma_tf32(float* c,
                                         unsigned a0, unsigned a1, unsigned a2, unsigned a3,
                                         unsigned b0, unsigned b1) {
    asm volatile(
        "mma.sync.aligned.m16n8k8.row.col.f32.tf32.tf32.f32 "
        "{%0,%1,%2,%3}, {%4,%5,%6,%7}, {%8,%9}, {%0,%1,%2,%3};\n"
        : "+f"(c[0]), "+f"(c[1]), "+f"(c[2]), "+f"(c[3])
        : "r"(a0), "r"(a1), "r"(a2), "r"(a3), "r"(b0), "r"(b1));
}

__device__ __forceinline__ unsigned cvt_tf32(float v) {
    unsigned r;
    asm("cvt.rna.tf32.f32 %0, %1;\n" : "=r"(r) : "f"(v));
    return r;
}

__device__ __forceinline__ float sqrt_approx(float x) {
    float r;
    asm("sqrt.approx.f32 %0, %1;\n" : "=f"(r) : "f"(x));
    return r;
}

__device__ __forceinline__ float rsqrt_approx(float x) {
    float r;
    asm("rsqrt.approx.f32 %0, %1;\n" : "=f"(r) : "f"(x));
    return r;
}

// ---------------- batched 8-value 256-thread sum ----------------
__device__ __forceinline__ void blk_sum8(const float* v, float* res, volatile float (*red)[8]) {
    int l = threadIdx.x & 31, w = threadIdx.x >> 5;
    #pragma unroll
    for (int r = 0; r < 8; r++) {
        float t = v[r];
        #pragma unroll
        for (int o = 16; o; o >>= 1) t += __shfl_xor_sync(0xffffffffu, t, o);
        if (l == 0) red[r][w] = t;
    }
    __syncthreads();
    if (threadIdx.x < 32) {
        int r = l >> 2, i = l & 3;
        float t = red[r][i] + red[r][i + 4];
        t += __shfl_xor_sync(0xffffffffu, t, 2);
        t += __shfl_xor_sync(0xffffffffu, t, 1);
        if (i == 0) red[r][0] = t;
    }
    __syncthreads();
    #pragma unroll
    for (int r = 0; r < 8; r++) res[r] = red[r][0];
    __syncthreads();
}

// ---------------- K1a: q/k projections + sq ----------------
__global__ void qk_proj_kernel(const float* __restrict__ x,
                               const float* __restrict__ qW, const float* __restrict__ qb,
                               const float* __restrict__ kW, const float* __restrict__ kb) {
    int row = blockIdx.x * 4 + (threadIdx.x >> 6);
    int f   = threadIdx.x & 63;
    const float* xr = x + (size_t)row * FF;
    float aq = qb[f], ak = kb[f], ss = 0.f;
    #pragma unroll
    for (int k = 0; k < FF; k++) {
        float xv = xr[k];
        aq = fmaf(xv, qW[k*FF + f], aq);
        ak = fmaf(xv, kW[k*FF + f], ak);
        ss = fmaf(xv, xv, ss);
    }
    g_q[(size_t)row*FF + f] = aq;
    g_k[(size_t)row*FF + f] = ak;
    if (f == 0) g_sq[row] = ss;
}

// ---------------- K2: 128x128 tile NT GEMM, tf32 mma, fp16 output (K=64) ----------------
// z<4 : G = x.x^T -> g_Gh  |  z>=4 : scores = q.k^T -> g_Sh
__global__ void __launch_bounds__(256, 2) gemm_nt_tf32(const float* __restrict__ x,
                                                       const float* __restrict__ q,
                                                       const float* __restrict__ k) {
    __shared__ __align__(16) float As[128][36];
    __shared__ __align__(16) float Bs[128][36];
    int zz = blockIdx.z;
    int b  = zz & 3;
    bool isqk = zz >= 4;
    int s0 = blockIdx.y << 7;
    int t0 = blockIdx.x << 7;
    const float* Ab = (isqk ? q : x) + (size_t)b * SS * FF;
    const float* Bb = (isqk ? k : x) + (size_t)b * SS * FF;
    __half*      Cb = (isqk ? g_Sh : g_Gh) + (size_t)b * SS * SS;
    int tid  = threadIdx.x;
    int lane = tid & 31;
    int wid  = tid >> 5;
    int rb   = (wid & 1) * 64;
    int cb   = (wid >> 1) * 32;
    int lr = lane >> 2, lc = lane & 3;

    float acc[4][4][4];
    #pragma unroll
    for (int i = 0; i < 4; i++)
        #pragma unroll
        for (int j = 0; j < 4; j++)
            #pragma unroll
            for (int r = 0; r < 4; r++) acc[i][j][r] = 0.f;

    #pragma unroll
    for (int st = 0; st < 2; st++) {
        int koff = st * 32;
        #pragma unroll
        for (int l = 0; l < 4; l++) {
            int f4 = tid + l*256;
            int r  = f4 >> 3;
            int kc = (f4 & 7) * 4;
            *(float4*)&As[r][kc] = *(const float4*)&Ab[(size_t)(s0 + r)*FF + koff + kc];
            *(float4*)&Bs[r][kc] = *(const float4*)&Bb[(size_t)(t0 + r)*FF + koff + kc];
        }
        __syncthreads();
        #pragma unroll
        for (int k0 = 0; k0 < 32; k0 += 8) {
            unsigned bh[4][2];
            #pragma unroll
            for (int nt = 0; nt < 4; nt++) {
                int n = cb + nt*8 + lr;
                bh[nt][0] = cvt_tf32(Bs[n][k0 + lc]);
                bh[nt][1] = cvt_tf32(Bs[n][k0 + 4 + lc]);
            }
            #pragma unroll
            for (int mt = 0; mt < 4; mt++) {
                int r = rb + mt*16 + lr;
                unsigned ah[4];
                ah[0] = cvt_tf32(As[r][k0 + lc]);
                ah[1] = cvt_tf32(As[r + 8][k0 + lc]);
                ah[2] = cvt_tf32(As[r][k0 + 4 + lc]);
                ah[3] = cvt_tf32(As[r + 8][k0 + 4 + lc]);
                #pragma unroll
                for (int nt = 0; nt < 4; nt++)
                    mma_tf32(acc[mt][nt], ah[0], ah[1], ah[2], ah[3], bh[nt][0], bh[nt][1]);
            }
        }
        __syncthreads();
    }
    #pragma unroll
    for (int mt = 0; mt < 4; mt++) {
        #pragma unroll
        for (int nt = 0; nt < 4; nt++) {
            int r    = s0 + rb + mt*16 + lr;
            int cidx = t0 + cb + nt*8 + (lc << 1);
            __half2 h01 = __floats2half2_rn(acc[mt][nt][0], acc[mt][nt][1]);
            __half2 h23 = __floats2half2_rn(acc[mt][nt][2], acc[mt][nt][3]);
            *(__half2*)&Cb[(size_t)r*SS + cidx]       = h01;
            *(__half2*)&Cb[(size_t)(r + 8)*SS + cidx] = h23;
        }
    }
}

// ---------------- K3: row kernel v9 — fp16 in/out, histogram quantile ----------------
__global__ void __launch_bounds__(512, 3) row_kernel(const float* __restrict__ alpha_p,
                                                     const float* __restrict__ sig_p) {
    __shared__ unsigned hist[NB];       // 8 KB
    __shared__ float redf[3][16];
    __shared__ float stat[3];           // d2min, d2max, Z
    __shared__ unsigned woff[16];
    __shared__ unsigned bq[6];
    int row = blockIdx.x;
    int b = row >> 11, s = row & (SS - 1);
    int tid = threadIdx.x;
    int lane = tid & 31, wid = tid >> 5;
    const __half* Ghrow = g_Gh + (size_t)b*SS*SS + (size_t)s*SS;
    const __half* Shrow = g_Sh + (size_t)b*SS*SS + (size_t)s*SS;
    __half*       Ehrow = g_Eh + (size_t)b*SS*SS + (size_t)s*SS;
    const float* sqb = g_sq + b*SS;
    float sqs = sqb[s];
    float rns = rsqrt_approx(fmaxf(sqs, 1e-24f));

    #pragma unroll
    for (int j = 0; j < 4; j++) hist[tid + j*512] = 0;

    // load 4 halfs of G and scores, 4 floats of sq
    uint2 gvp = ((const uint2*)Ghrow)[tid];
    uint2 svp = ((const uint2*)Shrow)[tid];
    float4 sq4 = ((const float4*)sqb)[tid];
    float gg[4], ssc[4];
    {
        __half2* gp = (__half2*)&gvp;
        __half2* sp = (__half2*)&svp;
        float2 a0 = __half22float2(gp[0]), a1 = __half22float2(gp[1]);
        float2 b0 = __half22float2(sp[0]), b1 = __half22float2(sp[1]);
        gg[0] = a0.x; gg[1] = a0.y; gg[2] = a1.x; gg[3] = a1.y;
        ssc[0] = b0.x; ssc[1] = b0.y; ssc[2] = b1.x; ssc[3] = b1.y;
    }
    float sq_[4] = {sq4.x, sq4.y, sq4.z, sq4.w};
    float d2[4];
    #pragma unroll
    for (int j = 0; j < 4; j++)
        d2[j] = fmaxf(sqs + sq_[j] - 2.0f*gg[j], 0.0f);
    float mn = fminf(fminf(d2[0], d2[1]), fminf(d2[2], d2[3]));
    float mx = fmaxf(fmaxf(d2[0], d2[1]), fmaxf(d2[2], d2[3]));
    float z = __expf(ssc[0]*0.125f) + __expf(ssc[1]*0.125f)
            + __expf(ssc[2]*0.125f) + __expf(ssc[3]*0.125f);
    #pragma unroll
    for (int o = 16; o; o >>= 1) {
        mn = fminf(mn, __shfl_xor_sync(0xffffffffu, mn, o));
        mx = fmaxf(mx, __shfl_xor_sync(0xffffffffu, mx, o));
        z += __shfl_xor_sync(0xffffffffu, z, o);
    }
    if (lane == 0) { redf[0][wid] = mn; redf[1][wid] = mx; redf[2][wid] = z; }
    __syncthreads();
    if (tid == 0) {
        float m0 = redf[0][0], m1 = redf[1][0], zz = redf[2][0];
        #pragma unroll
        for (int i = 1; i < 16; i++) {
            m0 = fminf(m0, redf[0][i]);
            m1 = fmaxf(m1, redf[1][i]);
            zz += redf[2][i];
        }
        stat[0] = m0; stat[1] = m1; stat[2] = zz;
    }
    __syncthreads();
    float d2min = stat[0], d2max = stat[1], Z = stat[2];
    float w   = (d2max - d2min) * (1.0f / NB);
    float iw  = (float)NB / fmaxf(d2max - d2min, 1e-30f);

    #pragma unroll
    for (int j = 0; j < 4; j++) {
        int bin = (int)((d2[j] - d2min) * iw);
        bin = bin < NB-1 ? bin : NB-1;
        bin = bin > 0 ? bin : 0;
        atomicAdd(&hist[bin], 1u);
    }
    __syncthreads();

    uint4 v0 = ((const uint4*)hist)[tid];
    unsigned vals[4] = {v0.x, v0.y, v0.z, v0.w};
    unsigned st = vals[0] + vals[1] + vals[2] + vals[3];
    unsigned e = st;
    #pragma unroll
    for (int o = 1; o < 32; o <<= 1) {
        unsigned t = __shfl_up_sync(0xffffffffu, e, o);
        if (lane >= o) e += t;
    }
    if (lane == 31) woff[wid] = e;
    unsigned lexcl = e - st;
    __syncthreads();
    if (tid < 32) {
        unsigned t = (lane < 16) ? woff[lane] : 0u;
        unsigned ei = t;
        #pragma unroll
        for (int o = 1; o < 16; o <<= 1) {
            unsigned u = __shfl_up_sync(0xffffffffu, ei, o);
            if (lane >= o) ei += u;
        }
        if (lane < 16) woff[lane] = ei - t;
    }
    __syncthreads();
    {
        unsigned run = woff[wid] + lexcl;
        #pragma unroll
        for (int j = 0; j < 4; j++) {
            unsigned excl = run; run += vals[j];
            if (excl <= 102u && 102u < run)  { bq[0] = excl; bq[1] = vals[j]; bq[2] = (unsigned)(tid*4 + j); }
            if (excl <= 1944u && 1944u < run){ bq[3] = excl; bq[4] = vals[j]; bq[5] = (unsigned)(tid*4 + j); }
        }
    }
    __syncthreads();

    float frA = (102.35f  - (float)bq[0] + 0.5f) / (float)bq[1];
    float frB = (1944.65f - (float)bq[3] + 0.5f) / (float)bq[4];
    frA = fminf(fmaxf(frA, 0.0f), 1.0f);
    frB = fminf(fmaxf(frB, 0.0f), 1.0f);
    float vmin = sqrt_approx(fmaxf(d2min + ((float)bq[2] + frA) * w, 0.0f));
    float vmax = sqrt_approx(fmaxf(d2min + ((float)bq[5] + frB) * w, 0.0f));

    float a  = 1.0f / (1.0f + __expf(-alpha_p[0]));
    float sg = log1pf(__expf(sig_p[0])) + 0.001f;
    float inv2s2 = 1.0f / (2.0f * sg * sg);
    float invZ = 1.0f / Z;
    float iden = 1.0f / (vmax - vmin + 1e-6f);
    float oo[4];
    #pragma unroll
    for (int j = 0; j < 4; j++) {
        float dist = sqrt_approx(d2[j]);
        float eu = fminf(fmaxf((dist - vmin)*iden, 0.0f), 1.0f);
        float rr = rsqrt_approx(fmaxf(sq_[j], 1e-24f));
        float cs = (gg[j]*rns*rr + 1.0f) * 0.5f;
        float hyb = a*cs + (1.0f - a)*(1.0f - eu);
        oo[j] = __expf(ssc[j]*0.125f - hyb*inv2s2) * invZ;
    }
    __half2 h0 = __floats2half2_rn(oo[0], oo[1]);
    __half2 h1 = __floats2half2_rn(oo[2], oo[3]);
    uint2 pk;
    pk.x = *(unsigned*)&h0;
    pk.y = *(unsigned*)&h1;
    ((uint2*)Ehrow)[tid] = pk;
}

// ---------------- K4: pe64 = E(fp16) @ x, tf32 mma, K-split ----------------
__global__ void __launch_bounds__(256, 2) gemm_Ex_tf32(const float* __restrict__ x) {
    __shared__ __align__(16) float Es[128][36];
    __shared__ __align__(16) float Xs[64][37];
    int part = blockIdx.x;
    int b  = blockIdx.z;
    int s0 = blockIdx.y << 7;
    const __half* Eb = g_Eh + (size_t)b*SS*SS;
    const float*  Xb = x    + (size_t)b*SS*FF;
    int tid  = threadIdx.x;
    int lane = tid & 31;
    int wid  = tid >> 5;
    int rb   = (wid & 1) * 64;
    int cb   = (wid >> 1) * 16;
    int lr = lane >> 2, lc = lane & 3;

    float acc[4][2][4];
    #pragma unroll
    for (int i = 0; i < 4; i++)
        #pragma unroll
        for (int j = 0; j < 2; j++)
            #pragma unroll
            for (int r = 0; r < 4; r++) acc[i][j][r] = 0.f;

    int kbeg = part * (SS/KSPLIT);
    for (int k0g = kbeg; k0g < kbeg + SS/KSPLIT; k0g += 32) {
        #pragma unroll
        for (int l = 0; l < 2; l++) {
            int f4 = tid + l*256;
            int r  = f4 >> 2;
            int kc = (f4 & 3) * 8;
            uint4 hv = *(const uint4*)&Eb[(size_t)(s0 + r)*SS + k0g + kc];
            __half2* hp = (__half2*)&hv;
            float2 f0 = __half22float2(hp[0]);
            float2 f1 = __half22float2(hp[1]);
            float2 f2 = __half22float2(hp[2]);
            float2 f3 = __half22float2(hp[3]);
            *(float4*)&Es[r][kc]     = make_float4(f0.x, f0.y, f1.x, f1.y);
            *(float4*)&Es[r][kc + 4] = make_float4(f2.x, f2.y, f3.x, f3.y);
        }
        #pragma unroll
        for (int l = 0; l < 2; l++) {
            int f4 = tid + l*256;
            int r  = f4 >> 4;
            int cc = (f4 & 15) * 4;
            float4 xv = *(const float4*)&Xb[(size_t)(k0g + r)*FF + cc];
            Xs[cc+0][r] = xv.x; Xs[cc+1][r] = xv.y; Xs[cc+2][r] = xv.z; Xs[cc+3][r] = xv.w;
        }
        __syncthreads();
        #pragma unroll
        for (int k0 = 0; k0 < 32; k0 += 8) {
            unsigned bh[2][2];
            #pragma unroll
            for (int nt = 0; nt < 2; nt++) {
                int n = cb + nt*8 + lr;
                bh[nt][0] = cvt_tf32(Xs[n][k0 + lc]);
                bh[nt][1] = cvt_tf32(Xs[n][k0 + 4 + lc]);
            }
            #pragma unroll
            for (int mt = 0; mt < 4; mt++) {
                int r = rb + mt*16 + lr;
                unsigned ah[4];
                ah[0] = cvt_tf32(Es[r][k0 + lc]);
                ah[1] = cvt_tf32(Es[r + 8][k0 + lc]);
                ah[2] = cvt_tf32(Es[r][k0 + 4 + lc]);
                ah[3] = cvt_tf32(Es[r + 8][k0 + 4 + lc]);
                #pragma unroll
                for (int nt = 0; nt < 2; nt++)
                    mma_tf32(acc[mt][nt], ah[0], ah[1], ah[2], ah[3], bh[nt][0], bh[nt][1]);
            }
        }
        __syncthreads();
    }
    #pragma unroll
    for (int mt = 0; mt < 4; mt++) {
        #pragma unroll
        for (int nt = 0; nt < 2; nt++) {
            int r = s0 + rb + mt*16 + lr;
            int f = cb + nt*8 + (lc << 1);
            size_t base0 = ((size_t)part*NROW + (size_t)b*SS + r)*FF + f;
            size_t base1 = ((size_t)part*NROW + (size_t)b*SS + r + 8)*FF + f;
            *(float2*)&g_pe[base0] = make_float2(acc[mt][nt][0], acc[mt][nt][1]);
            *(float2*)&g_pe[base1] = make_float2(acc[mt][nt][2], acc[mt][nt][3]);
        }
    }
}

// ---------------- K5: merged rpe + projection + dual LN -> out ----------------
__global__ void out_kernel(const float* __restrict__ x,
                           const float* __restrict__ rW, const float* __restrict__ rb,
                           const float* __restrict__ l1w, const float* __restrict__ l1b,
                           const float* __restrict__ lns_p, const float* __restrict__ sw,
                           const float* __restrict__ pW, const float* __restrict__ pb,
                           const float* __restrict__ l2w, const float* __restrict__ l2b,
                           float* __restrict__ out) {
    __shared__ float pe[4][64];
    __shared__ float red[8][8];
    __shared__ float sh3[4][3];
    int r0 = blockIdx.x << 2;
    int tid = threadIdx.x;
    int lane = tid & 31, wid = tid >> 5;
    int rr = tid >> 6, f = tid & 63;

    float lns = fminf(fmaxf(lns_p[0], 1.0f), (float)NSC);
    int n = (int)rintf(lns);

    float pv = 0.f;
    #pragma unroll
    for (int p = 0; p < KSPLIT; p++)
        pv += g_pe[((size_t)p*NROW + r0 + rr)*FF + f];
    pe[rr][f] = pv;

    if (wid < 4) {
        int row = r0 + wid;
        int b = row >> 11, s = row & (SS - 1);
        int sc = lane + 1;
        float s0 = 0.f, s1 = 0.f, s2 = 0.f;
        if (sc <= n && s >= sc) {
            const float* xb = x + (size_t)b * SS * FF;
            float ds = xb[(size_t)s*FF + 0];
            float es = xb[(size_t)s*FF + FF - 1];
            float dd = xb[(size_t)(s - sc)*FF + 0] - ds;
            float de = xb[(size_t)(s - sc)*FF + FF - 1] - es;
            float wd = sw[sc - 1] * expf(-fabsf(dd) * exp2f(-(float)sc));
            s0 = dd; s1 = de; s2 = wd;
        }
        #pragma unroll
        for (int o = 16; o; o >>= 1) {
            s0 += __shfl_xor_sync(0xffffffffu, s0, o);
            s1 += __shfl_xor_sync(0xffffffffu, s1, o);
            s2 += __shfl_xor_sync(0xffffffffu, s2, o);
        }
        if (lane == 0) { sh3[wid][0] = s0; sh3[wid][1] = s1; sh3[wid][2] = s2; }
    }
    __syncthreads();

    int d = tid;
    float w1 = rW[d], w2r = rW[DD + d], w3 = rW[2*DD + d];
    float rbv = (float)n * rb[d];
    float vals[8];
    #pragma unroll
    for (int r = 0; r < 4; r++)
        vals[r] = sh3[r][0]*w1 + sh3[r][1]*w2r + sh3[r][2]*w3 + rbv;
    {
        float pbv = pb[d];
        float a0 = pbv, a1 = pbv, a2 = pbv, a3 = pbv;
        #pragma unroll
        for (int ff = 0; ff < FF; ff++) {
            float wv = pW[ff*DD + d];
            a0 = fmaf(pe[0][ff], wv, a0);
            a1 = fmaf(pe[1][ff], wv, a1);
            a2 = fmaf(pe[2][ff], wv, a2);
            a3 = fmaf(pe[3][ff], wv, a3);
        }
        vals[4] = a0; vals[5] = a1; vals[6] = a2; vals[7] = a3;
    }

    float mean[8];
    blk_sum8(vals, mean, red);
    float dv[8], v2[8];
    #pragma unroll
    for (int r = 0; r < 8; r++) { dv[r] = vals[r] - mean[r]*(1.0f/DD); v2[r] = dv[r]*dv[r]; }
    float var[8];
    blk_sum8(v2, var, red);

    float lw1 = l1w[d], lb1 = l1b[d], lw2 = l2w[d], lb2 = l2b[d];
    #pragma unroll
    for (int r = 0; r < 4; r++) {
        float o1 = dv[r]   * rsqrtf(var[r]  *(1.0f/DD) + 1e-5f) * lw1 + lb1;
        float o2 = dv[r+4] * rsqrtf(var[r+4]*(1.0f/DD) + 1e-5f) * lw2 + lb2;
        out[(size_t)(r0 + r)*DD + d] = o1 + o2;
    }
}

// ---------------- launch ----------------
extern "C" void kernel_launch(void* const* d_in, const int* in_sizes, int n_in,
                              void* d_out, int out_size) {
    const float* x   = (const float*)d_in[0];
    const float* rW  = (const float*)d_in[1];
    const float* rb  = (const float*)d_in[2];
    const float* pW  = (const float*)d_in[3];
    const float* pb  = (const float*)d_in[4];
    const float* l1w = (const float*)d_in[5];
    const float* l1b = (const float*)d_in[6];
    const float* l2w = (const float*)d_in[7];
    const float* l2b = (const float*)d_in[8];
    const float* al  = (const float*)d_in[9];
    const float* sg  = (const float*)d_in[10];
    const float* lns = (const float*)d_in[11];
    const float* sw  = (const float*)d_in[12];
    const float* qW  = (const float*)d_in[13];
    const float* qb  = (const float*)d_in[14];
    const float* kW  = (const float*)d_in[15];
    const float* kb  = (const float*)d_in[16];
    float* out = (float*)d_out;

    float* qg; float* kg;
    cudaGetSymbolAddress((void**)&qg, g_q);
    cudaGetSymbolAddress((void**)&kg, g_k);

    qk_proj_kernel<<<NROW/4, 256>>>(x, qW, qb, kW, kb);
    gemm_nt_tf32<<<dim3(SS/128, SS/128, 2*BB), 256>>>(x, qg, kg);
    row_kernel<<<NROW, 512>>>(al, sg);
    gemm_Ex_tf32<<<dim3(KSPLIT, SS/128, BB), 256>>>(x);
    out_kernel<<<NROW/4, 256>>>(x, rW, rb, l1w, l1b, lns, sw, pW, pb, l2w, l2b, out);
}

// round 16
// speedup vs baseline: 1.4738x; 1.0189x over previous
#include <cuda_runtime.h>
#include <cuda_fp16.h>
#include <math.h>

#define BB 4
#define SS 2048
#define FF 64
#define DD 256
#define NSC 15
#define NROW (BB*SS)   /* 8192 */
#define KSPLIT 16
#define NB 2048        /* histogram bins for quantile */

// ---------------- device scratch ----------------
__device__ __half g_Gh[(size_t)BB*SS*SS];    // gram (fp16)
__device__ __half g_Sh[(size_t)BB*SS*SS];    // qk scores (fp16)
__device__ __half g_Eh[(size_t)BB*SS*SS];    // E weights (fp16)
__device__ __half g_xh[NROW*FF];             // x in fp16 (for HMMA B operand)
__device__ float  g_q[NROW*FF];
__device__ float  g_k[NROW*FF];
__device__ float  g_sq[NROW];
__device__ float  g_pe[(size_t)KSPLIT*NROW*FF];

// ---------------- mma helpers ----------------
__device__ __forceinline__ void mma_tf32(float* c,
                                         unsigned a0, unsigned a1, unsigned a2, unsigned a3,
                                         unsigned b0, unsigned b1) {
    asm volatile(
        "mma.sync.aligned.m16n8k8.row.col.f32.tf32.tf32.f32 "
        "{%0,%1,%2,%3}, {%4,%5,%6,%7}, {%8,%9}, {%0,%1,%2,%3};\n"
        : "+f"(c[0]), "+f"(c[1]), "+f"(c[2]), "+f"(c[3])
        : "r"(a0), "r"(a1), "r"(a2), "r"(a3), "r"(b0), "r"(b1));
}

__device__ __forceinline__ void mma_f16(float* c,
                                        unsigned a0, unsigned a1, unsigned a2, unsigned a3,
                                        unsigned b0, unsigned b1) {
    asm volatile(
        "mma.sync.aligned.m16n8k16.row.col.f32.f16.f16.f32 "
        "{%0,%1,%2,%3}, {%4,%5,%6,%7}, {%8,%9}, {%0,%1,%2,%3};\n"
        : "+f"(c[0]), "+f"(c[1]), "+f"(c[2]), "+f"(c[3])
        : "r"(a0), "r"(a1), "r"(a2), "r"(a3), "r"(b0), "r"(b1));
}

__device__ __forceinline__ unsigned cvt_tf32(float v) {
    unsigned r;
    asm("cvt.rna.tf32.f32 %0, %1;\n" : "=r"(r) : "f"(v));
    return r;
}

__device__ __forceinline__ float sqrt_approx(float x) {
    float r;
    asm("sqrt.approx.f32 %0, %1;\n" : "=f"(r) : "f"(x));
    return r;
}

__device__ __forceinline__ float rsqrt_approx(float x) {
    float r;
    asm("rsqrt.approx.f32 %0, %1;\n" : "=f"(r) : "f"(x));
    return r;
}

// ---------------- batched 8-value 256-thread sum ----------------
__device__ __forceinline__ void blk_sum8(const float* v, float* res, volatile float (*red)[8]) {
    int l = threadIdx.x & 31, w = threadIdx.x >> 5;
    #pragma unroll
    for (int r = 0; r < 8; r++) {
        float t = v[r];
        #pragma unroll
        for (int o = 16; o; o >>= 1) t += __shfl_xor_sync(0xffffffffu, t, o);
        if (l == 0) red[r][w] = t;
    }
    __syncthreads();
    if (threadIdx.x < 32) {
        int r = l >> 2, i = l & 3;
        float t = red[r][i] + red[r][i + 4];
        t += __shfl_xor_sync(0xffffffffu, t, 2);
        t += __shfl_xor_sync(0xffffffffu, t, 1);
        if (i == 0) red[r][0] = t;
    }
    __syncthreads();
    #pragma unroll
    for (int r = 0; r < 8; r++) res[r] = red[r][0];
    __syncthreads();
}

// ---------------- K1a: q/k projections + sq + x->fp16 ----------------
__global__ void qk_proj_kernel(const float* __restrict__ x,
                               const float* __restrict__ qW, const float* __restrict__ qb,
                               const float* __restrict__ kW, const float* __restrict__ kb) {
    int row = blockIdx.x * 4 + (threadIdx.x >> 6);
    int f   = threadIdx.x & 63;
    const float* xr = x + (size_t)row * FF;
    float aq = qb[f], ak = kb[f], ss = 0.f;
    #pragma unroll
    for (int k = 0; k < FF; k++) {
        float xv = xr[k];
        aq = fmaf(xv, qW[k*FF + f], aq);
        ak = fmaf(xv, kW[k*FF + f], ak);
        ss = fmaf(xv, xv, ss);
    }
    g_q[(size_t)row*FF + f] = aq;
    g_k[(size_t)row*FF + f] = ak;
    g_xh[(size_t)row*FF + f] = __float2half_rn(xr[f]);
    if (f == 0) g_sq[row] = ss;
}

// ---------------- K2: 128x128 tile NT GEMM, tf32 mma, fp16 output (K=64) ----------------
__global__ void __launch_bounds__(256, 2) gemm_nt_tf32(const float* __restrict__ x,
                                                       const float* __restrict__ q,
                                                       const float* __restrict__ k) {
    __shared__ __align__(16) float As[128][36];
    __shared__ __align__(16) float Bs[128][36];
    int zz = blockIdx.z;
    int b  = zz & 3;
    bool isqk = zz >= 4;
    int s0 = blockIdx.y << 7;
    int t0 = blockIdx.x << 7;
    const float* Ab = (isqk ? q : x) + (size_t)b * SS * FF;
    const float* Bb = (isqk ? k : x) + (size_t)b * SS * FF;
    __half*      Cb = (isqk ? g_Sh : g_Gh) + (size_t)b * SS * SS;
    int tid  = threadIdx.x;
    int lane = tid & 31;
    int wid  = tid >> 5;
    int rb   = (wid & 1) * 64;
    int cb   = (wid >> 1) * 32;
    int lr = lane >> 2, lc = lane & 3;

    float acc[4][4][4];
    #pragma unroll
    for (int i = 0; i < 4; i++)
        #pragma unroll
        for (int j = 0; j < 4; j++)
            #pragma unroll
            for (int r = 0; r < 4; r++) acc[i][j][r] = 0.f;

    #pragma unroll
    for (int st = 0; st < 2; st++) {
        int koff = st * 32;
        #pragma unroll
        for (int l = 0; l < 4; l++) {
            int f4 = tid + l*256;
            int r  = f4 >> 3;
            int kc = (f4 & 7) * 4;
            *(float4*)&As[r][kc] = *(const float4*)&Ab[(size_t)(s0 + r)*FF + koff + kc];
            *(float4*)&Bs[r][kc] = *(const float4*)&Bb[(size_t)(t0 + r)*FF + koff + kc];
        }
        __syncthreads();
        #pragma unroll
        for (int k0 = 0; k0 < 32; k0 += 8) {
            unsigned bh[4][2];
            #pragma unroll
            for (int nt = 0; nt < 4; nt++) {
                int n = cb + nt*8 + lr;
                bh[nt][0] = cvt_tf32(Bs[n][k0 + lc]);
                bh[nt][1] = cvt_tf32(Bs[n][k0 + 4 + lc]);
            }
            #pragma unroll
            for (int mt = 0; mt < 4; mt++) {
                int r = rb + mt*16 + lr;
                unsigned ah[4];
                ah[0] = cvt_tf32(As[r][k0 + lc]);
                ah[1] = cvt_tf32(As[r + 8][k0 + lc]);
                ah[2] = cvt_tf32(As[r][k0 + 4 + lc]);
                ah[3] = cvt_tf32(As[r + 8][k0 + 4 + lc]);
                #pragma unroll
                for (int nt = 0; nt < 4; nt++)
                    mma_tf32(acc[mt][nt], ah[0], ah[1], ah[2], ah[3], bh[nt][0], bh[nt][1]);
            }
        }
        __syncthreads();
    }
    #pragma unroll
    for (int mt = 0; mt < 4; mt++) {
        #pragma unroll
        for (int nt = 0; nt < 4; nt++) {
            int r    = s0 + rb + mt*16 + lr;
            int cidx = t0 + cb + nt*8 + (lc << 1);
            __half2 h01 = __floats2half2_rn(acc[mt][nt][0], acc[mt][nt][1]);
            __half2 h23 = __floats2half2_rn(acc[mt][nt][2], acc[mt][nt][3]);
            *(__half2*)&Cb[(size_t)r*SS + cidx]       = h01;
            *(__half2*)&Cb[(size_t)(r + 8)*SS + cidx] = h23;
        }
    }
}

// ---------------- K3: row kernel v9 — fp16 in/out, histogram quantile ----------------
__global__ void __launch_bounds__(512, 3) row_kernel(const float* __restrict__ alpha_p,
                                                     const float* __restrict__ sig_p) {
    __shared__ unsigned hist[NB];       // 8 KB
    __shared__ float redf[3][16];
    __shared__ float stat[3];
    __shared__ unsigned woff[16];
    __shared__ unsigned bq[6];
    int row = blockIdx.x;
    int b = row >> 11, s = row & (SS - 1);
    int tid = threadIdx.x;
    int lane = tid & 31, wid = tid >> 5;
    const __half* Ghrow = g_Gh + (size_t)b*SS*SS + (size_t)s*SS;
    const __half* Shrow = g_Sh + (size_t)b*SS*SS + (size_t)s*SS;
    __half*       Ehrow = g_Eh + (size_t)b*SS*SS + (size_t)s*SS;
    const float* sqb = g_sq + b*SS;
    float sqs = sqb[s];
    float rns = rsqrt_approx(fmaxf(sqs, 1e-24f));

    #pragma unroll
    for (int j = 0; j < 4; j++) hist[tid + j*512] = 0;

    uint2 gvp = ((const uint2*)Ghrow)[tid];
    uint2 svp = ((const uint2*)Shrow)[tid];
    float4 sq4 = ((const float4*)sqb)[tid];
    float gg[4], ssc[4];
    {
        __half2* gp = (__half2*)&gvp;
        __half2* sp = (__half2*)&svp;
        float2 a0 = __half22float2(gp[0]), a1 = __half22float2(gp[1]);
        float2 b0 = __half22float2(sp[0]), b1 = __half22float2(sp[1]);
        gg[0] = a0.x; gg[1] = a0.y; gg[2] = a1.x; gg[3] = a1.y;
        ssc[0] = b0.x; ssc[1] = b0.y; ssc[2] = b1.x; ssc[3] = b1.y;
    }
    float sq_[4] = {sq4.x, sq4.y, sq4.z, sq4.w};
    float d2[4];
    #pragma unroll
    for (int j = 0; j < 4; j++)
        d2[j] = fmaxf(sqs + sq_[j] - 2.0f*gg[j], 0.0f);
    float mn = fminf(fminf(d2[0], d2[1]), fminf(d2[2], d2[3]));
    float mx = fmaxf(fmaxf(d2[0], d2[1]), fmaxf(d2[2], d2[3]));
    float z = __expf(ssc[0]*0.125f) + __expf(ssc[1]*0.125f)
            + __expf(ssc[2]*0.125f) + __expf(ssc[3]*0.125f);
    #pragma unroll
    for (int o = 16; o; o >>= 1) {
        mn = fminf(mn, __shfl_xor_sync(0xffffffffu, mn, o));
        mx = fmaxf(mx, __shfl_xor_sync(0xffffffffu, mx, o));
        z += __shfl_xor_sync(0xffffffffu, z, o);
    }
    if (lane == 0) { redf[0][wid] = mn; redf[1][wid] = mx; redf[2][wid] = z; }
    __syncthreads();
    if (tid == 0) {
        float m0 = redf[0][0], m1 = redf[1][0], zz = redf[2][0];
        #pragma unroll
        for (int i = 1; i < 16; i++) {
            m0 = fminf(m0, redf[0][i]);
            m1 = fmaxf(m1, redf[1][i]);
            zz += redf[2][i];
        }
        stat[0] = m0; stat[1] = m1; stat[2] = zz;
    }
    __syncthreads();
    float d2min = stat[0], d2max = stat[1], Z = stat[2];
    float w   = (d2max - d2min) * (1.0f / NB);
    float iw  = (float)NB / fmaxf(d2max - d2min, 1e-30f);

    #pragma unroll
    for (int j = 0; j < 4; j++) {
        int bin = (int)((d2[j] - d2min) * iw);
        bin = bin < NB-1 ? bin : NB-1;
        bin = bin > 0 ? bin : 0;
        atomicAdd(&hist[bin], 1u);
    }
    __syncthreads();

    uint4 v0 = ((const uint4*)hist)[tid];
    unsigned vals[4] = {v0.x, v0.y, v0.z, v0.w};
    unsigned st = vals[0] + vals[1] + vals[2] + vals[3];
    unsigned e = st;
    #pragma unroll
    for (int o = 1; o < 32; o <<= 1) {
        unsigned t = __shfl_up_sync(0xffffffffu, e, o);
        if (lane >= o) e += t;
    }
    if (lane == 31) woff[wid] = e;
    unsigned lexcl = e - st;
    __syncthreads();
    if (tid < 32) {
        unsigned t = (lane < 16) ? woff[lane] : 0u;
        unsigned ei = t;
        #pragma unroll
        for (int o = 1; o < 16; o <<= 1) {
            unsigned u = __shfl_up_sync(0xffffffffu, ei, o);
            if (lane >= o) ei += u;
        }
        if (lane < 16) woff[lane] = ei - t;
    }
    __syncthreads();
    {
        unsigned run = woff[wid] + lexcl;
        #pragma unroll
        for (int j = 0; j < 4; j++) {
            unsigned excl = run; run += vals[j];
            if (excl <= 102u && 102u < run)  { bq[0] = excl; bq[1] = vals[j]; bq[2] = (unsigned)(tid*4 + j); }
            if (excl <= 1944u && 1944u < run){ bq[3] = excl; bq[4] = vals[j]; bq[5] = (unsigned)(tid*4 + j); }
        }
    }
    __syncthreads();

    float frA = (102.35f  - (float)bq[0] + 0.5f) / (float)bq[1];
    float frB = (1944.65f - (float)bq[3] + 0.5f) / (float)bq[4];
    frA = fminf(fmaxf(frA, 0.0f), 1.0f);
    frB = fminf(fmaxf(frB, 0.0f), 1.0f);
    float vmin = sqrt_approx(fmaxf(d2min + ((float)bq[2] + frA) * w, 0.0f));
    float vmax = sqrt_approx(fmaxf(d2min + ((float)bq[5] + frB) * w, 0.0f));

    float a  = 1.0f / (1.0f + __expf(-alpha_p[0]));
    float sg = log1pf(__expf(sig_p[0])) + 0.001f;
    float inv2s2 = 1.0f / (2.0f * sg * sg);
    float invZ = 1.0f / Z;
    float iden = 1.0f / (vmax - vmin + 1e-6f);
    float oo[4];
    #pragma unroll
    for (int j = 0; j < 4; j++) {
        float dist = sqrt_approx(d2[j]);
        float eu = fminf(fmaxf((dist - vmin)*iden, 0.0f), 1.0f);
        float rr = rsqrt_approx(fmaxf(sq_[j], 1e-24f));
        float cs = (gg[j]*rns*rr + 1.0f) * 0.5f;
        float hyb = a*cs + (1.0f - a)*(1.0f - eu);
        oo[j] = __expf(ssc[j]*0.125f - hyb*inv2s2) * invZ;
    }
    __half2 h0 = __floats2half2_rn(oo[0], oo[1]);
    __half2 h1 = __floats2half2_rn(oo[2], oo[3]);
    uint2 pk;
    pk.x = *(unsigned*)&h0;
    pk.y = *(unsigned*)&h1;
    ((uint2*)Ehrow)[tid] = pk;
}

// ---------------- K4: pe64 = E(fp16) @ x(fp16), native HMMA, K-split ----------------
__global__ void __launch_bounds__(256, 3) gemm_Ex_hmma() {
    __shared__ __align__(16) __half Es[128][40];
    __shared__ __align__(16) __half Xs[64][40];
    int part = blockIdx.x;
    int b  = blockIdx.z;
    int s0 = blockIdx.y << 7;
    const __half* Eb = g_Eh + (size_t)b*SS*SS;
    const __half* Xb = g_xh + (size_t)b*SS*FF;
    int tid  = threadIdx.x;
    int lane = tid & 31;
    int wid  = tid >> 5;
    int rb   = (wid & 1) * 64;
    int cb   = (wid >> 1) * 16;
    int gid = lane >> 2, t4 = lane & 3;

    float acc[4][2][4];
    #pragma unroll
    for (int i = 0; i < 4; i++)
        #pragma unroll
        for (int j = 0; j < 2; j++)
            #pragma unroll
            for (int r = 0; r < 4; r++) acc[i][j][r] = 0.f;

    int kbeg = part * (SS/KSPLIT);
    for (int k0g = kbeg; k0g < kbeg + SS/KSPLIT; k0g += 32) {
        // stage E: 128 rows x 32 halfs, native fp16, no conversion
        #pragma unroll
        for (int l = 0; l < 2; l++) {
            int f4 = tid + l*256;
            int r  = f4 >> 2;
            int kc = (f4 & 3) * 8;
            *(uint4*)&Es[r][kc] = *(const uint4*)&Eb[(size_t)(s0 + r)*SS + k0g + kc];
        }
        // stage X transposed: Xs[n][k] so B fragments are contiguous half2
        {
            int r  = tid >> 3;          // k row 0..31
            int cc = (tid & 7) * 8;     // f col base
            uint4 hv = *(const uint4*)&Xb[(size_t)(k0g + r)*FF + cc];
            __half* hp = (__half*)&hv;
            #pragma unroll
            for (int j = 0; j < 8; j++) Xs[cc + j][r] = hp[j];
        }
        __syncthreads();
        #pragma unroll
        for (int kk = 0; kk < 32; kk += 16) {
            unsigned bfr[2][2];
            #pragma unroll
            for (int nt = 0; nt < 2; nt++) {
                int n = cb + nt*8 + gid;
                bfr[nt][0] = *(const unsigned*)&Xs[n][kk + t4*2];
                bfr[nt][1] = *(const unsigned*)&Xs[n][kk + t4*2 + 8];
            }
            #pragma unroll
            for (int mt = 0; mt < 4; mt++) {
                int r = rb + mt*16 + gid;
                unsigned a0 = *(const unsigned*)&Es[r][kk + t4*2];
                unsigned a1 = *(const unsigned*)&Es[r + 8][kk + t4*2];
                unsigned a2 = *(const unsigned*)&Es[r][kk + t4*2 + 8];
                unsigned a3 = *(const unsigned*)&Es[r + 8][kk + t4*2 + 8];
                #pragma unroll
                for (int nt = 0; nt < 2; nt++)
                    mma_f16(acc[mt][nt], a0, a1, a2, a3, bfr[nt][0], bfr[nt][1]);
            }
        }
        __syncthreads();
    }
    #pragma unroll
    for (int mt = 0; mt < 4; mt++) {
        #pragma unroll
        for (int nt = 0; nt < 2; nt++) {
            int r = s0 + rb + mt*16 + gid;
            int f = cb + nt*8 + t4*2;
            size_t base0 = ((size_t)part*NROW + (size_t)b*SS + r)*FF + f;
            size_t base1 = ((size_t)part*NROW + (size_t)b*SS + r + 8)*FF + f;
            *(float2*)&g_pe[base0] = make_float2(acc[mt][nt][0], acc[mt][nt][1]);
            *(float2*)&g_pe[base1] = make_float2(acc[mt][nt][2], acc[mt][nt][3]);
        }
    }
}

// ---------------- K5: merged rpe + projection + dual LN -> out ----------------
__global__ void out_kernel(const float* __restrict__ x,
                           const float* __restrict__ rW, const float* __restrict__ rb,
                           const float* __restrict__ l1w, const float* __restrict__ l1b,
                           const float* __restrict__ lns_p, const float* __restrict__ sw,
                           const float* __restrict__ pW, const float* __restrict__ pb,
                           const float* __restrict__ l2w, const float* __restrict__ l2b,
                           float* __restrict__ out) {
    __shared__ float pe[4][64];
    __shared__ float red[8][8];
    __shared__ float sh3[4][3];
    int r0 = blockIdx.x << 2;
    int tid = threadIdx.x;
    int lane = tid & 31, wid = tid >> 5;
    int rr = tid >> 6, f = tid & 63;

    float lns = fminf(fmaxf(lns_p[0], 1.0f), (float)NSC);
    int n = (int)rintf(lns);

    float pv = 0.f;
    #pragma unroll
    for (int p = 0; p < KSPLIT; p++)
        pv += g_pe[((size_t)p*NROW + r0 + rr)*FF + f];
    pe[rr][f] = pv;

    if (wid < 4) {
        int row = r0 + wid;
        int b = row >> 11, s = row & (SS - 1);
        int sc = lane + 1;
        float s0 = 0.f, s1 = 0.f, s2 = 0.f;
        if (sc <= n && s >= sc) {
            const float* xb = x + (size_t)b * SS * FF;
            float ds = xb[(size_t)s*FF + 0];
            float es = xb[(size_t)s*FF + FF - 1];
            float dd = xb[(size_t)(s - sc)*FF + 0] - ds;
            float de = xb[(size_t)(s - sc)*FF + FF - 1] - es;
            float wd = sw[sc - 1] * expf(-fabsf(dd) * exp2f(-(float)sc));
            s0 = dd; s1 = de; s2 = wd;
        }
        #pragma unroll
        for (int o = 16; o; o >>= 1) {
            s0 += __shfl_xor_sync(0xffffffffu, s0, o);
            s1 += __shfl_xor_sync(0xffffffffu, s1, o);
            s2 += __shfl_xor_sync(0xffffffffu, s2, o);
        }
        if (lane == 0) { sh3[wid][0] = s0; sh3[wid][1] = s1; sh3[wid][2] = s2; }
    }
    __syncthreads();

    int d = tid;
    float w1 = rW[d], w2r = rW[DD + d], w3 = rW[2*DD + d];
    float rbv = (float)n * rb[d];
    float vals[8];
    #pragma unroll
    for (int r = 0; r < 4; r++)
        vals[r] = sh3[r][0]*w1 + sh3[r][1]*w2r + sh3[r][2]*w3 + rbv;
    {
        float pbv = pb[d];
        float a0 = pbv, a1 = pbv, a2 = pbv, a3 = pbv;
        #pragma unroll
        for (int ff = 0; ff < FF; ff++) {
            float wv = pW[ff*DD + d];
            a0 = fmaf(pe[0][ff], wv, a0);
            a1 = fmaf(pe[1][ff], wv, a1);
            a2 = fmaf(pe[2][ff], wv, a2);
            a3 = fmaf(pe[3][ff], wv, a3);
        }
        vals[4] = a0; vals[5] = a1; vals[6] = a2; vals[7] = a3;
    }

    float mean[8];
    blk_sum8(vals, mean, red);
    float dv[8], v2[8];
    #pragma unroll
    for (int r = 0; r < 8; r++) { dv[r] = vals[r] - mean[r]*(1.0f/DD); v2[r] = dv[r]*dv[r]; }
    float var[8];
    blk_sum8(v2, var, red);

    float lw1 = l1w[d], lb1 = l1b[d], lw2 = l2w[d], lb2 = l2b[d];
    #pragma unroll
    for (int r = 0; r < 4; r++) {
        float o1 = dv[r]   * rsqrtf(var[r]  *(1.0f/DD) + 1e-5f) * lw1 + lb1;
        float o2 = dv[r+4] * rsqrtf(var[r+4]*(1.0f/DD) + 1e-5f) * lw2 + lb2;
        out[(size_t)(r0 + r)*DD + d] = o1 + o2;
    }
}

// ---------------- launch ----------------
extern "C" void kernel_launch(void* const* d_in, const int* in_sizes, int n_in,
                              void* d_out, int out_size) {
    const float* x   = (const float*)d_in[0];
    const float* rW  = (const float*)d_in[1];
    const float* rb  = (const float*)d_in[2];
    const float* pW  = (const float*)d_in[3];
    const float* pb  = (const float*)d_in[4];
    const float* l1w = (const float*)d_in[5];
    const float* l1b = (const float*)d_in[6];
    const float* l2w = (const float*)d_in[7];
    const float* l2b = (const float*)d_in[8];
    const float* al  = (const float*)d_in[9];
    const float* sg  = (const float*)d_in[10];
    const float* lns = (const float*)d_in[11];
    const float* sw  = (const float*)d_in[12];
    const float* qW  = (const float*)d_in[13];
    const float* qb  = (const float*)d_in[14];
    const float* kW  = (const float*)d_in[15];
    const float* kb  = (const float*)d_in[16];
    float* out = (float*)d_out;

    float* qg; float* kg;
    cudaGetSymbolAddress((void**)&qg, g_q);
    cudaGetSymbolAddress((void**)&kg, g_k);

    qk_proj_kernel<<<NROW/4, 256>>>(x, qW, qb, kW, kb);
    gemm_nt_tf32<<<dim3(SS/128, SS/128, 2*BB), 256>>>(x, qg, kg);
    row_kernel<<<NROW, 512>>>(al, sg);
    gemm_Ex_hmma<<<dim3(KSPLIT, SS/128, BB), 256>>>();
    out_kernel<<<NROW/4, 256>>>(x, rW, rb, l1w, l1b, lns, sw, pW, pb, l2w, l2b, out);
}

// round 17
// speedup vs baseline: 1.6200x; 1.0992x over previous
#include <cuda_runtime.h>
#include <cuda_fp16.h>
#include <math.h>

#define BB 4
#define SS 2048
#define FF 64
#define DD 256
#define NSC 15
#define NROW (BB*SS)   /* 8192 */
#define KSPLIT 16
#define NB 2048        /* histogram bins for quantile */

// ---------------- device scratch ----------------
__device__ __half g_Gh[(size_t)BB*SS*SS];    // gram (fp16)
__device__ __half g_Sh[(size_t)BB*SS*SS];    // qk scores (fp16)
__device__ __half g_Eh[(size_t)BB*SS*SS];    // E weights (fp16)
__device__ __half g_xh[NROW*FF];             // x  in fp16
__device__ __half g_qh[NROW*FF];             // q  in fp16
__device__ __half g_kh[NROW*FF];             // k  in fp16
__device__ float  g_sq[NROW];
__device__ float  g_pe[(size_t)KSPLIT*NROW*FF];

// ---------------- mma helpers ----------------
__device__ __forceinline__ void mma_f16(float* c,
                                        unsigned a0, unsigned a1, unsigned a2, unsigned a3,
                                        unsigned b0, unsigned b1) {
    asm volatile(
        "mma.sync.aligned.m16n8k16.row.col.f32.f16.f16.f32 "
        "{%0,%1,%2,%3}, {%4,%5,%6,%7}, {%8,%9}, {%0,%1,%2,%3};\n"
        : "+f"(c[0]), "+f"(c[1]), "+f"(c[2]), "+f"(c[3])
        : "r"(a0), "r"(a1), "r"(a2), "r"(a3), "r"(b0), "r"(b1));
}

__device__ __forceinline__ float sqrt_approx(float x) {
    float r;
    asm("sqrt.approx.f32 %0, %1;\n" : "=f"(r) : "f"(x));
    return r;
}

__device__ __forceinline__ float rsqrt_approx(float x) {
    float r;
    asm("rsqrt.approx.f32 %0, %1;\n" : "=f"(r) : "f"(x));
    return r;
}

// ---------------- batched 8-value 256-thread sum ----------------
__device__ __forceinline__ void blk_sum8(const float* v, float* res, volatile float (*red)[8]) {
    int l = threadIdx.x & 31, w = threadIdx.x >> 5;
    #pragma unroll
    for (int r = 0; r < 8; r++) {
        float t = v[r];
        #pragma unroll
        for (int o = 16; o; o >>= 1) t += __shfl_xor_sync(0xffffffffu, t, o);
        if (l == 0) red[r][w] = t;
    }
    __syncthreads();
    if (threadIdx.x < 32) {
        int r = l >> 2, i = l & 3;
        float t = red[r][i] + red[r][i + 4];
        t += __shfl_xor_sync(0xffffffffu, t, 2);
        t += __shfl_xor_sync(0xffffffffu, t, 1);
        if (i == 0) red[r][0] = t;
    }
    __syncthreads();
    #pragma unroll
    for (int r = 0; r < 8; r++) res[r] = red[r][0];
    __syncthreads();
}

// ---------------- K1a: q/k projections (fp16 out) + sq + x->fp16 ----------------
__global__ void qk_proj_kernel(const float* __restrict__ x,
                               const float* __restrict__ qW, const float* __restrict__ qb,
                               const float* __restrict__ kW, const float* __restrict__ kb) {
    int row = blockIdx.x * 4 + (threadIdx.x >> 6);
    int f   = threadIdx.x & 63;
    const float* xr = x + (size_t)row * FF;
    float aq = qb[f], ak = kb[f], ss = 0.f;
    #pragma unroll
    for (int k = 0; k < FF; k++) {
        float xv = xr[k];
        aq = fmaf(xv, qW[k*FF + f], aq);
        ak = fmaf(xv, kW[k*FF + f], ak);
        ss = fmaf(xv, xv, ss);
    }
    g_qh[(size_t)row*FF + f] = __float2half_rn(aq);
    g_kh[(size_t)row*FF + f] = __float2half_rn(ak);
    g_xh[(size_t)row*FF + f] = __float2half_rn(xr[f]);
    if (f == 0) g_sq[row] = ss;
}

// ---------------- K2: 128x128 tile NT GEMM, fp16 HMMA (K=64), fp16 out ----------------
// z<4 : G = x.x^T -> g_Gh  |  z>=4 : scores = q.k^T -> g_Sh
__global__ void __launch_bounds__(256, 2) gemm_nt_hmma() {
    __shared__ __align__(16) __half As[128][80];
    __shared__ __align__(16) __half Bs[128][80];
    int zz = blockIdx.z;
    int b  = zz & 3;
    bool isqk = zz >= 4;
    int s0 = blockIdx.y << 7;
    int t0 = blockIdx.x << 7;
    const __half* Ab = (isqk ? g_qh : g_xh) + (size_t)b * SS * FF;
    const __half* Bb = (isqk ? g_kh : g_xh) + (size_t)b * SS * FF;
    __half*       Cb = (isqk ? g_Sh : g_Gh) + (size_t)b * SS * SS;
    int tid  = threadIdx.x;
    int lane = tid & 31;
    int wid  = tid >> 5;
    int rb   = (wid & 1) * 64;
    int cb   = (wid >> 1) * 32;
    int gid = lane >> 2, t4 = lane & 3;

    // stage A and B: 128 rows x 64 halfs each (1024 uint4 each)
    #pragma unroll
    for (int l = 0; l < 4; l++) {
        int f4 = tid + l*256;
        int r  = f4 >> 3;
        int kc = (f4 & 7) * 8;
        *(uint4*)&As[r][kc] = *(const uint4*)&Ab[(size_t)(s0 + r)*FF + kc];
        *(uint4*)&Bs[r][kc] = *(const uint4*)&Bb[(size_t)(t0 + r)*FF + kc];
    }
    __syncthreads();

    float acc[4][4][4];
    #pragma unroll
    for (int i = 0; i < 4; i++)
        #pragma unroll
        for (int j = 0; j < 4; j++)
            #pragma unroll
            for (int r = 0; r < 4; r++) acc[i][j][r] = 0.f;

    #pragma unroll
    for (int ks = 0; ks < 64; ks += 16) {
        unsigned bfr[4][2];
        #pragma unroll
        for (int nt = 0; nt < 4; nt++) {
            int n = cb + nt*8 + gid;
            bfr[nt][0] = *(const unsigned*)&Bs[n][ks + t4*2];
            bfr[nt][1] = *(const unsigned*)&Bs[n][ks + 8 + t4*2];
        }
        #pragma unroll
        for (int mt = 0; mt < 4; mt++) {
            int r = rb + mt*16 + gid;
            unsigned a0 = *(const unsigned*)&As[r][ks + t4*2];
            unsigned a1 = *(const unsigned*)&As[r + 8][ks + t4*2];
            unsigned a2 = *(const unsigned*)&As[r][ks + 8 + t4*2];
            unsigned a3 = *(const unsigned*)&As[r + 8][ks + 8 + t4*2];
            #pragma unroll
            for (int nt = 0; nt < 4; nt++)
                mma_f16(acc[mt][nt], a0, a1, a2, a3, bfr[nt][0], bfr[nt][1]);
        }
    }
    #pragma unroll
    for (int mt = 0; mt < 4; mt++) {
        #pragma unroll
        for (int nt = 0; nt < 4; nt++) {
            int r    = s0 + rb + mt*16 + gid;
            int cidx = t0 + cb + nt*8 + t4*2;
            __half2 h01 = __floats2half2_rn(acc[mt][nt][0], acc[mt][nt][1]);
            __half2 h23 = __floats2half2_rn(acc[mt][nt][2], acc[mt][nt][3]);
            *(__half2*)&Cb[(size_t)r*SS + cidx]       = h01;
            *(__half2*)&Cb[(size_t)(r + 8)*SS + cidx] = h23;
        }
    }
}

// ---------------- K3: row kernel — fp16 in/out, histogram quantile ----------------
__global__ void __launch_bounds__(512, 3) row_kernel(const float* __restrict__ alpha_p,
                                                     const float* __restrict__ sig_p) {
    __shared__ unsigned hist[NB];       // 8 KB
    __shared__ float redf[3][16];
    __shared__ float stat[3];
    __shared__ unsigned woff[16];
    __shared__ unsigned bq[6];
    int row = blockIdx.x;
    int b = row >> 11, s = row & (SS - 1);
    int tid = threadIdx.x;
    int lane = tid & 31, wid = tid >> 5;
    const __half* Ghrow = g_Gh + (size_t)b*SS*SS + (size_t)s*SS;
    const __half* Shrow = g_Sh + (size_t)b*SS*SS + (size_t)s*SS;
    __half*       Ehrow = g_Eh + (size_t)b*SS*SS + (size_t)s*SS;
    const float* sqb = g_sq + b*SS;
    float sqs = sqb[s];
    float rns = rsqrt_approx(fmaxf(sqs, 1e-24f));

    #pragma unroll
    for (int j = 0; j < 4; j++) hist[tid + j*512] = 0;

    uint2 gvp = ((const uint2*)Ghrow)[tid];
    uint2 svp = ((const uint2*)Shrow)[tid];
    float4 sq4 = ((const float4*)sqb)[tid];
    float gg[4], ssc[4];
    {
        __half2* gp = (__half2*)&gvp;
        __half2* sp = (__half2*)&svp;
        float2 a0 = __half22float2(gp[0]), a1 = __half22float2(gp[1]);
        float2 b0 = __half22float2(sp[0]), b1 = __half22float2(sp[1]);
        gg[0] = a0.x; gg[1] = a0.y; gg[2] = a1.x; gg[3] = a1.y;
        ssc[0] = b0.x; ssc[1] = b0.y; ssc[2] = b1.x; ssc[3] = b1.y;
    }
    float sq_[4] = {sq4.x, sq4.y, sq4.z, sq4.w};
    float d2[4];
    #pragma unroll
    for (int j = 0; j < 4; j++)
        d2[j] = fmaxf(sqs + sq_[j] - 2.0f*gg[j], 0.0f);
    float mn = fminf(fminf(d2[0], d2[1]), fminf(d2[2], d2[3]));
    float mx = fmaxf(fmaxf(d2[0], d2[1]), fmaxf(d2[2], d2[3]));
    float z = __expf(ssc[0]*0.125f) + __expf(ssc[1]*0.125f)
            + __expf(ssc[2]*0.125f) + __expf(ssc[3]*0.125f);
    #pragma unroll
    for (int o = 16; o; o >>= 1) {
        mn = fminf(mn, __shfl_xor_sync(0xffffffffu, mn, o));
        mx = fmaxf(mx, __shfl_xor_sync(0xffffffffu, mx, o));
        z += __shfl_xor_sync(0xffffffffu, z, o);
    }
    if (lane == 0) { redf[0][wid] = mn; redf[1][wid] = mx; redf[2][wid] = z; }
    __syncthreads();
    if (tid == 0) {
        float m0 = redf[0][0], m1 = redf[1][0], zz = redf[2][0];
        #pragma unroll
        for (int i = 1; i < 16; i++) {
            m0 = fminf(m0, redf[0][i]);
            m1 = fmaxf(m1, redf[1][i]);
            zz += redf[2][i];
        }
        stat[0] = m0; stat[1] = m1; stat[2] = zz;
    }
    __syncthreads();
    float d2min = stat[0], d2max = stat[1], Z = stat[2];
    float w   = (d2max - d2min) * (1.0f / NB);
    float iw  = (float)NB / fmaxf(d2max - d2min, 1e-30f);

    #pragma unroll
    for (int j = 0; j < 4; j++) {
        int bin = (int)((d2[j] - d2min) * iw);
        bin = bin < NB-1 ? bin : NB-1;
        bin = bin > 0 ? bin : 0;
        atomicAdd(&hist[bin], 1u);
    }
    __syncthreads();

    uint4 v0 = ((const uint4*)hist)[tid];
    unsigned vals[4] = {v0.x, v0.y, v0.z, v0.w};
    unsigned st = vals[0] + vals[1] + vals[2] + vals[3];
    unsigned e = st;
    #pragma unroll
    for (int o = 1; o < 32; o <<= 1) {
        unsigned t = __shfl_up_sync(0xffffffffu, e, o);
        if (lane >= o) e += t;
    }
    if (lane == 31) woff[wid] = e;
    unsigned lexcl = e - st;
    __syncthreads();
    if (tid < 32) {
        unsigned t = (lane < 16) ? woff[lane] : 0u;
        unsigned ei = t;
        #pragma unroll
        for (int o = 1; o < 16; o <<= 1) {
            unsigned u = __shfl_up_sync(0xffffffffu, ei, o);
            if (lane >= o) ei += u;
        }
        if (lane < 16) woff[lane] = ei - t;
    }
    __syncthreads();
    {
        unsigned run = woff[wid] + lexcl;
        #pragma unroll
        for (int j = 0; j < 4; j++) {
            unsigned excl = run; run += vals[j];
            if (excl <= 102u && 102u < run)  { bq[0] = excl; bq[1] = vals[j]; bq[2] = (unsigned)(tid*4 + j); }
            if (excl <= 1944u && 1944u < run){ bq[3] = excl; bq[4] = vals[j]; bq[5] = (unsigned)(tid*4 + j); }
        }
    }
    __syncthreads();

    float frA = (102.35f  - (float)bq[0] + 0.5f) / (float)bq[1];
    float frB = (1944.65f - (float)bq[3] + 0.5f) / (float)bq[4];
    frA = fminf(fmaxf(frA, 0.0f), 1.0f);
    frB = fminf(fmaxf(frB, 0.0f), 1.0f);
    float vmin = sqrt_approx(fmaxf(d2min + ((float)bq[2] + frA) * w, 0.0f));
    float vmax = sqrt_approx(fmaxf(d2min + ((float)bq[5] + frB) * w, 0.0f));

    float a  = 1.0f / (1.0f + __expf(-alpha_p[0]));
    float sg = log1pf(__expf(sig_p[0])) + 0.001f;
    float inv2s2 = 1.0f / (2.0f * sg * sg);
    float invZ = 1.0f / Z;
    float iden = 1.0f / (vmax - vmin + 1e-6f);
    float oo[4];
    #pragma unroll
    for (int j = 0; j < 4; j++) {
        float dist = sqrt_approx(d2[j]);
        float eu = fminf(fmaxf((dist - vmin)*iden, 0.0f), 1.0f);
        float rr = rsqrt_approx(fmaxf(sq_[j], 1e-24f));
        float cs = (gg[j]*rns*rr + 1.0f) * 0.5f;
        float hyb = a*cs + (1.0f - a)*(1.0f - eu);
        oo[j] = __expf(ssc[j]*0.125f - hyb*inv2s2) * invZ;
    }
    __half2 h0 = __floats2half2_rn(oo[0], oo[1]);
    __half2 h1 = __floats2half2_rn(oo[2], oo[3]);
    uint2 pk;
    pk.x = *(unsigned*)&h0;
    pk.y = *(unsigned*)&h1;
    ((uint2*)Ehrow)[tid] = pk;
}

// ---------------- K4: pe64 = E(fp16) @ x(fp16), native HMMA, K-split ----------------
__global__ void __launch_bounds__(256, 3) gemm_Ex_hmma() {
    __shared__ __align__(16) __half Es[128][40];
    __shared__ __align__(16) __half Xs[64][40];
    int part = blockIdx.x;
    int b  = blockIdx.z;
    int s0 = blockIdx.y << 7;
    const __half* Eb = g_Eh + (size_t)b*SS*SS;
    const __half* Xb = g_xh + (size_t)b*SS*FF;
    int tid  = threadIdx.x;
    int lane = tid & 31;
    int wid  = tid >> 5;
    int rb   = (wid & 1) * 64;
    int cb   = (wid >> 1) * 16;
    int gid = lane >> 2, t4 = lane & 3;

    float acc[4][2][4];
    #pragma unroll
    for (int i = 0; i < 4; i++)
        #pragma unroll
        for (int j = 0; j < 2; j++)
            #pragma unroll
            for (int r = 0; r < 4; r++) acc[i][j][r] = 0.f;

    int kbeg = part * (SS/KSPLIT);
    for (int k0g = kbeg; k0g < kbeg + SS/KSPLIT; k0g += 32) {
        #pragma unroll
        for (int l = 0; l < 2; l++) {
            int f4 = tid + l*256;
            int r  = f4 >> 2;
            int kc = (f4 & 3) * 8;
            *(uint4*)&Es[r][kc] = *(const uint4*)&Eb[(size_t)(s0 + r)*SS + k0g + kc];
        }
        {
            int r  = tid >> 3;
            int cc = (tid & 7) * 8;
            uint4 hv = *(const uint4*)&Xb[(size_t)(k0g + r)*FF + cc];
            __half* hp = (__half*)&hv;
            #pragma unroll
            for (int j = 0; j < 8; j++) Xs[cc + j][r] = hp[j];
        }
        __syncthreads();
        #pragma unroll
        for (int kk = 0; kk < 32; kk += 16) {
            unsigned bfr[2][2];
            #pragma unroll
            for (int nt = 0; nt < 2; nt++) {
                int n = cb + nt*8 + gid;
                bfr[nt][0] = *(const unsigned*)&Xs[n][kk + t4*2];
                bfr[nt][1] = *(const unsigned*)&Xs[n][kk + t4*2 + 8];
            }
            #pragma unroll
            for (int mt = 0; mt < 4; mt++) {
                int r = rb + mt*16 + gid;
                unsigned a0 = *(const unsigned*)&Es[r][kk + t4*2];
                unsigned a1 = *(const unsigned*)&Es[r + 8][kk + t4*2];
                unsigned a2 = *(const unsigned*)&Es[r][kk + t4*2 + 8];
                unsigned a3 = *(const unsigned*)&Es[r + 8][kk + t4*2 + 8];
                #pragma unroll
                for (int nt = 0; nt < 2; nt++)
                    mma_f16(acc[mt][nt], a0, a1, a2, a3, bfr[nt][0], bfr[nt][1]);
            }
        }
        __syncthreads();
    }
    #pragma unroll
    for (int mt = 0; mt < 4; mt++) {
        #pragma unroll
        for (int nt = 0; nt < 2; nt++) {
            int r = s0 + rb + mt*16 + gid;
            int f = cb + nt*8 + t4*2;
            size_t base0 = ((size_t)part*NROW + (size_t)b*SS + r)*FF + f;
            size_t base1 = ((size_t)part*NROW + (size_t)b*SS + r + 8)*FF + f;
            *(float2*)&g_pe[base0] = make_float2(acc[mt][nt][0], acc[mt][nt][1]);
            *(float2*)&g_pe[base1] = make_float2(acc[mt][nt][2], acc[mt][nt][3]);
        }
    }
}

// ---------------- K5: merged rpe + projection + dual LN -> out ----------------
__global__ void out_kernel(const float* __restrict__ x,
                           const float* __restrict__ rW, const float* __restrict__ rb,
                           const float* __restrict__ l1w, const float* __restrict__ l1b,
                           const float* __restrict__ lns_p, const float* __restrict__ sw,
                           const float* __restrict__ pW, const float* __restrict__ pb,
                           const float* __restrict__ l2w, const float* __restrict__ l2b,
                           float* __restrict__ out) {
    __shared__ float pe[4][64];
    __shared__ float red[8][8];
    __shared__ float sh3[4][3];
    int r0 = blockIdx.x << 2;
    int tid = threadIdx.x;
    int lane = tid & 31, wid = tid >> 5;
    int rr = tid >> 6, f = tid & 63;

    float lns = fminf(fmaxf(lns_p[0], 1.0f), (float)NSC);
    int n = (int)rintf(lns);

    float pv = 0.f;
    #pragma unroll
    for (int p = 0; p < KSPLIT; p++)
        pv += g_pe[((size_t)p*NROW + r0 + rr)*FF + f];
    pe[rr][f] = pv;

    if (wid < 4) {
        int row = r0 + wid;
        int b = row >> 11, s = row & (SS - 1);
        int sc = lane + 1;
        float s0 = 0.f, s1 = 0.f, s2 = 0.f;
        if (sc <= n && s >= sc) {
            const float* xb = x + (size_t)b * SS * FF;
            float ds = xb[(size_t)s*FF + 0];
            float es = xb[(size_t)s*FF + FF - 1];
            float dd = xb[(size_t)(s - sc)*FF + 0] - ds;
            float de = xb[(size_t)(s - sc)*FF + FF - 1] - es;
            float wd = sw[sc - 1] * expf(-fabsf(dd) * exp2f(-(float)sc));
            s0 = dd; s1 = de; s2 = wd;
        }
        #pragma unroll
        for (int o = 16; o; o >>= 1) {
            s0 += __shfl_xor_sync(0xffffffffu, s0, o);
            s1 += __shfl_xor_sync(0xffffffffu, s1, o);
            s2 += __shfl_xor_sync(0xffffffffu, s2, o);
        }
        if (lane == 0) { sh3[wid][0] = s0; sh3[wid][1] = s1; sh3[wid][2] = s2; }
    }
    __syncthreads();

    int d = tid;
    float w1 = rW[d], w2r = rW[DD + d], w3 = rW[2*DD + d];
    float rbv = (float)n * rb[d];
    float vals[8];
    #pragma unroll
    for (int r = 0; r < 4; r++)
        vals[r] = sh3[r][0]*w1 + sh3[r][1]*w2r + sh3[r][2]*w3 + rbv;
    {
        float pbv = pb[d];
        float a0 = pbv, a1 = pbv, a2 = pbv, a3 = pbv;
        #pragma unroll
        for (int ff = 0; ff < FF; ff++) {
            float wv = pW[ff*DD + d];
            a0 = fmaf(pe[0][ff], wv, a0);
            a1 = fmaf(pe[1][ff], wv, a1);
            a2 = fmaf(pe[2][ff], wv, a2);
            a3 = fmaf(pe[3][ff], wv, a3);
        }
        vals[4] = a0; vals[5] = a1; vals[6] = a2; vals[7] = a3;
    }

    float mean[8];
    blk_sum8(vals, mean, red);
    float dv[8], v2[8];
    #pragma unroll
    for (int r = 0; r < 8; r++) { dv[r] = vals[r] - mean[r]*(1.0f/DD); v2[r] = dv[r]*dv[r]; }
    float var[8];
    blk_sum8(v2, var, red);

    float lw1 = l1w[d], lb1 = l1b[d], lw2 = l2w[d], lb2 = l2b[d];
    #pragma unroll
    for (int r = 0; r < 4; r++) {
        float o1 = dv[r]   * rsqrtf(var[r]  *(1.0f/DD) + 1e-5f) * lw1 + lb1;
        float o2 = dv[r+4] * rsqrtf(var[r+4]*(1.0f/DD) + 1e-5f) * lw2 + lb2;
        out[(size_t)(r0 + r)*DD + d] = o1 + o2;
    }
}

// ---------------- launch ----------------
extern "C" void kernel_launch(void* const* d_in, const int* in_sizes, int n_in,
                              void* d_out, int out_size) {
    const float* x   = (const float*)d_in[0];
    const float* rW  = (const float*)d_in[1];
    const float* rb  = (const float*)d_in[2];
    const float* pW  = (const float*)d_in[3];
    const float* pb  = (const float*)d_in[4];
    const float* l1w = (const float*)d_in[5];
    const float* l1b = (const float*)d_in[6];
    const float* l2w = (const float*)d_in[7];
    const float* l2b = (const float*)d_in[8];
    const float* al  = (const float*)d_in[9];
    const float* sg  = (const float*)d_in[10];
    const float* lns = (const float*)d_in[11];
    const float* sw  = (const float*)d_in[12];
    const float* qW  = (const float*)d_in[13];
    const float* qb  = (const float*)d_in[14];
    const float* kW  = (const float*)d_in[15];
    const float* kb  = (const float*)d_in[16];
    float* out = (float*)d_out;

    qk_proj_kernel<<<NROW/4, 256>>>(x, qW, qb, kW, kb);
    gemm_nt_hmma<<<dim3(SS/128, SS/128, 2*BB), 256>>>();
    row_kernel<<<NROW, 512>>>(al, sg);
    gemm_Ex_hmma<<<dim3(KSPLIT, SS/128, BB), 256>>>();
    out_kernel<<<NROW/4, 256>>>(x, rW, rb, l1w, l1b, lns, sw, pW, pb, l2w, l2b, out);
}